// round 1
// baseline (speedup 1.0000x reference)
#include <cuda_runtime.h>

// ---------------- problem constants ----------------
#define NB   2
#define CR_  256
#define CS_  512
#define LL   4096     // 64*64
#define PS_  1024     // 32*32
#define DI_  512
#define DS_  16
#define NCH  32       // scan chunks
#define CT_  128      // chunk length (NCH*CT_ == LL)
#define EPSF 1e-5f

// ---------------- scratch (static device allocs only) ----------------
__device__ float g_sp   [NB*CR_*PS_];     // scp projected+BN (B,256,1024)
__device__ float g_fused[NB*CR_*LL];      // fused (B,C,HW)
__device__ float g_xt   [NB*LL*CR_];      // fused transposed (B,L,C)
__device__ float g_stats[NB*LL*2];        // per-row mean, rstd
__device__ float g_xm   [NB*LL*DI_];
__device__ float g_z    [NB*LL*DI_];
__device__ float g_u    [NB*LL*DI_];
__device__ float g_xdbl [NB*LL*48];
__device__ float g_dt   [NB*LL*DI_];
__device__ float g_P    [NB*DI_*DS_*NCH];
__device__ float g_Hc   [NB*DI_*DS_*NCH];
__device__ float g_hini [NB*DI_*DS_*NCH];
__device__ float g_yfin [NB*LL*DI_];

// =====================================================================
// K1: scp 1x1 conv GEMM + BN : sp[b,o,p] = BN(sum_c W[o,c]*scp[b,c,p])
// =====================================================================
__global__ void k_scp(const float* __restrict__ scp, const float* __restrict__ w,
                      const float* __restrict__ gg, const float* __restrict__ bb,
                      const float* __restrict__ mm, const float* __restrict__ vv) {
    __shared__ float As[16][65];  // [k][o]
    __shared__ float Bs[16][65];  // [k][p]
    const int b  = blockIdx.z;
    const int o0 = blockIdx.y * 64;
    const int p0 = blockIdx.x * 64;
    const int tid = threadIdx.x;
    const int tx = tid & 15, ty = tid >> 4;
    float acc[4][4] = {};
    for (int k0 = 0; k0 < 512; k0 += 16) {
#pragma unroll
        for (int i = 0; i < 4; i++) {
            int idx = tid + i * 256;
            int o = idx >> 4, kk = idx & 15;
            As[kk][o] = w[(o0 + o) * 512 + k0 + kk];
        }
#pragma unroll
        for (int i = 0; i < 4; i++) {
            int idx = tid + i * 256;
            int kk = idx >> 6, p = idx & 63;
            Bs[kk][p] = scp[(b * 512 + k0 + kk) * 1024 + p0 + p];
        }
        __syncthreads();
#pragma unroll
        for (int kk = 0; kk < 16; kk++) {
            float a[4], c[4];
#pragma unroll
            for (int i = 0; i < 4; i++) a[i] = As[kk][ty * 4 + i];
#pragma unroll
            for (int j = 0; j < 4; j++) c[j] = Bs[kk][tx * 4 + j];
#pragma unroll
            for (int i = 0; i < 4; i++)
#pragma unroll
                for (int j = 0; j < 4; j++) acc[i][j] += a[i] * c[j];
        }
        __syncthreads();
    }
#pragma unroll
    for (int i = 0; i < 4; i++) {
        int o = o0 + ty * 4 + i;
        float inv  = gg[o] * rsqrtf(vv[o] + EPSF);
        float beta = bb[o] - mm[o] * inv;
#pragma unroll
        for (int j = 0; j < 4; j++) {
            int p = p0 + tx * 4 + j;
            g_sp[(b * 256 + o) * 1024 + p] = acc[i][j] * inv + beta;
        }
    }
}

// =====================================================================
// K2: fused = BN(resnet) + bilinear_upsample(sp); write both (B,C,HW)
//     and transposed (B,HW,C) layouts (smem transpose for coalescing).
// =====================================================================
__global__ void k_fuse(const float* __restrict__ res,
                       const float* __restrict__ rg, const float* __restrict__ rb,
                       const float* __restrict__ rm, const float* __restrict__ rv) {
    __shared__ float tile[32][33];
    const int b  = blockIdx.z;
    const int c0 = blockIdx.y * 32;
    const int l0 = blockIdx.x * 32;
    const int tx = threadIdx.x, ty = threadIdx.y;  // 32 x 8
    const int l = l0 + tx;
    const int h = l >> 6, wq = l & 63;
    // half-pixel src coords for 2x upsample; clamped bilinear == jax renorm here
    float sh = h * 0.5f - 0.25f;
    float sw = wq * 0.5f - 0.25f;
    int h0 = (int)floorf(sh); float fh = sh - (float)h0;
    int w0 = (int)floorf(sw); float fw = sw - (float)w0;
    int h0c = max(h0, 0), h1c = min(h0 + 1, 31);
    int w0c = max(w0, 0), w1c = min(w0 + 1, 31);
#pragma unroll
    for (int i = 0; i < 4; i++) {
        int c = c0 + ty + i * 8;
        float inv  = rg[c] * rsqrtf(rv[c] + EPSF);
        float beta = rb[c] - rm[c] * inv;
        float val = res[(b * 256 + c) * 4096 + l] * inv + beta;
        const float* spb = g_sp + (b * 256 + c) * 1024;
        float s00 = spb[h0c * 32 + w0c], s01 = spb[h0c * 32 + w1c];
        float s10 = spb[h1c * 32 + w0c], s11 = spb[h1c * 32 + w1c];
        val += (1.f - fh) * ((1.f - fw) * s00 + fw * s01)
             +        fh  * ((1.f - fw) * s10 + fw * s11);
        g_fused[(b * 256 + c) * 4096 + l] = val;
        tile[ty + i * 8][tx] = val;
    }
    __syncthreads();
#pragma unroll
    for (int i = 0; i < 4; i++) {
        int c  = c0 + tx;
        int ll = l0 + ty + i * 8;
        g_xt[(b * 4096 + ll) * 256 + c] = tile[tx][ty + i * 8];
    }
}

// =====================================================================
// K3: LayerNorm row stats (mean, rstd) over CR=256
// =====================================================================
__global__ void k_lnstats() {
    const int row = blockIdx.x;  // B*L
    float v = g_xt[row * 256 + threadIdx.x];
    float s = v, sq = v * v;
#pragma unroll
    for (int o = 16; o; o >>= 1) {
        s  += __shfl_xor_sync(0xffffffffu, s,  o);
        sq += __shfl_xor_sync(0xffffffffu, sq, o);
    }
    __shared__ float ss[8], ssq[8];
    const int wid = threadIdx.x >> 5;
    if ((threadIdx.x & 31) == 0) { ss[wid] = s; ssq[wid] = sq; }
    __syncthreads();
    if (threadIdx.x == 0) {
        float S = 0.f, Q = 0.f;
#pragma unroll
        for (int i = 0; i < 8; i++) { S += ss[i]; Q += ssq[i]; }
        float mu  = S * (1.f / 256.f);
        float var = Q * (1.f / 256.f) - mu * mu;
        g_stats[row * 2]     = mu;
        g_stats[row * 2 + 1] = rsqrtf(var + EPSF);
    }
}

// =====================================================================
// K4: in_proj GEMM with fused LN apply. xz = LN(xt) @ W^T, split xm/z.
// =====================================================================
__global__ void k_inproj(const float* __restrict__ w,
                         const float* __restrict__ lg, const float* __restrict__ lb) {
    __shared__ float As[16][65];
    __shared__ float Bs[16][65];
    const int m0 = blockIdx.x * 64;
    const int n0 = blockIdx.y * 64;
    const int tid = threadIdx.x;
    const int tx = tid & 15, ty = tid >> 4;
    float mu[4], rs[4];
#pragma unroll
    for (int i = 0; i < 4; i++) {
        int m = (tid + i * 256) >> 4;
        mu[i] = g_stats[(m0 + m) * 2];
        rs[i] = g_stats[(m0 + m) * 2 + 1];
    }
    float acc[4][4] = {};
    for (int k0 = 0; k0 < 256; k0 += 16) {
#pragma unroll
        for (int i = 0; i < 4; i++) {
            int idx = tid + i * 256;
            int m = idx >> 4, kk = idx & 15;
            int gk = k0 + kk;
            float vv = g_xt[(m0 + m) * 256 + gk];
            As[kk][m] = (vv - mu[i]) * rs[i] * lg[gk] + lb[gk];
        }
#pragma unroll
        for (int i = 0; i < 4; i++) {
            int idx = tid + i * 256;
            int n = idx >> 4, kk = idx & 15;
            Bs[kk][n] = w[(n0 + n) * 256 + k0 + kk];
        }
        __syncthreads();
#pragma unroll
        for (int kk = 0; kk < 16; kk++) {
            float a[4], c[4];
#pragma unroll
            for (int i = 0; i < 4; i++) a[i] = As[kk][ty * 4 + i];
#pragma unroll
            for (int j = 0; j < 4; j++) c[j] = Bs[kk][tx * 4 + j];
#pragma unroll
            for (int i = 0; i < 4; i++)
#pragma unroll
                for (int j = 0; j < 4; j++) acc[i][j] += a[i] * c[j];
        }
        __syncthreads();
    }
#pragma unroll
    for (int i = 0; i < 4; i++) {
        int gm = m0 + ty * 4 + i;
#pragma unroll
        for (int j = 0; j < 4; j++) {
            int gn = n0 + tx * 4 + j;
            if (gn < 512) g_xm[gm * 512 + gn] = acc[i][j];
            else          g_z[gm * 512 + gn - 512] = acc[i][j];
        }
    }
}

// =====================================================================
// K5: causal depthwise conv (k=3) + SiLU -> u
// =====================================================================
__global__ void k_conv(const float* __restrict__ cw, const float* __restrict__ cb) {
    int idx = blockIdx.x * blockDim.x + threadIdx.x;  // B*L*DI
    int d = idx & 511;
    int l = (idx >> 9) & 4095;
    float x2 = g_xm[idx];
    float x1 = (l >= 1) ? g_xm[idx - 512]  : 0.f;
    float x0 = (l >= 2) ? g_xm[idx - 1024] : 0.f;
    float a = x0 * cw[d * 3] + x1 * cw[d * 3 + 1] + x2 * cw[d * 3 + 2] + cb[d];
    g_u[idx] = a / (1.f + __expf(-a));
}

// =====================================================================
// K6: x_proj GEMM: xdbl = u @ x_proj_w^T  (N=48)
// =====================================================================
__global__ void k_xproj(const float* __restrict__ w) {
    __shared__ float As[16][65];
    __shared__ float Bs[16][65];
    const int m0 = blockIdx.x * 64;
    const int tid = threadIdx.x;
    const int tx = tid & 15, ty = tid >> 4;
    float acc[4][4] = {};
    for (int k0 = 0; k0 < 512; k0 += 16) {
#pragma unroll
        for (int i = 0; i < 4; i++) {
            int idx = tid + i * 256;
            int m = idx >> 4, kk = idx & 15;
            As[kk][m] = g_u[(m0 + m) * 512 + k0 + kk];
        }
#pragma unroll
        for (int i = 0; i < 4; i++) {
            int idx = tid + i * 256;
            int n = idx >> 4, kk = idx & 15;
            Bs[kk][n] = (n < 48) ? w[n * 512 + k0 + kk] : 0.f;
        }
        __syncthreads();
#pragma unroll
        for (int kk = 0; kk < 16; kk++) {
            float a[4], c[4];
#pragma unroll
            for (int i = 0; i < 4; i++) a[i] = As[kk][ty * 4 + i];
#pragma unroll
            for (int j = 0; j < 4; j++) c[j] = Bs[kk][tx * 4 + j];
#pragma unroll
            for (int i = 0; i < 4; i++)
#pragma unroll
                for (int j = 0; j < 4; j++) acc[i][j] += a[i] * c[j];
        }
        __syncthreads();
    }
#pragma unroll
    for (int i = 0; i < 4; i++) {
        int gm = m0 + ty * 4 + i;
#pragma unroll
        for (int j = 0; j < 4; j++) {
            int gn = tx * 4 + j;
            if (gn < 48) g_xdbl[gm * 48 + gn] = acc[i][j];
        }
    }
}

// =====================================================================
// K7: dt_proj GEMM (K=16) + bias + softplus -> dt
// =====================================================================
__global__ void k_dtproj(const float* __restrict__ w, const float* __restrict__ dtb) {
    __shared__ float As[16][65];
    __shared__ float Bs[16][65];
    const int m0 = blockIdx.x * 64;
    const int n0 = blockIdx.y * 64;
    const int tid = threadIdx.x;
    const int tx = tid & 15, ty = tid >> 4;
    float acc[4][4] = {};
#pragma unroll
    for (int i = 0; i < 4; i++) {
        int idx = tid + i * 256;
        int m = idx >> 4, kk = idx & 15;
        As[kk][m] = g_xdbl[(m0 + m) * 48 + kk];
    }
#pragma unroll
    for (int i = 0; i < 4; i++) {
        int idx = tid + i * 256;
        int n = idx >> 4, kk = idx & 15;
        Bs[kk][n] = w[(n0 + n) * 16 + kk];
    }
    __syncthreads();
#pragma unroll
    for (int kk = 0; kk < 16; kk++) {
        float a[4], c[4];
#pragma unroll
        for (int i = 0; i < 4; i++) a[i] = As[kk][ty * 4 + i];
#pragma unroll
        for (int j = 0; j < 4; j++) c[j] = Bs[kk][tx * 4 + j];
#pragma unroll
        for (int i = 0; i < 4; i++)
#pragma unroll
            for (int j = 0; j < 4; j++) acc[i][j] += a[i] * c[j];
    }
#pragma unroll
    for (int i = 0; i < 4; i++) {
        int gm = m0 + ty * 4 + i;
#pragma unroll
        for (int j = 0; j < 4; j++) {
            int gn = n0 + tx * 4 + j;
            float x = acc[i][j] + dtb[gn];
            float sp = (x > 20.f) ? x : log1pf(__expf(x));
            g_dt[gm * 512 + gn] = sp;
        }
    }
}

// =====================================================================
// K8: scan pass 1 — per chunk: P = prod dA, Hc = local final state.
// Warp handles 2 channels (lane half), 16 states per half.
// =====================================================================
__global__ void k_scan1(const float* __restrict__ alog) {
    const int w    = (blockIdx.x * blockDim.x + threadIdx.x) >> 5;
    const int lane = threadIdx.x & 31;
    const int chunk = w & (NCH - 1);
    const int dpair = (w >> 5) & 255;
    const int b     = w >> 13;
    const int s = lane & 15;
    const int d = dpair * 2 + (lane >> 4);
    const float An = -__expf(alog[d * 16 + s]);
    float h = 0.f, P = 1.f;
    const int l0 = chunk * CT_;
    const float* dtp = g_dt   + ((b * LL) + l0) * 512 + d;
    const float* up  = g_u    + ((b * LL) + l0) * 512 + d;
    const float* bcp = g_xdbl + ((b * LL) + l0) * 48 + 16 + s;
#pragma unroll 4
    for (int t = 0; t < CT_; t++) {
        float dtv = dtp[t * 512];
        float uv  = up[t * 512];
        float bc  = bcp[t * 48];
        float dA  = __expf(dtv * An);
        h = fmaf(dA, h, dtv * bc * uv);
        P *= dA;
    }
    const int idx = ((b * 512 + d) * 16 + s) * NCH + chunk;
    g_P[idx]  = P;
    g_Hc[idx] = h;
}

// =====================================================================
// K9: sequential combine across chunks -> hinit per chunk
// =====================================================================
__global__ void k_comb() {
    const int t = blockIdx.x * blockDim.x + threadIdx.x;  // B*DI*DS = 16384
    const int base = t * NCH;
    float h = 0.f;
    for (int c = 0; c < NCH; c++) {
        g_hini[base + c] = h;
        h = g_P[base + c] * h + g_Hc[base + c];
    }
}

// =====================================================================
// K10: scan pass 2 — replay with correct init, y = (sum_s h*C + u*D)*silu(z)
// =====================================================================
__global__ void k_scan2(const float* __restrict__ alog, const float* __restrict__ Dp) {
    const int w    = (blockIdx.x * blockDim.x + threadIdx.x) >> 5;
    const int lane = threadIdx.x & 31;
    const int chunk = w & (NCH - 1);
    const int dpair = (w >> 5) & 255;
    const int b     = w >> 13;
    const int s = lane & 15;
    const int d = dpair * 2 + (lane >> 4);
    const float An = -__expf(alog[d * 16 + s]);
    const float Dv = Dp[d];
    const int idx0 = ((b * 512 + d) * 16 + s) * NCH + chunk;
    float h = g_hini[idx0];
    const int l0 = chunk * CT_;
    const float* dtp = g_dt   + ((b * LL) + l0) * 512 + d;
    const float* up  = g_u    + ((b * LL) + l0) * 512 + d;
    const float* bcp = g_xdbl + ((b * LL) + l0) * 48 + 16 + s;
    const float* ccp = g_xdbl + ((b * LL) + l0) * 48 + 32 + s;
    const float* zp  = g_z    + ((b * LL) + l0) * 512 + d;
    float* yp        = g_yfin + ((b * LL) + l0) * 512 + d;
#pragma unroll 2
    for (int t = 0; t < CT_; t++) {
        float dtv = dtp[t * 512];
        float uv  = up[t * 512];
        float bc  = bcp[t * 48];
        float cc  = ccp[t * 48];
        float dA  = __expf(dtv * An);
        h = fmaf(dA, h, dtv * bc * uv);
        float part = h * cc;
        part += __shfl_xor_sync(0xffffffffu, part, 1);
        part += __shfl_xor_sync(0xffffffffu, part, 2);
        part += __shfl_xor_sync(0xffffffffu, part, 4);
        part += __shfl_xor_sync(0xffffffffu, part, 8);
        if (s == 0) {
            float zv = zp[t * 512];
            float y = (part + uv * Dv) * (zv / (1.f + __expf(-zv)));
            yp[t * 512] = y;
        }
    }
}

// =====================================================================
// K11: out_proj GEMM + residual add -> d_out (B,C,H,W)
// =====================================================================
__global__ void k_outproj(const float* __restrict__ w, float* __restrict__ out) {
    __shared__ float As[16][65];
    __shared__ float Bs[16][65];
    const int m0 = blockIdx.x * 64;
    const int n0 = blockIdx.y * 64;
    const int tid = threadIdx.x;
    const int tx = tid & 15, ty = tid >> 4;
    float acc[4][4] = {};
    for (int k0 = 0; k0 < 512; k0 += 16) {
#pragma unroll
        for (int i = 0; i < 4; i++) {
            int idx = tid + i * 256;
            int m = idx >> 4, kk = idx & 15;
            As[kk][m] = g_yfin[(m0 + m) * 512 + k0 + kk];
        }
#pragma unroll
        for (int i = 0; i < 4; i++) {
            int idx = tid + i * 256;
            int n = idx >> 4, kk = idx & 15;
            Bs[kk][n] = w[(n0 + n) * 512 + k0 + kk];
        }
        __syncthreads();
#pragma unroll
        for (int kk = 0; kk < 16; kk++) {
            float a[4], c[4];
#pragma unroll
            for (int i = 0; i < 4; i++) a[i] = As[kk][ty * 4 + i];
#pragma unroll
            for (int j = 0; j < 4; j++) c[j] = Bs[kk][tx * 4 + j];
#pragma unroll
            for (int i = 0; i < 4; i++)
#pragma unroll
                for (int j = 0; j < 4; j++) acc[i][j] += a[i] * c[j];
        }
        __syncthreads();
    }
#pragma unroll
    for (int i = 0; i < 4; i++) {
        int gm = m0 + ty * 4 + i;
        int b  = gm >> 12;
        int l  = gm & 4095;
#pragma unroll
        for (int j = 0; j < 4; j++) {
            int gn = n0 + tx * 4 + j;
            int o = (b * 256 + gn) * 4096 + l;
            out[o] = acc[i][j] + g_fused[o];
        }
    }
}

// =====================================================================
extern "C" void kernel_launch(void* const* d_in, const int* in_sizes, int n_in,
                              void* d_out, int out_size) {
    const float* resnet = (const float*)d_in[0];
    const float* scp    = (const float*)d_in[1];
    const float* scpw   = (const float*)d_in[2];
    const float* sg = (const float*)d_in[3];
    const float* sb = (const float*)d_in[4];
    const float* sm = (const float*)d_in[5];
    const float* sv = (const float*)d_in[6];
    const float* rg = (const float*)d_in[7];
    const float* rb = (const float*)d_in[8];
    const float* rm = (const float*)d_in[9];
    const float* rv = (const float*)d_in[10];
    const float* lg = (const float*)d_in[11];
    const float* lb = (const float*)d_in[12];
    const float* inw = (const float*)d_in[13];
    const float* cw  = (const float*)d_in[14];
    const float* cb  = (const float*)d_in[15];
    const float* xw  = (const float*)d_in[16];
    const float* dtw = (const float*)d_in[17];
    const float* dtb = (const float*)d_in[18];
    const float* alog = (const float*)d_in[19];
    const float* Dp   = (const float*)d_in[20];
    const float* ow   = (const float*)d_in[21];
    float* out = (float*)d_out;

    k_scp    <<<dim3(16, 4, 2), 256>>>(scp, scpw, sg, sb, sm, sv);
    k_fuse   <<<dim3(128, 8, 2), dim3(32, 8)>>>(resnet, rg, rb, rm, rv);
    k_lnstats<<<NB * LL, 256>>>();
    k_inproj <<<dim3(128, 16), 256>>>(inw, lg, lb);
    k_conv   <<<(NB * LL * DI_) / 256, 256>>>(cw, cb);
    k_xproj  <<<dim3(128, 1), 256>>>(xw);
    k_dtproj <<<dim3(128, 8), 256>>>(dtw, dtb);
    k_scan1  <<<2048, 256>>>(alog);
    k_comb   <<<64, 256>>>();
    k_scan2  <<<2048, 256>>>(alog, Dp);
    k_outproj<<<dim3(128, 4), 256>>>(ow, out);
}

// round 2
// speedup vs baseline: 1.2468x; 1.2468x over previous
#include <cuda_runtime.h>

// ---------------- problem constants ----------------
#define NB   2
#define CR_  256
#define CS_  512
#define LL   4096     // 64*64
#define PS_  1024     // 32*32
#define DI_  512
#define DS_  16
#define NCH  32       // scan chunks
#define CT_  128      // chunk length (NCH*CT_ == LL)
#define EPSF 1e-5f

typedef unsigned long long ull;

// packed f32x2 helpers (FFMA2 path — ptxas never auto-generates this)
__device__ __forceinline__ ull dupf(float x) {
    ull r; unsigned u = __float_as_uint(x);
    asm("mov.b64 %0, {%1, %2};" : "=l"(r) : "r"(u), "r"(u));
    return r;
}
__device__ __forceinline__ void fma2(ull& d, ull a, ull b) {
    asm("fma.rn.f32x2 %0, %1, %2, %3;" : "=l"(d) : "l"(a), "l"(b), "l"(d));
}
__device__ __forceinline__ void unpk(ull v, float& lo, float& hi) {
    unsigned a, b;
    asm("mov.b64 {%0, %1}, %2;" : "=r"(a), "=r"(b) : "l"(v));
    lo = __uint_as_float(a); hi = __uint_as_float(b);
}

// ---------------- scratch (static device allocs only) ----------------
__device__ float g_sp   [NB*CR_*PS_];     // scp projected+BN (B,256,1024)
__device__ float g_fused[NB*CR_*LL];      // fused (B,C,HW)
__device__ float g_xt   [NB*LL*CR_];      // fused transposed (B,L,C)
__device__ float g_stats[NB*LL*2];        // per-row mean, rstd
__device__ float g_xm   [NB*LL*DI_];
__device__ float g_z    [NB*LL*DI_];
__device__ float g_u    [NB*LL*DI_];
__device__ float g_xdbl [NB*LL*48];
__device__ float g_dt   [NB*LL*DI_];
__device__ float g_P    [NB*DI_*DS_*NCH];
__device__ float g_Hc   [NB*DI_*DS_*NCH];
__device__ float g_hini [NB*DI_*DS_*NCH];
__device__ float g_yfin [NB*LL*DI_];

// =====================================================================
// K1: scp 1x1 conv GEMM + BN : sp[b,o,p] = BN(sum_c W[o,c]*scp[b,c,p])
// =====================================================================
__global__ void k_scp(const float* __restrict__ scp, const float* __restrict__ w,
                      const float* __restrict__ gg, const float* __restrict__ bb,
                      const float* __restrict__ mm, const float* __restrict__ vv) {
    __shared__ float As[16][65];  // [k][o]
    __shared__ float Bs[16][65];  // [k][p]
    const int b  = blockIdx.z;
    const int o0 = blockIdx.y * 64;
    const int p0 = blockIdx.x * 64;
    const int tid = threadIdx.x;
    const int tx = tid & 15, ty = tid >> 4;
    float acc[4][4] = {};
    for (int k0 = 0; k0 < 512; k0 += 16) {
#pragma unroll
        for (int i = 0; i < 4; i++) {
            int idx = tid + i * 256;
            int o = idx >> 4, kk = idx & 15;
            As[kk][o] = w[(o0 + o) * 512 + k0 + kk];
        }
#pragma unroll
        for (int i = 0; i < 4; i++) {
            int idx = tid + i * 256;
            int kk = idx >> 6, p = idx & 63;
            Bs[kk][p] = scp[(b * 512 + k0 + kk) * 1024 + p0 + p];
        }
        __syncthreads();
#pragma unroll
        for (int kk = 0; kk < 16; kk++) {
            float a[4], c[4];
#pragma unroll
            for (int i = 0; i < 4; i++) a[i] = As[kk][ty * 4 + i];
#pragma unroll
            for (int j = 0; j < 4; j++) c[j] = Bs[kk][tx * 4 + j];
#pragma unroll
            for (int i = 0; i < 4; i++)
#pragma unroll
                for (int j = 0; j < 4; j++) acc[i][j] += a[i] * c[j];
        }
        __syncthreads();
    }
#pragma unroll
    for (int i = 0; i < 4; i++) {
        int o = o0 + ty * 4 + i;
        float inv  = gg[o] * rsqrtf(vv[o] + EPSF);
        float beta = bb[o] - mm[o] * inv;
#pragma unroll
        for (int j = 0; j < 4; j++) {
            int p = p0 + tx * 4 + j;
            g_sp[(b * 256 + o) * 1024 + p] = acc[i][j] * inv + beta;
        }
    }
}

// =====================================================================
// K2: fused = BN(resnet) + bilinear_upsample(sp); write both (B,C,HW)
//     and transposed (B,HW,C) layouts (smem transpose for coalescing).
// =====================================================================
__global__ void k_fuse(const float* __restrict__ res,
                       const float* __restrict__ rg, const float* __restrict__ rb,
                       const float* __restrict__ rm, const float* __restrict__ rv) {
    __shared__ float tile[32][33];
    const int b  = blockIdx.z;
    const int c0 = blockIdx.y * 32;
    const int l0 = blockIdx.x * 32;
    const int tx = threadIdx.x, ty = threadIdx.y;  // 32 x 8
    const int l = l0 + tx;
    const int h = l >> 6, wq = l & 63;
    float sh = h * 0.5f - 0.25f;
    float sw = wq * 0.5f - 0.25f;
    int h0 = (int)floorf(sh); float fh = sh - (float)h0;
    int w0 = (int)floorf(sw); float fw = sw - (float)w0;
    int h0c = max(h0, 0), h1c = min(h0 + 1, 31);
    int w0c = max(w0, 0), w1c = min(w0 + 1, 31);
#pragma unroll
    for (int i = 0; i < 4; i++) {
        int c = c0 + ty + i * 8;
        float inv  = rg[c] * rsqrtf(rv[c] + EPSF);
        float beta = rb[c] - rm[c] * inv;
        float val = res[(b * 256 + c) * 4096 + l] * inv + beta;
        const float* spb = g_sp + (b * 256 + c) * 1024;
        float s00 = spb[h0c * 32 + w0c], s01 = spb[h0c * 32 + w1c];
        float s10 = spb[h1c * 32 + w0c], s11 = spb[h1c * 32 + w1c];
        val += (1.f - fh) * ((1.f - fw) * s00 + fw * s01)
             +        fh  * ((1.f - fw) * s10 + fw * s11);
        g_fused[(b * 256 + c) * 4096 + l] = val;
        tile[ty + i * 8][tx] = val;
    }
    __syncthreads();
#pragma unroll
    for (int i = 0; i < 4; i++) {
        int c  = c0 + tx;
        int ll = l0 + ty + i * 8;
        g_xt[(b * 4096 + ll) * 256 + c] = tile[tx][ty + i * 8];
    }
}

// =====================================================================
// K3: LayerNorm row stats (mean, rstd) over CR=256
// =====================================================================
__global__ void k_lnstats() {
    const int row = blockIdx.x;  // B*L
    float v = g_xt[row * 256 + threadIdx.x];
    float s = v, sq = v * v;
#pragma unroll
    for (int o = 16; o; o >>= 1) {
        s  += __shfl_xor_sync(0xffffffffu, s,  o);
        sq += __shfl_xor_sync(0xffffffffu, sq, o);
    }
    __shared__ float ss[8], ssq[8];
    const int wid = threadIdx.x >> 5;
    if ((threadIdx.x & 31) == 0) { ss[wid] = s; ssq[wid] = sq; }
    __syncthreads();
    if (threadIdx.x == 0) {
        float S = 0.f, Q = 0.f;
#pragma unroll
        for (int i = 0; i < 8; i++) { S += ss[i]; Q += ssq[i]; }
        float mu  = S * (1.f / 256.f);
        float var = Q * (1.f / 256.f) - mu * mu;
        g_stats[row * 2]     = mu;
        g_stats[row * 2 + 1] = rsqrtf(var + EPSF);
    }
}

// =====================================================================
// K4: in_proj GEMM (128x128x16 tile, 8x8 microtile, FFMA2) + fused LN
// =====================================================================
__global__ void __launch_bounds__(256, 2)
k_inproj2(const float* __restrict__ w,
          const float* __restrict__ lg, const float* __restrict__ lb) {
    __shared__ float As[16][132];
    __shared__ float Bs[16][132];
    const int m0 = blockIdx.x * 128;
    const int n0 = blockIdx.y * 128;
    const int tid = threadIdx.x;
    const int tx = tid & 15, ty = tid >> 4;
    const int r = tid >> 2, q = tid & 3;
    const float mu0 = g_stats[(m0 + r) * 2],      rs0 = g_stats[(m0 + r) * 2 + 1];
    const float mu1 = g_stats[(m0 + r + 64) * 2], rs1 = g_stats[(m0 + r + 64) * 2 + 1];
    ull acc[8][4];
#pragma unroll
    for (int i = 0; i < 8; i++)
#pragma unroll
        for (int j = 0; j < 4; j++) acc[i][j] = 0ull;

    float4 a0 = *(const float4*)&g_xt[(m0 + r) * 256 + q * 4];
    float4 a1 = *(const float4*)&g_xt[(m0 + r + 64) * 256 + q * 4];
    float4 b0 = *(const float4*)&w[(n0 + r) * 256 + q * 4];
    float4 b1 = *(const float4*)&w[(n0 + r + 64) * 256 + q * 4];

    for (int kt = 0; kt < 16; kt++) {
        const int k0 = kt * 16;
        float4 g4 = *(const float4*)&lg[k0 + q * 4];
        float4 e4 = *(const float4*)&lb[k0 + q * 4];
        float4 t0, t1;
        t0.x = (a0.x - mu0) * rs0 * g4.x + e4.x;
        t0.y = (a0.y - mu0) * rs0 * g4.y + e4.y;
        t0.z = (a0.z - mu0) * rs0 * g4.z + e4.z;
        t0.w = (a0.w - mu0) * rs0 * g4.w + e4.w;
        t1.x = (a1.x - mu1) * rs1 * g4.x + e4.x;
        t1.y = (a1.y - mu1) * rs1 * g4.y + e4.y;
        t1.z = (a1.z - mu1) * rs1 * g4.z + e4.z;
        t1.w = (a1.w - mu1) * rs1 * g4.w + e4.w;
        __syncthreads();
        As[q * 4 + 0][r] = t0.x; As[q * 4 + 1][r] = t0.y;
        As[q * 4 + 2][r] = t0.z; As[q * 4 + 3][r] = t0.w;
        As[q * 4 + 0][r + 64] = t1.x; As[q * 4 + 1][r + 64] = t1.y;
        As[q * 4 + 2][r + 64] = t1.z; As[q * 4 + 3][r + 64] = t1.w;
        Bs[q * 4 + 0][r] = b0.x; Bs[q * 4 + 1][r] = b0.y;
        Bs[q * 4 + 2][r] = b0.z; Bs[q * 4 + 3][r] = b0.w;
        Bs[q * 4 + 0][r + 64] = b1.x; Bs[q * 4 + 1][r + 64] = b1.y;
        Bs[q * 4 + 2][r + 64] = b1.z; Bs[q * 4 + 3][r + 64] = b1.w;
        __syncthreads();
        if (kt + 1 < 16) {
            const int kn = k0 + 16;
            a0 = *(const float4*)&g_xt[(m0 + r) * 256 + kn + q * 4];
            a1 = *(const float4*)&g_xt[(m0 + r + 64) * 256 + kn + q * 4];
            b0 = *(const float4*)&w[(n0 + r) * 256 + kn + q * 4];
            b1 = *(const float4*)&w[(n0 + r + 64) * 256 + kn + q * 4];
        }
#pragma unroll
        for (int k = 0; k < 16; k++) {
            float4 av0 = *(const float4*)&As[k][ty * 8];
            float4 av1 = *(const float4*)&As[k][ty * 8 + 4];
            ulonglong2 bv0 = *(const ulonglong2*)&Bs[k][tx * 8];
            ulonglong2 bv1 = *(const ulonglong2*)&Bs[k][tx * 8 + 4];
            ull bd0 = bv0.x, bd1 = bv0.y, bd2 = bv1.x, bd3 = bv1.y;
            float am[8] = {av0.x, av0.y, av0.z, av0.w, av1.x, av1.y, av1.z, av1.w};
#pragma unroll
            for (int i = 0; i < 8; i++) {
                ull ad = dupf(am[i]);
                fma2(acc[i][0], ad, bd0);
                fma2(acc[i][1], ad, bd1);
                fma2(acc[i][2], ad, bd2);
                fma2(acc[i][3], ad, bd3);
            }
        }
    }
    const bool isx = (n0 < 512);
    float* dst = isx ? g_xm : g_z;
    const int nb = isx ? n0 : (n0 - 512);
#pragma unroll
    for (int i = 0; i < 8; i++) {
        int gm = m0 + ty * 8 + i;
        float4 v0, v1;
        unpk(acc[i][0], v0.x, v0.y); unpk(acc[i][1], v0.z, v0.w);
        unpk(acc[i][2], v1.x, v1.y); unpk(acc[i][3], v1.z, v1.w);
        *(float4*)&dst[gm * 512 + nb + tx * 8]     = v0;
        *(float4*)&dst[gm * 512 + nb + tx * 8 + 4] = v1;
    }
}

// =====================================================================
// K5: causal depthwise conv (k=3) + SiLU -> u
// =====================================================================
__global__ void k_conv(const float* __restrict__ cw, const float* __restrict__ cb) {
    int idx = blockIdx.x * blockDim.x + threadIdx.x;  // B*L*DI
    int d = idx & 511;
    int l = (idx >> 9) & 4095;
    float x2 = g_xm[idx];
    float x1 = (l >= 1) ? g_xm[idx - 512]  : 0.f;
    float x0 = (l >= 2) ? g_xm[idx - 1024] : 0.f;
    float a = x0 * cw[d * 3] + x1 * cw[d * 3 + 1] + x2 * cw[d * 3 + 2] + cb[d];
    g_u[idx] = a / (1.f + __expf(-a));
}

// =====================================================================
// K6: x_proj GEMM: xdbl = u @ x_proj_w^T  (N=48)
// =====================================================================
__global__ void k_xproj(const float* __restrict__ w) {
    __shared__ float As[16][65];
    __shared__ float Bs[16][65];
    const int m0 = blockIdx.x * 64;
    const int tid = threadIdx.x;
    const int tx = tid & 15, ty = tid >> 4;
    float acc[4][4] = {};
    for (int k0 = 0; k0 < 512; k0 += 16) {
#pragma unroll
        for (int i = 0; i < 4; i++) {
            int idx = tid + i * 256;
            int m = idx >> 4, kk = idx & 15;
            As[kk][m] = g_u[(m0 + m) * 512 + k0 + kk];
        }
#pragma unroll
        for (int i = 0; i < 4; i++) {
            int idx = tid + i * 256;
            int n = idx >> 4, kk = idx & 15;
            Bs[kk][n] = (n < 48) ? w[n * 512 + k0 + kk] : 0.f;
        }
        __syncthreads();
#pragma unroll
        for (int kk = 0; kk < 16; kk++) {
            float a[4], c[4];
#pragma unroll
            for (int i = 0; i < 4; i++) a[i] = As[kk][ty * 4 + i];
#pragma unroll
            for (int j = 0; j < 4; j++) c[j] = Bs[kk][tx * 4 + j];
#pragma unroll
            for (int i = 0; i < 4; i++)
#pragma unroll
                for (int j = 0; j < 4; j++) acc[i][j] += a[i] * c[j];
        }
        __syncthreads();
    }
#pragma unroll
    for (int i = 0; i < 4; i++) {
        int gm = m0 + ty * 4 + i;
#pragma unroll
        for (int j = 0; j < 4; j++) {
            int gn = tx * 4 + j;
            if (gn < 48) g_xdbl[gm * 48 + gn] = acc[i][j];
        }
    }
}

// =====================================================================
// K7: dt_proj GEMM (K=16) + bias + softplus -> dt
// =====================================================================
__global__ void k_dtproj(const float* __restrict__ w, const float* __restrict__ dtb) {
    __shared__ float As[16][65];
    __shared__ float Bs[16][65];
    const int m0 = blockIdx.x * 64;
    const int n0 = blockIdx.y * 64;
    const int tid = threadIdx.x;
    const int tx = tid & 15, ty = tid >> 4;
    float acc[4][4] = {};
#pragma unroll
    for (int i = 0; i < 4; i++) {
        int idx = tid + i * 256;
        int m = idx >> 4, kk = idx & 15;
        As[kk][m] = g_xdbl[(m0 + m) * 48 + kk];
    }
#pragma unroll
    for (int i = 0; i < 4; i++) {
        int idx = tid + i * 256;
        int n = idx >> 4, kk = idx & 15;
        Bs[kk][n] = w[(n0 + n) * 16 + kk];
    }
    __syncthreads();
#pragma unroll
    for (int kk = 0; kk < 16; kk++) {
        float a[4], c[4];
#pragma unroll
        for (int i = 0; i < 4; i++) a[i] = As[kk][ty * 4 + i];
#pragma unroll
        for (int j = 0; j < 4; j++) c[j] = Bs[kk][tx * 4 + j];
#pragma unroll
        for (int i = 0; i < 4; i++)
#pragma unroll
            for (int j = 0; j < 4; j++) acc[i][j] += a[i] * c[j];
    }
#pragma unroll
    for (int i = 0; i < 4; i++) {
        int gm = m0 + ty * 4 + i;
#pragma unroll
        for (int j = 0; j < 4; j++) {
            int gn = n0 + tx * 4 + j;
            float x = acc[i][j] + dtb[gn];
            float sp = (x > 20.f) ? x : log1pf(__expf(x));
            g_dt[gm * 512 + gn] = sp;
        }
    }
}

// =====================================================================
// K8: scan pass 1 — per chunk: P = prod dA, Hc = local final state.
// =====================================================================
__global__ void k_scan1(const float* __restrict__ alog) {
    const int w    = (blockIdx.x * blockDim.x + threadIdx.x) >> 5;
    const int lane = threadIdx.x & 31;
    const int chunk = w & (NCH - 1);
    const int dpair = (w >> 5) & 255;
    const int b     = w >> 13;
    const int s = lane & 15;
    const int d = dpair * 2 + (lane >> 4);
    const float An = -__expf(alog[d * 16 + s]);
    float h = 0.f, P = 1.f;
    const int l0 = chunk * CT_;
    const float* dtp = g_dt   + ((b * LL) + l0) * 512 + d;
    const float* up  = g_u    + ((b * LL) + l0) * 512 + d;
    const float* bcp = g_xdbl + ((b * LL) + l0) * 48 + 16 + s;
#pragma unroll 4
    for (int t = 0; t < CT_; t++) {
        float dtv = dtp[t * 512];
        float uv  = up[t * 512];
        float bc  = bcp[t * 48];
        float dA  = __expf(dtv * An);
        h = fmaf(dA, h, dtv * bc * uv);
        P *= dA;
    }
    const int idx = ((b * 512 + d) * 16 + s) * NCH + chunk;
    g_P[idx]  = P;
    g_Hc[idx] = h;
}

// =====================================================================
// K9: sequential combine across chunks -> hinit per chunk
// =====================================================================
__global__ void k_comb() {
    const int t = blockIdx.x * blockDim.x + threadIdx.x;  // B*DI*DS = 16384
    const int base = t * NCH;
    float h = 0.f;
    for (int c = 0; c < NCH; c++) {
        g_hini[base + c] = h;
        h = g_P[base + c] * h + g_Hc[base + c];
    }
}

// =====================================================================
// K10: scan pass 2 — replay with correct init, y = (sum_s h*C + u*D)*silu(z)
// =====================================================================
__global__ void k_scan2(const float* __restrict__ alog, const float* __restrict__ Dp) {
    const int w    = (blockIdx.x * blockDim.x + threadIdx.x) >> 5;
    const int lane = threadIdx.x & 31;
    const int chunk = w & (NCH - 1);
    const int dpair = (w >> 5) & 255;
    const int b     = w >> 13;
    const int s = lane & 15;
    const int d = dpair * 2 + (lane >> 4);
    const float An = -__expf(alog[d * 16 + s]);
    const float Dv = Dp[d];
    const int idx0 = ((b * 512 + d) * 16 + s) * NCH + chunk;
    float h = g_hini[idx0];
    const int l0 = chunk * CT_;
    const float* dtp = g_dt   + ((b * LL) + l0) * 512 + d;
    const float* up  = g_u    + ((b * LL) + l0) * 512 + d;
    const float* bcp = g_xdbl + ((b * LL) + l0) * 48 + 16 + s;
    const float* ccp = g_xdbl + ((b * LL) + l0) * 48 + 32 + s;
    const float* zp  = g_z    + ((b * LL) + l0) * 512 + d;
    float* yp        = g_yfin + ((b * LL) + l0) * 512 + d;
#pragma unroll 2
    for (int t = 0; t < CT_; t++) {
        float dtv = dtp[t * 512];
        float uv  = up[t * 512];
        float bc  = bcp[t * 48];
        float cc  = ccp[t * 48];
        float dA  = __expf(dtv * An);
        h = fmaf(dA, h, dtv * bc * uv);
        float part = h * cc;
        part += __shfl_xor_sync(0xffffffffu, part, 1);
        part += __shfl_xor_sync(0xffffffffu, part, 2);
        part += __shfl_xor_sync(0xffffffffu, part, 4);
        part += __shfl_xor_sync(0xffffffffu, part, 8);
        if (s == 0) {
            float zv = zp[t * 512];
            float y = (part + uv * Dv) * (zv / (1.f + __expf(-zv)));
            yp[t * 512] = y;
        }
    }
}

// =====================================================================
// K11: out_proj GEMM (128x128x16 tile, FFMA2) + residual add
// =====================================================================
__global__ void __launch_bounds__(256, 2)
k_outproj2(const float* __restrict__ w, float* __restrict__ out) {
    __shared__ float As[16][132];
    __shared__ float Bs[16][132];
    const int m0 = blockIdx.x * 128;
    const int n0 = blockIdx.y * 128;
    const int tid = threadIdx.x;
    const int tx = tid & 15, ty = tid >> 4;
    const int r = tid >> 2, q = tid & 3;
    ull acc[8][4];
#pragma unroll
    for (int i = 0; i < 8; i++)
#pragma unroll
        for (int j = 0; j < 4; j++) acc[i][j] = 0ull;

    float4 a0 = *(const float4*)&g_yfin[(m0 + r) * 512 + q * 4];
    float4 a1 = *(const float4*)&g_yfin[(m0 + r + 64) * 512 + q * 4];
    float4 b0 = *(const float4*)&w[(n0 + r) * 512 + q * 4];
    float4 b1 = *(const float4*)&w[(n0 + r + 64) * 512 + q * 4];

    for (int kt = 0; kt < 32; kt++) {
        __syncthreads();
        As[q * 4 + 0][r] = a0.x; As[q * 4 + 1][r] = a0.y;
        As[q * 4 + 2][r] = a0.z; As[q * 4 + 3][r] = a0.w;
        As[q * 4 + 0][r + 64] = a1.x; As[q * 4 + 1][r + 64] = a1.y;
        As[q * 4 + 2][r + 64] = a1.z; As[q * 4 + 3][r + 64] = a1.w;
        Bs[q * 4 + 0][r] = b0.x; Bs[q * 4 + 1][r] = b0.y;
        Bs[q * 4 + 2][r] = b0.z; Bs[q * 4 + 3][r] = b0.w;
        Bs[q * 4 + 0][r + 64] = b1.x; Bs[q * 4 + 1][r + 64] = b1.y;
        Bs[q * 4 + 2][r + 64] = b1.z; Bs[q * 4 + 3][r + 64] = b1.w;
        __syncthreads();
        if (kt + 1 < 32) {
            const int kn = (kt + 1) * 16;
            a0 = *(const float4*)&g_yfin[(m0 + r) * 512 + kn + q * 4];
            a1 = *(const float4*)&g_yfin[(m0 + r + 64) * 512 + kn + q * 4];
            b0 = *(const float4*)&w[(n0 + r) * 512 + kn + q * 4];
            b1 = *(const float4*)&w[(n0 + r + 64) * 512 + kn + q * 4];
        }
#pragma unroll
        for (int k = 0; k < 16; k++) {
            float4 av0 = *(const float4*)&As[k][ty * 8];
            float4 av1 = *(const float4*)&As[k][ty * 8 + 4];
            ulonglong2 bv0 = *(const ulonglong2*)&Bs[k][tx * 8];
            ulonglong2 bv1 = *(const ulonglong2*)&Bs[k][tx * 8 + 4];
            ull bd0 = bv0.x, bd1 = bv0.y, bd2 = bv1.x, bd3 = bv1.y;
            float am[8] = {av0.x, av0.y, av0.z, av0.w, av1.x, av1.y, av1.z, av1.w};
#pragma unroll
            for (int i = 0; i < 8; i++) {
                ull ad = dupf(am[i]);
                fma2(acc[i][0], ad, bd0);
                fma2(acc[i][1], ad, bd1);
                fma2(acc[i][2], ad, bd2);
                fma2(acc[i][3], ad, bd3);
            }
        }
    }
    // epilogue: transpose per-thread, add residual, store (B,C,HW)
    float s[8][8];
#pragma unroll
    for (int i = 0; i < 8; i++)
#pragma unroll
        for (int jp = 0; jp < 4; jp++)
            unpk(acc[i][jp], s[i][2 * jp], s[i][2 * jp + 1]);
    const int b  = m0 >> 12;
    const int l0 = (m0 & 4095) + ty * 8;
#pragma unroll
    for (int j = 0; j < 8; j++) {
        int gn = n0 + tx * 8 + j;
        const float* fu = &g_fused[(b * 256 + gn) * 4096 + l0];
        float4 f0 = *(const float4*)fu;
        float4 f1 = *(const float4*)(fu + 4);
        float4 o0, o1;
        o0.x = s[0][j] + f0.x; o0.y = s[1][j] + f0.y;
        o0.z = s[2][j] + f0.z; o0.w = s[3][j] + f0.w;
        o1.x = s[4][j] + f1.x; o1.y = s[5][j] + f1.y;
        o1.z = s[6][j] + f1.z; o1.w = s[7][j] + f1.w;
        *(float4*)&out[(b * 256 + gn) * 4096 + l0]     = o0;
        *(float4*)&out[(b * 256 + gn) * 4096 + l0 + 4] = o1;
    }
}

// =====================================================================
extern "C" void kernel_launch(void* const* d_in, const int* in_sizes, int n_in,
                              void* d_out, int out_size) {
    const float* resnet = (const float*)d_in[0];
    const float* scp    = (const float*)d_in[1];
    const float* scpw   = (const float*)d_in[2];
    const float* sg = (const float*)d_in[3];
    const float* sb = (const float*)d_in[4];
    const float* sm = (const float*)d_in[5];
    const float* sv = (const float*)d_in[6];
    const float* rg = (const float*)d_in[7];
    const float* rb = (const float*)d_in[8];
    const float* rm = (const float*)d_in[9];
    const float* rv = (const float*)d_in[10];
    const float* lg = (const float*)d_in[11];
    const float* lb = (const float*)d_in[12];
    const float* inw = (const float*)d_in[13];
    const float* cw  = (const float*)d_in[14];
    const float* cb  = (const float*)d_in[15];
    const float* xw  = (const float*)d_in[16];
    const float* dtw = (const float*)d_in[17];
    const float* dtb = (const float*)d_in[18];
    const float* alog = (const float*)d_in[19];
    const float* Dp   = (const float*)d_in[20];
    const float* ow   = (const float*)d_in[21];
    float* out = (float*)d_out;

    k_scp    <<<dim3(16, 4, 2), 256>>>(scp, scpw, sg, sb, sm, sv);
    k_fuse   <<<dim3(128, 8, 2), dim3(32, 8)>>>(resnet, rg, rb, rm, rv);
    k_lnstats<<<NB * LL, 256>>>();
    k_inproj2<<<dim3(64, 8), 256>>>(inw, lg, lb);
    k_conv   <<<(NB * LL * DI_) / 256, 256>>>(cw, cb);
    k_xproj  <<<dim3(128, 1), 256>>>(xw);
    k_dtproj <<<dim3(128, 8), 256>>>(dtw, dtb);
    k_scan1  <<<2048, 256>>>(alog);
    k_comb   <<<64, 256>>>();
    k_scan2  <<<2048, 256>>>(alog, Dp);
    k_outproj2<<<dim3(64, 2), 256>>>(ow, out);
}

// round 3
// speedup vs baseline: 1.3024x; 1.0446x over previous
#include <cuda_runtime.h>

// ---------------- problem constants ----------------
#define NB   2
#define CR_  256
#define CS_  512
#define LL   4096     // 64*64
#define PS_  1024     // 32*32
#define DI_  512
#define DS_  16
#define NCH  32       // scan chunks
#define CT_  128      // chunk length (NCH*CT_ == LL)
#define EPSF 1e-5f

typedef unsigned long long ull;

// packed f32x2 helpers (FFMA2 path — ptxas never auto-generates this)
__device__ __forceinline__ ull dupf(float x) {
    ull r; unsigned u = __float_as_uint(x);
    asm("mov.b64 %0, {%1, %2};" : "=l"(r) : "r"(u), "r"(u));
    return r;
}
__device__ __forceinline__ void fma2(ull& d, ull a, ull b) {
    asm("fma.rn.f32x2 %0, %1, %2, %3;" : "=l"(d) : "l"(a), "l"(b), "l"(d));
}
__device__ __forceinline__ void unpk(ull v, float& lo, float& hi) {
    unsigned a, b;
    asm("mov.b64 {%0, %1}, %2;" : "=r"(a), "=r"(b) : "l"(v));
    lo = __uint_as_float(a); hi = __uint_as_float(b);
}

// ---------------- scratch (static device allocs only) ----------------
__device__ float  g_sp   [NB*CR_*PS_];
__device__ float  g_fused[NB*CR_*LL];
__device__ float  g_xt   [NB*LL*CR_];
__device__ float  g_stats[NB*LL*2];
__device__ float  g_xm   [NB*LL*DI_];
__device__ float  g_z    [NB*LL*DI_];
__device__ float  g_u    [NB*LL*DI_];
__device__ float  g_dtin [NB*LL*DS_];
__device__ float2 g_bcc  [NB*LL*DS_];     // {B_s, C_s} interleaved
__device__ float2 g_a    [NB*LL*DI_];     // {dt, dt*u}
__device__ float2 g_uz   [NB*LL*DI_];     // {u, silu(z)}
__device__ float  g_P    [NB*DI_*DS_*NCH];
__device__ float  g_Hc   [NB*DI_*DS_*NCH];
__device__ float  g_hini [NB*DI_*DS_*NCH];
__device__ float  g_yfin [NB*LL*DI_];

// =====================================================================
// K1: scp 1x1 conv GEMM + BN
// =====================================================================
__global__ void k_scp(const float* __restrict__ scp, const float* __restrict__ w,
                      const float* __restrict__ gg, const float* __restrict__ bb,
                      const float* __restrict__ mm, const float* __restrict__ vv) {
    __shared__ float As[16][65];
    __shared__ float Bs[16][65];
    const int b  = blockIdx.z;
    const int o0 = blockIdx.y * 64;
    const int p0 = blockIdx.x * 64;
    const int tid = threadIdx.x;
    const int tx = tid & 15, ty = tid >> 4;
    float acc[4][4] = {};
    for (int k0 = 0; k0 < 512; k0 += 16) {
#pragma unroll
        for (int i = 0; i < 4; i++) {
            int idx = tid + i * 256;
            int o = idx >> 4, kk = idx & 15;
            As[kk][o] = w[(o0 + o) * 512 + k0 + kk];
        }
#pragma unroll
        for (int i = 0; i < 4; i++) {
            int idx = tid + i * 256;
            int kk = idx >> 6, p = idx & 63;
            Bs[kk][p] = scp[(b * 512 + k0 + kk) * 1024 + p0 + p];
        }
        __syncthreads();
#pragma unroll
        for (int kk = 0; kk < 16; kk++) {
            float a[4], c[4];
#pragma unroll
            for (int i = 0; i < 4; i++) a[i] = As[kk][ty * 4 + i];
#pragma unroll
            for (int j = 0; j < 4; j++) c[j] = Bs[kk][tx * 4 + j];
#pragma unroll
            for (int i = 0; i < 4; i++)
#pragma unroll
                for (int j = 0; j < 4; j++) acc[i][j] += a[i] * c[j];
        }
        __syncthreads();
    }
#pragma unroll
    for (int i = 0; i < 4; i++) {
        int o = o0 + ty * 4 + i;
        float inv  = gg[o] * rsqrtf(vv[o] + EPSF);
        float beta = bb[o] - mm[o] * inv;
#pragma unroll
        for (int j = 0; j < 4; j++) {
            int p = p0 + tx * 4 + j;
            g_sp[(b * 256 + o) * 1024 + p] = acc[i][j] * inv + beta;
        }
    }
}

// =====================================================================
// K2: fused = BN(resnet) + bilinear(sp); write (B,C,HW) and (B,HW,C)
// =====================================================================
__global__ void k_fuse(const float* __restrict__ res,
                       const float* __restrict__ rg, const float* __restrict__ rb,
                       const float* __restrict__ rm, const float* __restrict__ rv) {
    __shared__ float tile[32][33];
    const int b  = blockIdx.z;
    const int c0 = blockIdx.y * 32;
    const int l0 = blockIdx.x * 32;
    const int tx = threadIdx.x, ty = threadIdx.y;
    const int l = l0 + tx;
    const int h = l >> 6, wq = l & 63;
    float sh = h * 0.5f - 0.25f;
    float sw = wq * 0.5f - 0.25f;
    int h0 = (int)floorf(sh); float fh = sh - (float)h0;
    int w0 = (int)floorf(sw); float fw = sw - (float)w0;
    int h0c = max(h0, 0), h1c = min(h0 + 1, 31);
    int w0c = max(w0, 0), w1c = min(w0 + 1, 31);
#pragma unroll
    for (int i = 0; i < 4; i++) {
        int c = c0 + ty + i * 8;
        float inv  = rg[c] * rsqrtf(rv[c] + EPSF);
        float beta = rb[c] - rm[c] * inv;
        float val = res[(b * 256 + c) * 4096 + l] * inv + beta;
        const float* spb = g_sp + (b * 256 + c) * 1024;
        float s00 = spb[h0c * 32 + w0c], s01 = spb[h0c * 32 + w1c];
        float s10 = spb[h1c * 32 + w0c], s11 = spb[h1c * 32 + w1c];
        val += (1.f - fh) * ((1.f - fw) * s00 + fw * s01)
             +        fh  * ((1.f - fw) * s10 + fw * s11);
        g_fused[(b * 256 + c) * 4096 + l] = val;
        tile[ty + i * 8][tx] = val;
    }
    __syncthreads();
#pragma unroll
    for (int i = 0; i < 4; i++) {
        int c  = c0 + tx;
        int ll = l0 + ty + i * 8;
        g_xt[(b * 4096 + ll) * 256 + c] = tile[tx][ty + i * 8];
    }
}

// =====================================================================
// K3: LayerNorm row stats
// =====================================================================
__global__ void k_lnstats() {
    const int row = blockIdx.x;
    float v = g_xt[row * 256 + threadIdx.x];
    float s = v, sq = v * v;
#pragma unroll
    for (int o = 16; o; o >>= 1) {
        s  += __shfl_xor_sync(0xffffffffu, s,  o);
        sq += __shfl_xor_sync(0xffffffffu, sq, o);
    }
    __shared__ float ss[8], ssq[8];
    const int wid = threadIdx.x >> 5;
    if ((threadIdx.x & 31) == 0) { ss[wid] = s; ssq[wid] = sq; }
    __syncthreads();
    if (threadIdx.x == 0) {
        float S = 0.f, Q = 0.f;
#pragma unroll
        for (int i = 0; i < 8; i++) { S += ss[i]; Q += ssq[i]; }
        float mu  = S * (1.f / 256.f);
        float var = Q * (1.f / 256.f) - mu * mu;
        g_stats[row * 2]     = mu;
        g_stats[row * 2 + 1] = rsqrtf(var + EPSF);
    }
}

// =====================================================================
// K4: in_proj GEMM: 128x128 tile, ktile=8, A pre-dup'd in smem,
//     double-buffered (1 sync/ktile), FFMA2 inner loop, fused LN.
// =====================================================================
__global__ void __launch_bounds__(256, 2)
k_inproj3(const float* __restrict__ w,
          const float* __restrict__ lg, const float* __restrict__ lb) {
    __shared__ ull   As2[2][8][130];
    __shared__ float Bs [2][8][132];
    const int m0 = blockIdx.x * 128;
    const int n0 = blockIdx.y * 128;
    const int tid = threadIdx.x;
    const int tx = tid & 15, ty = tid >> 4;
    const int r = tid >> 1;           // 0..127
    const int q = (tid & 1) * 4;      // k offset 0 or 4
    const float mu = g_stats[(m0 + r) * 2];
    const float rs = g_stats[(m0 + r) * 2 + 1];
    ull acc[8][4];
#pragma unroll
    for (int i = 0; i < 8; i++)
#pragma unroll
        for (int j = 0; j < 4; j++) acc[i][j] = 0ull;

    float4 a = *(const float4*)&g_xt[(m0 + r) * 256 + q];
    float4 b = *(const float4*)&w[(n0 + r) * 256 + q];
    float4 g4 = *(const float4*)&lg[q];
    float4 e4 = *(const float4*)&lb[q];
    int buf = 0;
    {
        float4 t;
        t.x = (a.x - mu) * rs * g4.x + e4.x;
        t.y = (a.y - mu) * rs * g4.y + e4.y;
        t.z = (a.z - mu) * rs * g4.z + e4.z;
        t.w = (a.w - mu) * rs * g4.w + e4.w;
        As2[0][q + 0][r] = dupf(t.x); As2[0][q + 1][r] = dupf(t.y);
        As2[0][q + 2][r] = dupf(t.z); As2[0][q + 3][r] = dupf(t.w);
        Bs[0][q + 0][r] = b.x; Bs[0][q + 1][r] = b.y;
        Bs[0][q + 2][r] = b.z; Bs[0][q + 3][r] = b.w;
    }
    __syncthreads();
    for (int kt = 0; kt < 32; kt++) {
        if (kt < 31) {
            const int kn = (kt + 1) * 8 + q;
            a  = *(const float4*)&g_xt[(m0 + r) * 256 + kn];
            b  = *(const float4*)&w[(n0 + r) * 256 + kn];
            g4 = *(const float4*)&lg[kn];
            e4 = *(const float4*)&lb[kn];
        }
#pragma unroll
        for (int k = 0; k < 8; k++) {
            ulonglong2 A01 = *(const ulonglong2*)&As2[buf][k][ty * 8];
            ulonglong2 A23 = *(const ulonglong2*)&As2[buf][k][ty * 8 + 2];
            ulonglong2 A45 = *(const ulonglong2*)&As2[buf][k][ty * 8 + 4];
            ulonglong2 A67 = *(const ulonglong2*)&As2[buf][k][ty * 8 + 6];
            ulonglong2 B01 = *(const ulonglong2*)&Bs[buf][k][tx * 8];
            ulonglong2 B23 = *(const ulonglong2*)&Bs[buf][k][tx * 8 + 4];
            ull ad[8] = {A01.x, A01.y, A23.x, A23.y, A45.x, A45.y, A67.x, A67.y};
            ull bd[4] = {B01.x, B01.y, B23.x, B23.y};
#pragma unroll
            for (int i = 0; i < 8; i++) {
                fma2(acc[i][0], ad[i], bd[0]);
                fma2(acc[i][1], ad[i], bd[1]);
                fma2(acc[i][2], ad[i], bd[2]);
                fma2(acc[i][3], ad[i], bd[3]);
            }
        }
        if (kt < 31) {
            float4 t;
            t.x = (a.x - mu) * rs * g4.x + e4.x;
            t.y = (a.y - mu) * rs * g4.y + e4.y;
            t.z = (a.z - mu) * rs * g4.z + e4.z;
            t.w = (a.w - mu) * rs * g4.w + e4.w;
            int nb = buf ^ 1;
            As2[nb][q + 0][r] = dupf(t.x); As2[nb][q + 1][r] = dupf(t.y);
            As2[nb][q + 2][r] = dupf(t.z); As2[nb][q + 3][r] = dupf(t.w);
            Bs[nb][q + 0][r] = b.x; Bs[nb][q + 1][r] = b.y;
            Bs[nb][q + 2][r] = b.z; Bs[nb][q + 3][r] = b.w;
            __syncthreads();
            buf ^= 1;
        }
    }
    const bool isx = (n0 < 512);
    float* dst = isx ? g_xm : g_z;
    const int nb2 = isx ? n0 : (n0 - 512);
#pragma unroll
    for (int i = 0; i < 8; i++) {
        int gm = m0 + ty * 8 + i;
        float4 v0, v1;
        unpk(acc[i][0], v0.x, v0.y); unpk(acc[i][1], v0.z, v0.w);
        unpk(acc[i][2], v1.x, v1.y); unpk(acc[i][3], v1.z, v1.w);
        *(float4*)&dst[gm * 512 + nb2 + tx * 8]     = v0;
        *(float4*)&dst[gm * 512 + nb2 + tx * 8 + 4] = v1;
    }
}

// =====================================================================
// K5: causal depthwise conv (k=3) + SiLU -> u ; also write {u, silu(z)}
// =====================================================================
__global__ void k_conv(const float* __restrict__ cw, const float* __restrict__ cb) {
    int idx = blockIdx.x * blockDim.x + threadIdx.x;
    int d = idx & 511;
    int l = (idx >> 9) & 4095;
    float x2 = g_xm[idx];
    float x1 = (l >= 1) ? g_xm[idx - 512]  : 0.f;
    float x0 = (l >= 2) ? g_xm[idx - 1024] : 0.f;
    float a = x0 * cw[d * 3] + x1 * cw[d * 3 + 1] + x2 * cw[d * 3 + 2] + cb[d];
    float u = a / (1.f + __expf(-a));
    g_u[idx] = u;
    float zv = g_z[idx];
    float2 p; p.x = u; p.y = zv / (1.f + __expf(-zv));
    g_uz[idx] = p;
}

// =====================================================================
// K6: x_proj GEMM (N=48): writes dt_in dense + {bc,cc} interleaved
// =====================================================================
__global__ void k_xproj(const float* __restrict__ w) {
    __shared__ float As[16][65];
    __shared__ float Bs[16][65];
    const int m0 = blockIdx.x * 64;
    const int tid = threadIdx.x;
    const int tx = tid & 15, ty = tid >> 4;
    float acc[4][4] = {};
    for (int k0 = 0; k0 < 512; k0 += 16) {
#pragma unroll
        for (int i = 0; i < 4; i++) {
            int idx = tid + i * 256;
            int m = idx >> 4, kk = idx & 15;
            As[kk][m] = g_u[(m0 + m) * 512 + k0 + kk];
        }
#pragma unroll
        for (int i = 0; i < 4; i++) {
            int idx = tid + i * 256;
            int n = idx >> 4, kk = idx & 15;
            Bs[kk][n] = (n < 48) ? w[n * 512 + k0 + kk] : 0.f;
        }
        __syncthreads();
#pragma unroll
        for (int kk = 0; kk < 16; kk++) {
            float a[4], c[4];
#pragma unroll
            for (int i = 0; i < 4; i++) a[i] = As[kk][ty * 4 + i];
#pragma unroll
            for (int j = 0; j < 4; j++) c[j] = Bs[kk][tx * 4 + j];
#pragma unroll
            for (int i = 0; i < 4; i++)
#pragma unroll
                for (int j = 0; j < 4; j++) acc[i][j] += a[i] * c[j];
        }
        __syncthreads();
    }
    float* bccf = (float*)g_bcc;
#pragma unroll
    for (int i = 0; i < 4; i++) {
        int gm = m0 + ty * 4 + i;
#pragma unroll
        for (int j = 0; j < 4; j++) {
            int gn = tx * 4 + j;
            float v = acc[i][j];
            if (gn < 16)      g_dtin[gm * 16 + gn] = v;
            else if (gn < 32) bccf[gm * 32 + 2 * (gn - 16)] = v;
            else if (gn < 48) bccf[gm * 32 + 2 * (gn - 32) + 1] = v;
        }
    }
}

// =====================================================================
// K7: dt_proj GEMM (K=16) + softplus; writes {dt, dt*u}
// =====================================================================
__global__ void k_dtproj(const float* __restrict__ w, const float* __restrict__ dtb) {
    __shared__ float As[16][65];
    __shared__ float Bs[16][65];
    const int m0 = blockIdx.x * 64;
    const int n0 = blockIdx.y * 64;
    const int tid = threadIdx.x;
    const int tx = tid & 15, ty = tid >> 4;
    float acc[4][4] = {};
#pragma unroll
    for (int i = 0; i < 4; i++) {
        int idx = tid + i * 256;
        int m = idx >> 4, kk = idx & 15;
        As[kk][m] = g_dtin[(m0 + m) * 16 + kk];
    }
#pragma unroll
    for (int i = 0; i < 4; i++) {
        int idx = tid + i * 256;
        int n = idx >> 4, kk = idx & 15;
        Bs[kk][n] = w[(n0 + n) * 16 + kk];
    }
    __syncthreads();
#pragma unroll
    for (int kk = 0; kk < 16; kk++) {
        float a[4], c[4];
#pragma unroll
        for (int i = 0; i < 4; i++) a[i] = As[kk][ty * 4 + i];
#pragma unroll
        for (int j = 0; j < 4; j++) c[j] = Bs[kk][tx * 4 + j];
#pragma unroll
        for (int i = 0; i < 4; i++)
#pragma unroll
            for (int j = 0; j < 4; j++) acc[i][j] += a[i] * c[j];
    }
#pragma unroll
    for (int i = 0; i < 4; i++) {
        int gm = m0 + ty * 4 + i;
        float4 u4 = *(const float4*)&g_u[gm * 512 + n0 + tx * 4];
        float um[4] = {u4.x, u4.y, u4.z, u4.w};
#pragma unroll
        for (int j = 0; j < 4; j++) {
            int gn = n0 + tx * 4 + j;
            float x = acc[i][j] + dtb[gn];
            float sp = (x > 20.f) ? x : log1pf(__expf(x));
            float2 p; p.x = sp; p.y = sp * um[j];
            g_a[gm * 512 + gn] = p;
        }
    }
}

// =====================================================================
// K8: scan pass 1 — per chunk: P = prod dA, Hc = local final state
// =====================================================================
__global__ void k_scan1(const float* __restrict__ alog) {
    const int w    = (blockIdx.x * blockDim.x + threadIdx.x) >> 5;
    const int lane = threadIdx.x & 31;
    const int chunk = w & (NCH - 1);
    const int dpair = (w >> 5) & 255;
    const int b     = w >> 13;
    const int s = lane & 15;
    const int d = dpair * 2 + (lane >> 4);
    const float An = -__expf(alog[d * 16 + s]);
    float h = 0.f, P = 1.f;
    const int l0 = chunk * CT_;
    const float2* ap = g_a   + (size_t)(b * LL + l0) * 512 + d;
    const float2* bp = g_bcc + (size_t)(b * LL + l0) * 16 + s;
#pragma unroll 4
    for (int t = 0; t < CT_; t++) {
        float2 av = ap[t * 512];
        float2 bc = bp[t * 16];
        float dA  = __expf(av.x * An);
        h = fmaf(dA, h, av.y * bc.x);
        P *= dA;
    }
    const int idx = ((b * 512 + d) * 16 + s) * NCH + chunk;
    g_P[idx]  = P;
    g_Hc[idx] = h;
}

// =====================================================================
// K9: sequential combine across chunks
// =====================================================================
__global__ void k_comb() {
    const int t = blockIdx.x * blockDim.x + threadIdx.x;
    const int base = t * NCH;
    float h = 0.f;
    for (int c = 0; c < NCH; c++) {
        g_hini[base + c] = h;
        h = g_P[base + c] * h + g_Hc[base + c];
    }
}

// =====================================================================
// K10: scan pass 2 — replay, y = (sum_s h*C + u*D)*silu(z)
// =====================================================================
__global__ void k_scan2(const float* __restrict__ alog, const float* __restrict__ Dp) {
    const int w    = (blockIdx.x * blockDim.x + threadIdx.x) >> 5;
    const int lane = threadIdx.x & 31;
    const int chunk = w & (NCH - 1);
    const int dpair = (w >> 5) & 255;
    const int b     = w >> 13;
    const int s = lane & 15;
    const int d = dpair * 2 + (lane >> 4);
    const float An = -__expf(alog[d * 16 + s]);
    const float Dv = Dp[d];
    const int idx0 = ((b * 512 + d) * 16 + s) * NCH + chunk;
    float h = g_hini[idx0];
    const int l0 = chunk * CT_;
    const float2* ap = g_a   + (size_t)(b * LL + l0) * 512 + d;
    const float2* bp = g_bcc + (size_t)(b * LL + l0) * 16 + s;
    const float2* up = g_uz  + (size_t)(b * LL + l0) * 512 + d;
    float* yp        = g_yfin + (size_t)(b * LL + l0) * 512 + d;
#pragma unroll 2
    for (int t = 0; t < CT_; t++) {
        float2 av = ap[t * 512];
        float2 bc = bp[t * 16];
        float dA  = __expf(av.x * An);
        h = fmaf(dA, h, av.y * bc.x);
        float part = h * bc.y;
        part += __shfl_xor_sync(0xffffffffu, part, 1);
        part += __shfl_xor_sync(0xffffffffu, part, 2);
        part += __shfl_xor_sync(0xffffffffu, part, 4);
        part += __shfl_xor_sync(0xffffffffu, part, 8);
        if (s == 0) {
            float2 uzv = up[t * 512];
            yp[t * 512] = (part + uzv.x * Dv) * uzv.y;
        }
    }
}

// =====================================================================
// K11: out_proj GEMM (128x128, ktile=8, dup'd A, double-buffered) + residual
// =====================================================================
__global__ void __launch_bounds__(256, 2)
k_outproj3(const float* __restrict__ w, float* __restrict__ out) {
    __shared__ ull   As2[2][8][130];
    __shared__ float Bs [2][8][132];
    const int m0 = blockIdx.x * 128;
    const int n0 = blockIdx.y * 128;
    const int tid = threadIdx.x;
    const int tx = tid & 15, ty = tid >> 4;
    const int r = tid >> 1;
    const int q = (tid & 1) * 4;
    ull acc[8][4];
#pragma unroll
    for (int i = 0; i < 8; i++)
#pragma unroll
        for (int j = 0; j < 4; j++) acc[i][j] = 0ull;

    float4 a = *(const float4*)&g_yfin[(m0 + r) * 512 + q];
    float4 b = *(const float4*)&w[(n0 + r) * 512 + q];
    int buf = 0;
    As2[0][q + 0][r] = dupf(a.x); As2[0][q + 1][r] = dupf(a.y);
    As2[0][q + 2][r] = dupf(a.z); As2[0][q + 3][r] = dupf(a.w);
    Bs[0][q + 0][r] = b.x; Bs[0][q + 1][r] = b.y;
    Bs[0][q + 2][r] = b.z; Bs[0][q + 3][r] = b.w;
    __syncthreads();
    for (int kt = 0; kt < 64; kt++) {
        if (kt < 63) {
            const int kn = (kt + 1) * 8 + q;
            a = *(const float4*)&g_yfin[(m0 + r) * 512 + kn];
            b = *(const float4*)&w[(n0 + r) * 512 + kn];
        }
#pragma unroll
        for (int k = 0; k < 8; k++) {
            ulonglong2 A01 = *(const ulonglong2*)&As2[buf][k][ty * 8];
            ulonglong2 A23 = *(const ulonglong2*)&As2[buf][k][ty * 8 + 2];
            ulonglong2 A45 = *(const ulonglong2*)&As2[buf][k][ty * 8 + 4];
            ulonglong2 A67 = *(const ulonglong2*)&As2[buf][k][ty * 8 + 6];
            ulonglong2 B01 = *(const ulonglong2*)&Bs[buf][k][tx * 8];
            ulonglong2 B23 = *(const ulonglong2*)&Bs[buf][k][tx * 8 + 4];
            ull ad[8] = {A01.x, A01.y, A23.x, A23.y, A45.x, A45.y, A67.x, A67.y};
            ull bd[4] = {B01.x, B01.y, B23.x, B23.y};
#pragma unroll
            for (int i = 0; i < 8; i++) {
                fma2(acc[i][0], ad[i], bd[0]);
                fma2(acc[i][1], ad[i], bd[1]);
                fma2(acc[i][2], ad[i], bd[2]);
                fma2(acc[i][3], ad[i], bd[3]);
            }
        }
        if (kt < 63) {
            int nb = buf ^ 1;
            As2[nb][q + 0][r] = dupf(a.x); As2[nb][q + 1][r] = dupf(a.y);
            As2[nb][q + 2][r] = dupf(a.z); As2[nb][q + 3][r] = dupf(a.w);
            Bs[nb][q + 0][r] = b.x; Bs[nb][q + 1][r] = b.y;
            Bs[nb][q + 2][r] = b.z; Bs[nb][q + 3][r] = b.w;
            __syncthreads();
            buf ^= 1;
        }
    }
    float s[8][8];
#pragma unroll
    for (int i = 0; i < 8; i++)
#pragma unroll
        for (int jp = 0; jp < 4; jp++)
            unpk(acc[i][jp], s[i][2 * jp], s[i][2 * jp + 1]);
    const int bb = m0 >> 12;
    const int l0 = (m0 & 4095) + ty * 8;
#pragma unroll
    for (int j = 0; j < 8; j++) {
        int gn = n0 + tx * 8 + j;
        const float* fu = &g_fused[(bb * 256 + gn) * 4096 + l0];
        float4 f0 = *(const float4*)fu;
        float4 f1 = *(const float4*)(fu + 4);
        float4 o0, o1;
        o0.x = s[0][j] + f0.x; o0.y = s[1][j] + f0.y;
        o0.z = s[2][j] + f0.z; o0.w = s[3][j] + f0.w;
        o1.x = s[4][j] + f1.x; o1.y = s[5][j] + f1.y;
        o1.z = s[6][j] + f1.z; o1.w = s[7][j] + f1.w;
        *(float4*)&out[(bb * 256 + gn) * 4096 + l0]     = o0;
        *(float4*)&out[(bb * 256 + gn) * 4096 + l0 + 4] = o1;
    }
}

// =====================================================================
extern "C" void kernel_launch(void* const* d_in, const int* in_sizes, int n_in,
                              void* d_out, int out_size) {
    const float* resnet = (const float*)d_in[0];
    const float* scp    = (const float*)d_in[1];
    const float* scpw   = (const float*)d_in[2];
    const float* sg = (const float*)d_in[3];
    const float* sb = (const float*)d_in[4];
    const float* sm = (const float*)d_in[5];
    const float* sv = (const float*)d_in[6];
    const float* rg = (const float*)d_in[7];
    const float* rb = (const float*)d_in[8];
    const float* rm = (const float*)d_in[9];
    const float* rv = (const float*)d_in[10];
    const float* lg = (const float*)d_in[11];
    const float* lb = (const float*)d_in[12];
    const float* inw = (const float*)d_in[13];
    const float* cw  = (const float*)d_in[14];
    const float* cb  = (const float*)d_in[15];
    const float* xw  = (const float*)d_in[16];
    const float* dtw = (const float*)d_in[17];
    const float* dtb = (const float*)d_in[18];
    const float* alog = (const float*)d_in[19];
    const float* Dp   = (const float*)d_in[20];
    const float* ow   = (const float*)d_in[21];
    float* out = (float*)d_out;

    k_scp    <<<dim3(16, 4, 2), 256>>>(scp, scpw, sg, sb, sm, sv);
    k_fuse   <<<dim3(128, 8, 2), dim3(32, 8)>>>(resnet, rg, rb, rm, rv);
    k_lnstats<<<NB * LL, 256>>>();
    k_inproj3<<<dim3(64, 8), 256>>>(inw, lg, lb);
    k_conv   <<<(NB * LL * DI_) / 256, 256>>>(cw, cb);
    k_xproj  <<<dim3(128, 1), 256>>>(xw);
    k_dtproj <<<dim3(128, 8), 256>>>(dtw, dtb);
    k_scan1  <<<2048, 256>>>(alog);
    k_comb   <<<64, 256>>>();
    k_scan2  <<<2048, 256>>>(alog, Dp);
    k_outproj3<<<dim3(64, 2), 256>>>(ow, out);
}

// round 4
// speedup vs baseline: 1.4838x; 1.1392x over previous
#include <cuda_runtime.h>

// ---------------- problem constants ----------------
#define NB   2
#define CR_  256
#define CS_  512
#define LL   4096     // 64*64
#define PS_  1024     // 32*32
#define DI_  512
#define DS_  16
#define NCH  32       // scan chunks
#define CT_  128      // chunk length (NCH*CT_ == LL)
#define TT_  (NB*DI_*DS_)   // 16384 scan tracks
#define EPSF 1e-5f
#define LOG2E 1.4426950408889634f

typedef unsigned long long ull;

// packed f32x2 helpers (FFMA2 path — ptxas never auto-generates this)
__device__ __forceinline__ ull dupf(float x) {
    ull r; unsigned u = __float_as_uint(x);
    asm("mov.b64 %0, {%1, %2};" : "=l"(r) : "r"(u), "r"(u));
    return r;
}
__device__ __forceinline__ void fma2(ull& d, ull a, ull b) {
    asm("fma.rn.f32x2 %0, %1, %2, %3;" : "=l"(d) : "l"(a), "l"(b), "l"(d));
}
__device__ __forceinline__ void unpk(ull v, float& lo, float& hi) {
    unsigned a, b;
    asm("mov.b64 {%0, %1}, %2;" : "=r"(a), "=r"(b) : "l"(v));
    lo = __uint_as_float(a); hi = __uint_as_float(b);
}

// ---------------- scratch (static device allocs only) ----------------
__device__ float  g_sp   [NB*CR_*PS_];
__device__ float  g_fused[NB*CR_*LL];
__device__ float  g_xt   [NB*LL*CR_];
__device__ float2 g_psum [NB*LL*8];       // per (row, c-block) partial {sum, sumsq}
__device__ float  g_xm   [NB*LL*DI_];
__device__ float  g_z    [NB*LL*DI_];
__device__ float  g_u    [NB*LL*DI_];
__device__ float  g_dtin [NB*LL*DS_];
__device__ float2 g_bcc  [NB*LL*DS_];     // {B_s, C_s} interleaved
__device__ float2 g_a    [NB*LL*DI_];     // {dt, dt*u}
__device__ float2 g_uz   [NB*LL*DI_];     // {u, silu(z)}
__device__ float  g_P    [NCH*TT_];       // chunk-major
__device__ float  g_Hc   [NCH*TT_];
__device__ float  g_hini [NCH*TT_];
__device__ float  g_yfin [NB*LL*DI_];

// =====================================================================
// K1: scp 1x1 conv GEMM + BN
// =====================================================================
__global__ void k_scp(const float* __restrict__ scp, const float* __restrict__ w,
                      const float* __restrict__ gg, const float* __restrict__ bb,
                      const float* __restrict__ mm, const float* __restrict__ vv) {
    __shared__ float As[16][65];
    __shared__ float Bs[16][65];
    const int b  = blockIdx.z;
    const int o0 = blockIdx.y * 64;
    const int p0 = blockIdx.x * 64;
    const int tid = threadIdx.x;
    const int tx = tid & 15, ty = tid >> 4;
    float acc[4][4] = {};
    for (int k0 = 0; k0 < 512; k0 += 16) {
#pragma unroll
        for (int i = 0; i < 4; i++) {
            int idx = tid + i * 256;
            int o = idx >> 4, kk = idx & 15;
            As[kk][o] = w[(o0 + o) * 512 + k0 + kk];
        }
#pragma unroll
        for (int i = 0; i < 4; i++) {
            int idx = tid + i * 256;
            int kk = idx >> 6, p = idx & 63;
            Bs[kk][p] = scp[(b * 512 + k0 + kk) * 1024 + p0 + p];
        }
        __syncthreads();
#pragma unroll
        for (int kk = 0; kk < 16; kk++) {
            float a[4], c[4];
#pragma unroll
            for (int i = 0; i < 4; i++) a[i] = As[kk][ty * 4 + i];
#pragma unroll
            for (int j = 0; j < 4; j++) c[j] = Bs[kk][tx * 4 + j];
#pragma unroll
            for (int i = 0; i < 4; i++)
#pragma unroll
                for (int j = 0; j < 4; j++) acc[i][j] += a[i] * c[j];
        }
        __syncthreads();
    }
#pragma unroll
    for (int i = 0; i < 4; i++) {
        int o = o0 + ty * 4 + i;
        float inv  = gg[o] * rsqrtf(vv[o] + EPSF);
        float beta = bb[o] - mm[o] * inv;
#pragma unroll
        for (int j = 0; j < 4; j++) {
            int p = p0 + tx * 4 + j;
            g_sp[(b * 256 + o) * 1024 + p] = acc[i][j] * inv + beta;
        }
    }
}

// =====================================================================
// K2: fused = BN(resnet) + bilinear(sp); write (B,C,HW) and (B,HW,C),
//     plus per-block LN partial sums into g_psum.
// =====================================================================
__global__ void k_fuse(const float* __restrict__ res,
                       const float* __restrict__ rg, const float* __restrict__ rb,
                       const float* __restrict__ rm, const float* __restrict__ rv) {
    __shared__ float tile[32][33];
    const int b  = blockIdx.z;
    const int c0 = blockIdx.y * 32;
    const int l0 = blockIdx.x * 32;
    const int tx = threadIdx.x, ty = threadIdx.y;
    const int l = l0 + tx;
    const int h = l >> 6, wq = l & 63;
    float sh = h * 0.5f - 0.25f;
    float sw = wq * 0.5f - 0.25f;
    int h0 = (int)floorf(sh); float fh = sh - (float)h0;
    int w0 = (int)floorf(sw); float fw = sw - (float)w0;
    int h0c = max(h0, 0), h1c = min(h0 + 1, 31);
    int w0c = max(w0, 0), w1c = min(w0 + 1, 31);
#pragma unroll
    for (int i = 0; i < 4; i++) {
        int c = c0 + ty + i * 8;
        float inv  = rg[c] * rsqrtf(rv[c] + EPSF);
        float beta = rb[c] - rm[c] * inv;
        float val = res[(b * 256 + c) * 4096 + l] * inv + beta;
        const float* spb = g_sp + (b * 256 + c) * 1024;
        float s00 = spb[h0c * 32 + w0c], s01 = spb[h0c * 32 + w1c];
        float s10 = spb[h1c * 32 + w0c], s11 = spb[h1c * 32 + w1c];
        val += (1.f - fh) * ((1.f - fw) * s00 + fw * s01)
             +        fh  * ((1.f - fw) * s10 + fw * s11);
        g_fused[(b * 256 + c) * 4096 + l] = val;
        tile[ty + i * 8][tx] = val;
    }
    __syncthreads();
#pragma unroll
    for (int i = 0; i < 4; i++) {
        int c  = c0 + tx;
        int ll = l0 + ty + i * 8;
        g_xt[(b * 4096 + ll) * 256 + c] = tile[tx][ty + i * 8];
    }
    // LN partial sums: warp 0 (32 threads) reduce each l-column over 32 c's
    const int tid = ty * 32 + tx;
    if (tid < 32) {
        float s = 0.f, q = 0.f;
#pragma unroll
        for (int cc = 0; cc < 32; cc++) {
            float v = tile[cc][tid];
            s += v; q += v * v;
        }
        g_psum[(b * 4096 + l0 + tid) * 8 + (c0 >> 5)] = make_float2(s, q);
    }
}

// =====================================================================
// K4: in_proj GEMM: 128x128x16 tile, 8x8 microtile, FFMA2, reg-dup A,
//     double-buffered smem (1 sync / ktile), fused LN (stats from psum).
// =====================================================================
__global__ void __launch_bounds__(256, 2)
k_inproj4(const float* __restrict__ w,
          const float* __restrict__ lg, const float* __restrict__ lb) {
    __shared__ float As[2][16][132];
    __shared__ float Bs[2][16][132];
    const int m0 = blockIdx.x * 128;
    const int n0 = blockIdx.y * 128;
    const int tid = threadIdx.x;
    const int tx = tid & 15, ty = tid >> 4;
    const int r = tid >> 2, q = tid & 3;
    // LN stats for rows m0+r and m0+r+64
    float s0 = 0.f, q0 = 0.f, s1 = 0.f, q1 = 0.f;
#pragma unroll
    for (int i = 0; i < 8; i++) {
        float2 p = g_psum[(m0 + r) * 8 + i];      s0 += p.x; q0 += p.y;
        float2 p2 = g_psum[(m0 + r + 64) * 8 + i]; s1 += p2.x; q1 += p2.y;
    }
    const float mu0 = s0 * (1.f / 256.f);
    const float rs0 = rsqrtf(q0 * (1.f / 256.f) - mu0 * mu0 + EPSF);
    const float mu1 = s1 * (1.f / 256.f);
    const float rs1 = rsqrtf(q1 * (1.f / 256.f) - mu1 * mu1 + EPSF);

    ull acc[8][4];
#pragma unroll
    for (int i = 0; i < 8; i++)
#pragma unroll
        for (int j = 0; j < 4; j++) acc[i][j] = 0ull;

    float4 a0 = *(const float4*)&g_xt[(m0 + r) * 256 + q * 4];
    float4 a1 = *(const float4*)&g_xt[(m0 + r + 64) * 256 + q * 4];
    float4 b0 = *(const float4*)&w[(n0 + r) * 256 + q * 4];
    float4 b1 = *(const float4*)&w[(n0 + r + 64) * 256 + q * 4];
    float4 g4 = *(const float4*)&lg[q * 4];
    float4 e4 = *(const float4*)&lb[q * 4];
    int buf = 0;
    {
        float4 t0, t1;
        t0.x = (a0.x - mu0) * rs0 * g4.x + e4.x;
        t0.y = (a0.y - mu0) * rs0 * g4.y + e4.y;
        t0.z = (a0.z - mu0) * rs0 * g4.z + e4.z;
        t0.w = (a0.w - mu0) * rs0 * g4.w + e4.w;
        t1.x = (a1.x - mu1) * rs1 * g4.x + e4.x;
        t1.y = (a1.y - mu1) * rs1 * g4.y + e4.y;
        t1.z = (a1.z - mu1) * rs1 * g4.z + e4.z;
        t1.w = (a1.w - mu1) * rs1 * g4.w + e4.w;
        As[0][q * 4 + 0][r] = t0.x; As[0][q * 4 + 1][r] = t0.y;
        As[0][q * 4 + 2][r] = t0.z; As[0][q * 4 + 3][r] = t0.w;
        As[0][q * 4 + 0][r + 64] = t1.x; As[0][q * 4 + 1][r + 64] = t1.y;
        As[0][q * 4 + 2][r + 64] = t1.z; As[0][q * 4 + 3][r + 64] = t1.w;
        Bs[0][q * 4 + 0][r] = b0.x; Bs[0][q * 4 + 1][r] = b0.y;
        Bs[0][q * 4 + 2][r] = b0.z; Bs[0][q * 4 + 3][r] = b0.w;
        Bs[0][q * 4 + 0][r + 64] = b1.x; Bs[0][q * 4 + 1][r + 64] = b1.y;
        Bs[0][q * 4 + 2][r + 64] = b1.z; Bs[0][q * 4 + 3][r + 64] = b1.w;
    }
    __syncthreads();
    for (int kt = 0; kt < 16; kt++) {
        if (kt < 15) {
            const int kn = (kt + 1) * 16 + q * 4;
            a0 = *(const float4*)&g_xt[(m0 + r) * 256 + kn];
            a1 = *(const float4*)&g_xt[(m0 + r + 64) * 256 + kn];
            b0 = *(const float4*)&w[(n0 + r) * 256 + kn];
            b1 = *(const float4*)&w[(n0 + r + 64) * 256 + kn];
            g4 = *(const float4*)&lg[kn];
            e4 = *(const float4*)&lb[kn];
        }
#pragma unroll
        for (int k = 0; k < 16; k++) {
            float4 av0 = *(const float4*)&As[buf][k][ty * 8];
            float4 av1 = *(const float4*)&As[buf][k][ty * 8 + 4];
            ulonglong2 bv0 = *(const ulonglong2*)&Bs[buf][k][tx * 8];
            ulonglong2 bv1 = *(const ulonglong2*)&Bs[buf][k][tx * 8 + 4];
            ull bd0 = bv0.x, bd1 = bv0.y, bd2 = bv1.x, bd3 = bv1.y;
            float am[8] = {av0.x, av0.y, av0.z, av0.w, av1.x, av1.y, av1.z, av1.w};
#pragma unroll
            for (int i = 0; i < 8; i++) {
                ull ad = dupf(am[i]);
                fma2(acc[i][0], ad, bd0);
                fma2(acc[i][1], ad, bd1);
                fma2(acc[i][2], ad, bd2);
                fma2(acc[i][3], ad, bd3);
            }
        }
        if (kt < 15) {
            float4 t0, t1;
            t0.x = (a0.x - mu0) * rs0 * g4.x + e4.x;
            t0.y = (a0.y - mu0) * rs0 * g4.y + e4.y;
            t0.z = (a0.z - mu0) * rs0 * g4.z + e4.z;
            t0.w = (a0.w - mu0) * rs0 * g4.w + e4.w;
            t1.x = (a1.x - mu1) * rs1 * g4.x + e4.x;
            t1.y = (a1.y - mu1) * rs1 * g4.y + e4.y;
            t1.z = (a1.z - mu1) * rs1 * g4.z + e4.z;
            t1.w = (a1.w - mu1) * rs1 * g4.w + e4.w;
            int nb = buf ^ 1;
            As[nb][q * 4 + 0][r] = t0.x; As[nb][q * 4 + 1][r] = t0.y;
            As[nb][q * 4 + 2][r] = t0.z; As[nb][q * 4 + 3][r] = t0.w;
            As[nb][q * 4 + 0][r + 64] = t1.x; As[nb][q * 4 + 1][r + 64] = t1.y;
            As[nb][q * 4 + 2][r + 64] = t1.z; As[nb][q * 4 + 3][r + 64] = t1.w;
            Bs[nb][q * 4 + 0][r] = b0.x; Bs[nb][q * 4 + 1][r] = b0.y;
            Bs[nb][q * 4 + 2][r] = b0.z; Bs[nb][q * 4 + 3][r] = b0.w;
            Bs[nb][q * 4 + 0][r + 64] = b1.x; Bs[nb][q * 4 + 1][r + 64] = b1.y;
            Bs[nb][q * 4 + 2][r + 64] = b1.z; Bs[nb][q * 4 + 3][r + 64] = b1.w;
            __syncthreads();
            buf ^= 1;
        }
    }
    const bool isx = (n0 < 512);
    float* dst = isx ? g_xm : g_z;
    const int nb2 = isx ? n0 : (n0 - 512);
#pragma unroll
    for (int i = 0; i < 8; i++) {
        int gm = m0 + ty * 8 + i;
        float4 v0, v1;
        unpk(acc[i][0], v0.x, v0.y); unpk(acc[i][1], v0.z, v0.w);
        unpk(acc[i][2], v1.x, v1.y); unpk(acc[i][3], v1.z, v1.w);
        *(float4*)&dst[gm * 512 + nb2 + tx * 8]     = v0;
        *(float4*)&dst[gm * 512 + nb2 + tx * 8 + 4] = v1;
    }
}

// =====================================================================
// K5: causal depthwise conv (k=3) + SiLU -> u ; {u, silu(z)}; float4
// =====================================================================
__global__ void k_conv4(const float* __restrict__ cw, const float* __restrict__ cb) {
    const int g = blockIdx.x * blockDim.x + threadIdx.x;  // B*L*DI/4
    const int base = g * 4;
    const int d = base & 511;
    const int l = (base >> 9) & 4095;
    float4 x2 = *(const float4*)&g_xm[base];
    float4 x1 = make_float4(0.f, 0.f, 0.f, 0.f);
    float4 x0 = make_float4(0.f, 0.f, 0.f, 0.f);
    if (l >= 1) x1 = *(const float4*)&g_xm[base - 512];
    if (l >= 2) x0 = *(const float4*)&g_xm[base - 1024];
    float4 w0 = *(const float4*)&cw[d * 3];
    float4 w1 = *(const float4*)&cw[d * 3 + 4];
    float4 w2 = *(const float4*)&cw[d * 3 + 8];
    float4 cb4 = *(const float4*)&cb[d];
    float f[12] = {w0.x, w0.y, w0.z, w0.w, w1.x, w1.y, w1.z, w1.w, w2.x, w2.y, w2.z, w2.w};
    float a0 = x0.x * f[0] + x1.x * f[1]  + x2.x * f[2]  + cb4.x;
    float a1 = x0.y * f[3] + x1.y * f[4]  + x2.y * f[5]  + cb4.y;
    float a2 = x0.z * f[6] + x1.z * f[7]  + x2.z * f[8]  + cb4.z;
    float a3 = x0.w * f[9] + x1.w * f[10] + x2.w * f[11] + cb4.w;
    float4 u4;
    u4.x = a0 / (1.f + __expf(-a0));
    u4.y = a1 / (1.f + __expf(-a1));
    u4.z = a2 / (1.f + __expf(-a2));
    u4.w = a3 / (1.f + __expf(-a3));
    *(float4*)&g_u[base] = u4;
    float4 z4 = *(const float4*)&g_z[base];
    float4 p0, p1;
    p0.x = u4.x; p0.y = z4.x / (1.f + __expf(-z4.x));
    p0.z = u4.y; p0.w = z4.y / (1.f + __expf(-z4.y));
    p1.x = u4.z; p1.y = z4.z / (1.f + __expf(-z4.z));
    p1.z = u4.w; p1.w = z4.w / (1.f + __expf(-z4.w));
    *(float4*)&g_uz[base]     = p0;
    *(float4*)&g_uz[base + 2] = p1;
}

// =====================================================================
// K6: x_proj GEMM (N=48): writes dt_in dense + {bc,cc} interleaved
// =====================================================================
__global__ void k_xproj(const float* __restrict__ w) {
    __shared__ float As[16][65];
    __shared__ float Bs[16][65];
    const int m0 = blockIdx.x * 64;
    const int tid = threadIdx.x;
    const int tx = tid & 15, ty = tid >> 4;
    float acc[4][4] = {};
    for (int k0 = 0; k0 < 512; k0 += 16) {
#pragma unroll
        for (int i = 0; i < 4; i++) {
            int idx = tid + i * 256;
            int m = idx >> 4, kk = idx & 15;
            As[kk][m] = g_u[(m0 + m) * 512 + k0 + kk];
        }
#pragma unroll
        for (int i = 0; i < 4; i++) {
            int idx = tid + i * 256;
            int n = idx >> 4, kk = idx & 15;
            Bs[kk][n] = (n < 48) ? w[n * 512 + k0 + kk] : 0.f;
        }
        __syncthreads();
#pragma unroll
        for (int kk = 0; kk < 16; kk++) {
            float a[4], c[4];
#pragma unroll
            for (int i = 0; i < 4; i++) a[i] = As[kk][ty * 4 + i];
#pragma unroll
            for (int j = 0; j < 4; j++) c[j] = Bs[kk][tx * 4 + j];
#pragma unroll
            for (int i = 0; i < 4; i++)
#pragma unroll
                for (int j = 0; j < 4; j++) acc[i][j] += a[i] * c[j];
        }
        __syncthreads();
    }
    float* bccf = (float*)g_bcc;
#pragma unroll
    for (int i = 0; i < 4; i++) {
        int gm = m0 + ty * 4 + i;
#pragma unroll
        for (int j = 0; j < 4; j++) {
            int gn = tx * 4 + j;
            float v = acc[i][j];
            if (gn < 16)      g_dtin[gm * 16 + gn] = v;
            else if (gn < 32) bccf[gm * 32 + 2 * (gn - 16)] = v;
            else if (gn < 48) bccf[gm * 32 + 2 * (gn - 32) + 1] = v;
        }
    }
}

// =====================================================================
// K7: dt_proj GEMM (K=16) + softplus; writes {dt, dt*u}
// =====================================================================
__global__ void k_dtproj(const float* __restrict__ w, const float* __restrict__ dtb) {
    __shared__ float As[16][65];
    __shared__ float Bs[16][65];
    const int m0 = blockIdx.x * 64;
    const int n0 = blockIdx.y * 64;
    const int tid = threadIdx.x;
    const int tx = tid & 15, ty = tid >> 4;
    float acc[4][4] = {};
#pragma unroll
    for (int i = 0; i < 4; i++) {
        int idx = tid + i * 256;
        int m = idx >> 4, kk = idx & 15;
        As[kk][m] = g_dtin[(m0 + m) * 16 + kk];
    }
#pragma unroll
    for (int i = 0; i < 4; i++) {
        int idx = tid + i * 256;
        int n = idx >> 4, kk = idx & 15;
        Bs[kk][n] = w[(n0 + n) * 16 + kk];
    }
    __syncthreads();
#pragma unroll
    for (int kk = 0; kk < 16; kk++) {
        float a[4], c[4];
#pragma unroll
        for (int i = 0; i < 4; i++) a[i] = As[kk][ty * 4 + i];
#pragma unroll
        for (int j = 0; j < 4; j++) c[j] = Bs[kk][tx * 4 + j];
#pragma unroll
        for (int i = 0; i < 4; i++)
#pragma unroll
            for (int j = 0; j < 4; j++) acc[i][j] += a[i] * c[j];
    }
#pragma unroll
    for (int i = 0; i < 4; i++) {
        int gm = m0 + ty * 4 + i;
        float4 u4 = *(const float4*)&g_u[gm * 512 + n0 + tx * 4];
        float um[4] = {u4.x, u4.y, u4.z, u4.w};
#pragma unroll
        for (int j = 0; j < 4; j++) {
            int gn = n0 + tx * 4 + j;
            float x = acc[i][j] + dtb[gn];
            float sp = (x > 20.f) ? x : log1pf(__expf(x));
            float2 p; p.x = sp; p.y = sp * um[j];
            g_a[gm * 512 + gn] = p;
        }
    }
}

// =====================================================================
// K8: scan pass 1 — per chunk: P = prod dA, Hc = local final state
// =====================================================================
__global__ void k_scan1(const float* __restrict__ alog) {
    const int w    = (blockIdx.x * blockDim.x + threadIdx.x) >> 5;
    const int lane = threadIdx.x & 31;
    const int chunk = w & (NCH - 1);
    const int dpair = (w >> 5) & 255;
    const int b     = w >> 13;
    const int s = lane & 15;
    const int d = dpair * 2 + (lane >> 4);
    const float An2 = -__expf(alog[d * 16 + s]) * LOG2E;
    float h = 0.f, P = 1.f;
    const int l0 = chunk * CT_;
    const float2* ap = g_a   + (size_t)(b * LL + l0) * 512 + d;
    const float2* bp = g_bcc + (size_t)(b * LL + l0) * 16 + s;
#pragma unroll 4
    for (int t = 0; t < CT_; t++) {
        float2 av = ap[t * 512];
        float2 bc = bp[t * 16];
        float dA  = exp2f(av.x * An2);
        h = fmaf(dA, h, av.y * bc.x);
        P *= dA;
    }
    const int tI = (b * 512 + d) * 16 + s;
    g_P[chunk * TT_ + tI]  = P;
    g_Hc[chunk * TT_ + tI] = h;
}

// =====================================================================
// K9: sequential combine across chunks (chunk-major: coalesced)
// =====================================================================
__global__ void k_comb() {
    const int t = blockIdx.x * blockDim.x + threadIdx.x;  // 16384
    float h = 0.f;
    for (int c = 0; c < NCH; c++) {
        g_hini[c * TT_ + t] = h;
        h = g_P[c * TT_ + t] * h + g_Hc[c * TT_ + t];
    }
}

// =====================================================================
// K10: scan pass 2 — replay, y = (sum_s h*C + u*D)*silu(z)
// =====================================================================
__global__ void k_scan2(const float* __restrict__ alog, const float* __restrict__ Dp) {
    const int w    = (blockIdx.x * blockDim.x + threadIdx.x) >> 5;
    const int lane = threadIdx.x & 31;
    const int chunk = w & (NCH - 1);
    const int dpair = (w >> 5) & 255;
    const int b     = w >> 13;
    const int s = lane & 15;
    const int d = dpair * 2 + (lane >> 4);
    const float An2 = -__expf(alog[d * 16 + s]) * LOG2E;
    const float Dv = Dp[d];
    const int tI = (b * 512 + d) * 16 + s;
    float h = g_hini[chunk * TT_ + tI];
    const int l0 = chunk * CT_;
    const float2* ap = g_a   + (size_t)(b * LL + l0) * 512 + d;
    const float2* bp = g_bcc + (size_t)(b * LL + l0) * 16 + s;
    const float2* up = g_uz  + (size_t)(b * LL + l0) * 512 + d;
    float* yp        = g_yfin + (size_t)(b * LL + l0) * 512 + d;
#pragma unroll 2
    for (int t = 0; t < CT_; t++) {
        float2 av = ap[t * 512];
        float2 bc = bp[t * 16];
        float dA  = exp2f(av.x * An2);
        h = fmaf(dA, h, av.y * bc.x);
        float part = h * bc.y;
        part += __shfl_xor_sync(0xffffffffu, part, 1);
        part += __shfl_xor_sync(0xffffffffu, part, 2);
        part += __shfl_xor_sync(0xffffffffu, part, 4);
        part += __shfl_xor_sync(0xffffffffu, part, 8);
        if (s == 0) {
            float2 uzv = up[t * 512];
            yp[t * 512] = (part + uzv.x * Dv) * uzv.y;
        }
    }
}

// =====================================================================
// K11: out_proj GEMM (128x128x16 tile, FFMA2, double-buffered) + residual
// =====================================================================
__global__ void __launch_bounds__(256, 2)
k_outproj4(const float* __restrict__ w, float* __restrict__ out) {
    __shared__ float As[2][16][132];
    __shared__ float Bs[2][16][132];
    const int m0 = blockIdx.x * 128;
    const int n0 = blockIdx.y * 128;
    const int tid = threadIdx.x;
    const int tx = tid & 15, ty = tid >> 4;
    const int r = tid >> 2, q = tid & 3;
    ull acc[8][4];
#pragma unroll
    for (int i = 0; i < 8; i++)
#pragma unroll
        for (int j = 0; j < 4; j++) acc[i][j] = 0ull;

    float4 a0 = *(const float4*)&g_yfin[(m0 + r) * 512 + q * 4];
    float4 a1 = *(const float4*)&g_yfin[(m0 + r + 64) * 512 + q * 4];
    float4 b0 = *(const float4*)&w[(n0 + r) * 512 + q * 4];
    float4 b1 = *(const float4*)&w[(n0 + r + 64) * 512 + q * 4];
    int buf = 0;
    As[0][q * 4 + 0][r] = a0.x; As[0][q * 4 + 1][r] = a0.y;
    As[0][q * 4 + 2][r] = a0.z; As[0][q * 4 + 3][r] = a0.w;
    As[0][q * 4 + 0][r + 64] = a1.x; As[0][q * 4 + 1][r + 64] = a1.y;
    As[0][q * 4 + 2][r + 64] = a1.z; As[0][q * 4 + 3][r + 64] = a1.w;
    Bs[0][q * 4 + 0][r] = b0.x; Bs[0][q * 4 + 1][r] = b0.y;
    Bs[0][q * 4 + 2][r] = b0.z; Bs[0][q * 4 + 3][r] = b0.w;
    Bs[0][q * 4 + 0][r + 64] = b1.x; Bs[0][q * 4 + 1][r + 64] = b1.y;
    Bs[0][q * 4 + 2][r + 64] = b1.z; Bs[0][q * 4 + 3][r + 64] = b1.w;
    __syncthreads();
    for (int kt = 0; kt < 32; kt++) {
        if (kt < 31) {
            const int kn = (kt + 1) * 16 + q * 4;
            a0 = *(const float4*)&g_yfin[(m0 + r) * 512 + kn];
            a1 = *(const float4*)&g_yfin[(m0 + r + 64) * 512 + kn];
            b0 = *(const float4*)&w[(n0 + r) * 512 + kn];
            b1 = *(const float4*)&w[(n0 + r + 64) * 512 + kn];
        }
#pragma unroll
        for (int k = 0; k < 16; k++) {
            float4 av0 = *(const float4*)&As[buf][k][ty * 8];
            float4 av1 = *(const float4*)&As[buf][k][ty * 8 + 4];
            ulonglong2 bv0 = *(const ulonglong2*)&Bs[buf][k][tx * 8];
            ulonglong2 bv1 = *(const ulonglong2*)&Bs[buf][k][tx * 8 + 4];
            ull bd0 = bv0.x, bd1 = bv0.y, bd2 = bv1.x, bd3 = bv1.y;
            float am[8] = {av0.x, av0.y, av0.z, av0.w, av1.x, av1.y, av1.z, av1.w};
#pragma unroll
            for (int i = 0; i < 8; i++) {
                ull ad = dupf(am[i]);
                fma2(acc[i][0], ad, bd0);
                fma2(acc[i][1], ad, bd1);
                fma2(acc[i][2], ad, bd2);
                fma2(acc[i][3], ad, bd3);
            }
        }
        if (kt < 31) {
            int nb = buf ^ 1;
            As[nb][q * 4 + 0][r] = a0.x; As[nb][q * 4 + 1][r] = a0.y;
            As[nb][q * 4 + 2][r] = a0.z; As[nb][q * 4 + 3][r] = a0.w;
            As[nb][q * 4 + 0][r + 64] = a1.x; As[nb][q * 4 + 1][r + 64] = a1.y;
            As[nb][q * 4 + 2][r + 64] = a1.z; As[nb][q * 4 + 3][r + 64] = a1.w;
            Bs[nb][q * 4 + 0][r] = b0.x; Bs[nb][q * 4 + 1][r] = b0.y;
            Bs[nb][q * 4 + 2][r] = b0.z; Bs[nb][q * 4 + 3][r] = b0.w;
            Bs[nb][q * 4 + 0][r + 64] = b1.x; Bs[nb][q * 4 + 1][r + 64] = b1.y;
            Bs[nb][q * 4 + 2][r + 64] = b1.z; Bs[nb][q * 4 + 3][r + 64] = b1.w;
            __syncthreads();
            buf ^= 1;
        }
    }
    float s[8][8];
#pragma unroll
    for (int i = 0; i < 8; i++)
#pragma unroll
        for (int jp = 0; jp < 4; jp++)
            unpk(acc[i][jp], s[i][2 * jp], s[i][2 * jp + 1]);
    const int bb = m0 >> 12;
    const int l0 = (m0 & 4095) + ty * 8;
#pragma unroll
    for (int j = 0; j < 8; j++) {
        int gn = n0 + tx * 8 + j;
        const float* fu = &g_fused[(bb * 256 + gn) * 4096 + l0];
        float4 f0 = *(const float4*)fu;
        float4 f1 = *(const float4*)(fu + 4);
        float4 o0, o1;
        o0.x = s[0][j] + f0.x; o0.y = s[1][j] + f0.y;
        o0.z = s[2][j] + f0.z; o0.w = s[3][j] + f0.w;
        o1.x = s[4][j] + f1.x; o1.y = s[5][j] + f1.y;
        o1.z = s[6][j] + f1.z; o1.w = s[7][j] + f1.w;
        *(float4*)&out[(bb * 256 + gn) * 4096 + l0]     = o0;
        *(float4*)&out[(bb * 256 + gn) * 4096 + l0 + 4] = o1;
    }
}

// =====================================================================
extern "C" void kernel_launch(void* const* d_in, const int* in_sizes, int n_in,
                              void* d_out, int out_size) {
    const float* resnet = (const float*)d_in[0];
    const float* scp    = (const float*)d_in[1];
    const float* scpw   = (const float*)d_in[2];
    const float* sg = (const float*)d_in[3];
    const float* sb = (const float*)d_in[4];
    const float* sm = (const float*)d_in[5];
    const float* sv = (const float*)d_in[6];
    const float* rg = (const float*)d_in[7];
    const float* rb = (const float*)d_in[8];
    const float* rm = (const float*)d_in[9];
    const float* rv = (const float*)d_in[10];
    const float* lg = (const float*)d_in[11];
    const float* lb = (const float*)d_in[12];
    const float* inw = (const float*)d_in[13];
    const float* cw  = (const float*)d_in[14];
    const float* cb  = (const float*)d_in[15];
    const float* xw  = (const float*)d_in[16];
    const float* dtw = (const float*)d_in[17];
    const float* dtb = (const float*)d_in[18];
    const float* alog = (const float*)d_in[19];
    const float* Dp   = (const float*)d_in[20];
    const float* ow   = (const float*)d_in[21];
    float* out = (float*)d_out;

    k_scp    <<<dim3(16, 4, 2), 256>>>(scp, scpw, sg, sb, sm, sv);
    k_fuse   <<<dim3(128, 8, 2), dim3(32, 8)>>>(resnet, rg, rb, rm, rv);
    k_inproj4<<<dim3(64, 8), 256>>>(inw, lg, lb);
    k_conv4  <<<(NB * LL * DI_) / 1024, 256>>>(cw, cb);
    k_xproj  <<<dim3(128, 1), 256>>>(xw);
    k_dtproj <<<dim3(128, 8), 256>>>(dtw, dtb);
    k_scan1  <<<2048, 256>>>(alog);
    k_comb   <<<64, 256>>>();
    k_scan2  <<<2048, 256>>>(alog, Dp);
    k_outproj4<<<dim3(64, 2), 256>>>(ow, out);
}

// round 5
// speedup vs baseline: 1.8558x; 1.2508x over previous
#include <cuda_runtime.h>

// ---------------- problem constants ----------------
#define NB   2
#define CR_  256
#define CS_  512
#define LL   4096     // 64*64
#define PS_  1024     // 32*32
#define DI_  512
#define DS_  16
#define NCH  32       // scan chunks
#define CT_  128      // chunk length (NCH*CT_ == LL)
#define TT_  (NB*DI_*DS_)   // 16384 scan tracks
#define EPSF 1e-5f
#define LOG2E 1.4426950408889634f

typedef unsigned long long ull;

__device__ __forceinline__ unsigned tf32c(float x) {
    unsigned r; asm("cvt.rna.tf32.f32 %0, %1;" : "=r"(r) : "f"(x)); return r;
}
__device__ __forceinline__ void mma8(float* c, const unsigned* a, const unsigned* b) {
    asm volatile("mma.sync.aligned.m16n8k8.row.col.f32.tf32.tf32.f32 "
        "{%0,%1,%2,%3}, {%4,%5,%6,%7}, {%8,%9}, {%0,%1,%2,%3};"
        : "+f"(c[0]), "+f"(c[1]), "+f"(c[2]), "+f"(c[3])
        : "r"(a[0]), "r"(a[1]), "r"(a[2]), "r"(a[3]), "r"(b[0]), "r"(b[1]));
}

// ---------------- scratch (static device allocs only) ----------------
__device__ float  g_sp   [NB*CR_*PS_];
__device__ float  g_fused[NB*CR_*LL];
__device__ float  g_xt   [NB*LL*CR_];
__device__ float2 g_psum [NB*LL*8];       // per (row, c-block) partial {sum, sumsq}
__device__ float  g_xm   [NB*LL*DI_];
__device__ float  g_z    [NB*LL*DI_];
__device__ float  g_u    [NB*LL*DI_];
__device__ float  g_dtin [NB*LL*DS_];
__device__ float2 g_bcc  [NB*LL*DS_];     // {B_s, C_s} interleaved
__device__ float2 g_a    [NB*LL*DI_];     // {dt, dt*u}
__device__ float2 g_uz   [NB*LL*DI_];     // {u, silu(z)}
__device__ float  g_P    [NCH*TT_];       // chunk-major
__device__ float  g_Hc   [NCH*TT_];
__device__ float  g_hini [NCH*TT_];
__device__ float  g_yfin [NB*LL*DI_];

// =====================================================================
// K1: scp 1x1 conv GEMM + BN (fp32 — feeds the residual backbone)
// =====================================================================
__global__ void k_scp(const float* __restrict__ scp, const float* __restrict__ w,
                      const float* __restrict__ gg, const float* __restrict__ bb,
                      const float* __restrict__ mm, const float* __restrict__ vv) {
    __shared__ float As[16][65];
    __shared__ float Bs[16][65];
    const int b  = blockIdx.z;
    const int o0 = blockIdx.y * 64;
    const int p0 = blockIdx.x * 64;
    const int tid = threadIdx.x;
    const int tx = tid & 15, ty = tid >> 4;
    float acc[4][4] = {};
    for (int k0 = 0; k0 < 512; k0 += 16) {
#pragma unroll
        for (int i = 0; i < 4; i++) {
            int idx = tid + i * 256;
            int o = idx >> 4, kk = idx & 15;
            As[kk][o] = w[(o0 + o) * 512 + k0 + kk];
        }
#pragma unroll
        for (int i = 0; i < 4; i++) {
            int idx = tid + i * 256;
            int kk = idx >> 6, p = idx & 63;
            Bs[kk][p] = scp[(b * 512 + k0 + kk) * 1024 + p0 + p];
        }
        __syncthreads();
#pragma unroll
        for (int kk = 0; kk < 16; kk++) {
            float a[4], c[4];
#pragma unroll
            for (int i = 0; i < 4; i++) a[i] = As[kk][ty * 4 + i];
#pragma unroll
            for (int j = 0; j < 4; j++) c[j] = Bs[kk][tx * 4 + j];
#pragma unroll
            for (int i = 0; i < 4; i++)
#pragma unroll
                for (int j = 0; j < 4; j++) acc[i][j] += a[i] * c[j];
        }
        __syncthreads();
    }
#pragma unroll
    for (int i = 0; i < 4; i++) {
        int o = o0 + ty * 4 + i;
        float inv  = gg[o] * rsqrtf(vv[o] + EPSF);
        float beta = bb[o] - mm[o] * inv;
#pragma unroll
        for (int j = 0; j < 4; j++) {
            int p = p0 + tx * 4 + j;
            g_sp[(b * 256 + o) * 1024 + p] = acc[i][j] * inv + beta;
        }
    }
}

// =====================================================================
// K2: fused = BN(resnet) + bilinear(sp); (B,C,HW) + (B,HW,C) + LN psums
// =====================================================================
__global__ void k_fuse(const float* __restrict__ res,
                       const float* __restrict__ rg, const float* __restrict__ rb,
                       const float* __restrict__ rm, const float* __restrict__ rv) {
    __shared__ float tile[32][33];
    const int b  = blockIdx.z;
    const int c0 = blockIdx.y * 32;
    const int l0 = blockIdx.x * 32;
    const int tx = threadIdx.x, ty = threadIdx.y;
    const int l = l0 + tx;
    const int h = l >> 6, wq = l & 63;
    float sh = h * 0.5f - 0.25f;
    float sw = wq * 0.5f - 0.25f;
    int h0 = (int)floorf(sh); float fh = sh - (float)h0;
    int w0 = (int)floorf(sw); float fw = sw - (float)w0;
    int h0c = max(h0, 0), h1c = min(h0 + 1, 31);
    int w0c = max(w0, 0), w1c = min(w0 + 1, 31);
#pragma unroll
    for (int i = 0; i < 4; i++) {
        int c = c0 + ty + i * 8;
        float inv  = rg[c] * rsqrtf(rv[c] + EPSF);
        float beta = rb[c] - rm[c] * inv;
        float val = res[(b * 256 + c) * 4096 + l] * inv + beta;
        const float* spb = g_sp + (b * 256 + c) * 1024;
        float s00 = spb[h0c * 32 + w0c], s01 = spb[h0c * 32 + w1c];
        float s10 = spb[h1c * 32 + w0c], s11 = spb[h1c * 32 + w1c];
        val += (1.f - fh) * ((1.f - fw) * s00 + fw * s01)
             +        fh  * ((1.f - fw) * s10 + fw * s11);
        g_fused[(b * 256 + c) * 4096 + l] = val;
        tile[ty + i * 8][tx] = val;
    }
    __syncthreads();
#pragma unroll
    for (int i = 0; i < 4; i++) {
        int c  = c0 + tx;
        int ll = l0 + ty + i * 8;
        g_xt[(b * 4096 + ll) * 256 + c] = tile[tx][ty + i * 8];
    }
    const int tid = ty * 32 + tx;
    if (tid < 32) {
        float s = 0.f, q = 0.f;
#pragma unroll
        for (int cc = 0; cc < 32; cc++) {
            float v = tile[cc][tid];
            s += v; q += v * v;
        }
        g_psum[(b * 4096 + l0 + tid) * 8 + (c0 >> 5)] = make_float2(s, q);
    }
}

// =====================================================================
// K4: in_proj GEMM — TF32 mma.sync m16n8k8, 128x128 block, 64x32 warp
//     tile, K staged by 32 with register prefetch, fused LN on A.
// =====================================================================
__global__ void __launch_bounds__(256)
k_inproj_tc(const float* __restrict__ w,
            const float* __restrict__ lg, const float* __restrict__ lb) {
    __shared__ __align__(16) unsigned As[128 * 36];
    __shared__ __align__(16) unsigned Bs[128 * 36];
    __shared__ float s_mu[128], s_rs[128];
    const int m0 = blockIdx.x * 128, n0 = blockIdx.y * 128;
    const int tid = threadIdx.x, lane = tid & 31, wid = tid >> 5;
    const int wm = wid >> 2, wn = wid & 3;
    const int g = lane >> 2, t4 = lane & 3;
    if (tid < 128) {
        float s = 0.f, qq = 0.f;
#pragma unroll
        for (int i = 0; i < 8; i++) {
            float2 p = g_psum[(m0 + tid) * 8 + i];
            s += p.x; qq += p.y;
        }
        float mu = s * (1.f / 256.f);
        s_mu[tid] = mu;
        s_rs[tid] = rsqrtf(qq * (1.f / 256.f) - mu * mu + EPSF);
    }
    __syncthreads();
    const int r0 = tid >> 3, c4 = tid & 7;
    float mu[4], rs[4];
#pragma unroll
    for (int i = 0; i < 4; i++) { mu[i] = s_mu[r0 + 32 * i]; rs[i] = s_rs[r0 + 32 * i]; }
    float acc[4][4][4] = {};
    float4 av[4], bv[4], g4, e4;
#pragma unroll
    for (int i = 0; i < 4; i++) {
        av[i] = *(const float4*)&g_xt[(m0 + r0 + 32 * i) * 256 + c4 * 4];
        bv[i] = *(const float4*)&w[(n0 + r0 + 32 * i) * 256 + c4 * 4];
    }
    g4 = *(const float4*)&lg[c4 * 4];
    e4 = *(const float4*)&lb[c4 * 4];
    for (int st = 0; st < 8; st++) {
#pragma unroll
        for (int i = 0; i < 4; i++) {
            int row = r0 + 32 * i;
            unsigned* da = &As[row * 36 + c4 * 4];
            da[0] = tf32c((av[i].x - mu[i]) * rs[i] * g4.x + e4.x);
            da[1] = tf32c((av[i].y - mu[i]) * rs[i] * g4.y + e4.y);
            da[2] = tf32c((av[i].z - mu[i]) * rs[i] * g4.z + e4.z);
            da[3] = tf32c((av[i].w - mu[i]) * rs[i] * g4.w + e4.w);
            unsigned* db = &Bs[row * 36 + c4 * 4];
            db[0] = tf32c(bv[i].x); db[1] = tf32c(bv[i].y);
            db[2] = tf32c(bv[i].z); db[3] = tf32c(bv[i].w);
        }
        __syncthreads();
        if (st < 7) {
            const int k0 = (st + 1) * 32;
#pragma unroll
            for (int i = 0; i < 4; i++) {
                av[i] = *(const float4*)&g_xt[(m0 + r0 + 32 * i) * 256 + k0 + c4 * 4];
                bv[i] = *(const float4*)&w[(n0 + r0 + 32 * i) * 256 + k0 + c4 * 4];
            }
            g4 = *(const float4*)&lg[k0 + c4 * 4];
            e4 = *(const float4*)&lb[k0 + c4 * 4];
        }
#pragma unroll
        for (int k8 = 0; k8 < 4; k8++) {
            const int kb = k8 * 8;
            unsigned af[4][4], bf[4][2];
#pragma unroll
            for (int mf = 0; mf < 4; mf++) {
                int m = wm * 64 + mf * 16 + g;
                af[mf][0] = As[m * 36 + kb + t4];
                af[mf][1] = As[(m + 8) * 36 + kb + t4];
                af[mf][2] = As[m * 36 + kb + t4 + 4];
                af[mf][3] = As[(m + 8) * 36 + kb + t4 + 4];
            }
#pragma unroll
            for (int nf = 0; nf < 4; nf++) {
                int n = wn * 32 + nf * 8 + g;
                bf[nf][0] = Bs[n * 36 + kb + t4];
                bf[nf][1] = Bs[n * 36 + kb + t4 + 4];
            }
#pragma unroll
            for (int mf = 0; mf < 4; mf++)
#pragma unroll
                for (int nf = 0; nf < 4; nf++)
                    mma8(acc[mf][nf], af[mf], bf[nf]);
        }
        __syncthreads();
    }
    float* dst = (n0 < 512) ? g_xm : g_z;
    const int nb = (n0 < 512) ? n0 : (n0 - 512);
#pragma unroll
    for (int mf = 0; mf < 4; mf++) {
        int m = m0 + wm * 64 + mf * 16 + g;
#pragma unroll
        for (int nf = 0; nf < 4; nf++) {
            int n = nb + wn * 32 + nf * 8 + 2 * t4;
            *(float2*)&dst[m * 512 + n]       = make_float2(acc[mf][nf][0], acc[mf][nf][1]);
            *(float2*)&dst[(m + 8) * 512 + n] = make_float2(acc[mf][nf][2], acc[mf][nf][3]);
        }
    }
}

// =====================================================================
// K5: causal depthwise conv (k=3) + SiLU -> u ; {u, silu(z)}; float4
// =====================================================================
__global__ void k_conv4(const float* __restrict__ cw, const float* __restrict__ cb) {
    const int g = blockIdx.x * blockDim.x + threadIdx.x;
    const int base = g * 4;
    const int d = base & 511;
    const int l = (base >> 9) & 4095;
    float4 x2 = *(const float4*)&g_xm[base];
    float4 x1 = make_float4(0.f, 0.f, 0.f, 0.f);
    float4 x0 = make_float4(0.f, 0.f, 0.f, 0.f);
    if (l >= 1) x1 = *(const float4*)&g_xm[base - 512];
    if (l >= 2) x0 = *(const float4*)&g_xm[base - 1024];
    float4 w0 = *(const float4*)&cw[d * 3];
    float4 w1 = *(const float4*)&cw[d * 3 + 4];
    float4 w2 = *(const float4*)&cw[d * 3 + 8];
    float4 cb4 = *(const float4*)&cb[d];
    float f[12] = {w0.x, w0.y, w0.z, w0.w, w1.x, w1.y, w1.z, w1.w, w2.x, w2.y, w2.z, w2.w};
    float a0 = x0.x * f[0] + x1.x * f[1]  + x2.x * f[2]  + cb4.x;
    float a1 = x0.y * f[3] + x1.y * f[4]  + x2.y * f[5]  + cb4.y;
    float a2 = x0.z * f[6] + x1.z * f[7]  + x2.z * f[8]  + cb4.z;
    float a3 = x0.w * f[9] + x1.w * f[10] + x2.w * f[11] + cb4.w;
    float4 u4;
    u4.x = a0 / (1.f + __expf(-a0));
    u4.y = a1 / (1.f + __expf(-a1));
    u4.z = a2 / (1.f + __expf(-a2));
    u4.w = a3 / (1.f + __expf(-a3));
    *(float4*)&g_u[base] = u4;
    float4 z4 = *(const float4*)&g_z[base];
    float4 p0, p1;
    p0.x = u4.x; p0.y = z4.x / (1.f + __expf(-z4.x));
    p0.z = u4.y; p0.w = z4.y / (1.f + __expf(-z4.y));
    p1.x = u4.z; p1.y = z4.z / (1.f + __expf(-z4.z));
    p1.z = u4.w; p1.w = z4.w / (1.f + __expf(-z4.w));
    *(float4*)&g_uz[base]     = p0;
    *(float4*)&g_uz[base + 2] = p1;
}

// =====================================================================
// K6: x_proj GEMM (N=48): writes dt_in dense + {bc,cc} interleaved
// =====================================================================
__global__ void k_xproj(const float* __restrict__ w) {
    __shared__ float As[16][65];
    __shared__ float Bs[16][65];
    const int m0 = blockIdx.x * 64;
    const int tid = threadIdx.x;
    const int tx = tid & 15, ty = tid >> 4;
    float acc[4][4] = {};
    for (int k0 = 0; k0 < 512; k0 += 16) {
#pragma unroll
        for (int i = 0; i < 4; i++) {
            int idx = tid + i * 256;
            int m = idx >> 4, kk = idx & 15;
            As[kk][m] = g_u[(m0 + m) * 512 + k0 + kk];
        }
#pragma unroll
        for (int i = 0; i < 4; i++) {
            int idx = tid + i * 256;
            int n = idx >> 4, kk = idx & 15;
            Bs[kk][n] = (n < 48) ? w[n * 512 + k0 + kk] : 0.f;
        }
        __syncthreads();
#pragma unroll
        for (int kk = 0; kk < 16; kk++) {
            float a[4], c[4];
#pragma unroll
            for (int i = 0; i < 4; i++) a[i] = As[kk][ty * 4 + i];
#pragma unroll
            for (int j = 0; j < 4; j++) c[j] = Bs[kk][tx * 4 + j];
#pragma unroll
            for (int i = 0; i < 4; i++)
#pragma unroll
                for (int j = 0; j < 4; j++) acc[i][j] += a[i] * c[j];
        }
        __syncthreads();
    }
    float* bccf = (float*)g_bcc;
#pragma unroll
    for (int i = 0; i < 4; i++) {
        int gm = m0 + ty * 4 + i;
#pragma unroll
        for (int j = 0; j < 4; j++) {
            int gn = tx * 4 + j;
            float v = acc[i][j];
            if (gn < 16)      g_dtin[gm * 16 + gn] = v;
            else if (gn < 32) bccf[gm * 32 + 2 * (gn - 16)] = v;
            else if (gn < 48) bccf[gm * 32 + 2 * (gn - 32) + 1] = v;
        }
    }
}

// =====================================================================
// K7: dt_proj GEMM (K=16) + softplus; writes {dt, dt*u}
// =====================================================================
__global__ void k_dtproj(const float* __restrict__ w, const float* __restrict__ dtb) {
    __shared__ float As[16][65];
    __shared__ float Bs[16][65];
    const int m0 = blockIdx.x * 64;
    const int n0 = blockIdx.y * 64;
    const int tid = threadIdx.x;
    const int tx = tid & 15, ty = tid >> 4;
    float acc[4][4] = {};
#pragma unroll
    for (int i = 0; i < 4; i++) {
        int idx = tid + i * 256;
        int m = idx >> 4, kk = idx & 15;
        As[kk][m] = g_dtin[(m0 + m) * 16 + kk];
    }
#pragma unroll
    for (int i = 0; i < 4; i++) {
        int idx = tid + i * 256;
        int n = idx >> 4, kk = idx & 15;
        Bs[kk][n] = w[(n0 + n) * 16 + kk];
    }
    __syncthreads();
#pragma unroll
    for (int kk = 0; kk < 16; kk++) {
        float a[4], c[4];
#pragma unroll
        for (int i = 0; i < 4; i++) a[i] = As[kk][ty * 4 + i];
#pragma unroll
        for (int j = 0; j < 4; j++) c[j] = Bs[kk][tx * 4 + j];
#pragma unroll
        for (int i = 0; i < 4; i++)
#pragma unroll
            for (int j = 0; j < 4; j++) acc[i][j] += a[i] * c[j];
    }
#pragma unroll
    for (int i = 0; i < 4; i++) {
        int gm = m0 + ty * 4 + i;
        float4 u4 = *(const float4*)&g_u[gm * 512 + n0 + tx * 4];
        float um[4] = {u4.x, u4.y, u4.z, u4.w};
#pragma unroll
        for (int j = 0; j < 4; j++) {
            int gn = n0 + tx * 4 + j;
            float x = acc[i][j] + dtb[gn];
            float sp = (x > 20.f) ? x : log1pf(__expf(x));
            float2 p; p.x = sp; p.y = sp * um[j];
            g_a[gm * 512 + gn] = p;
        }
    }
}

// =====================================================================
// K8: scan pass 1 — per chunk: P = prod dA, Hc = local final state
// =====================================================================
__global__ void k_scan1(const float* __restrict__ alog) {
    const int w    = (blockIdx.x * blockDim.x + threadIdx.x) >> 5;
    const int lane = threadIdx.x & 31;
    const int chunk = w & (NCH - 1);
    const int dpair = (w >> 5) & 255;
    const int b     = w >> 13;
    const int s = lane & 15;
    const int d = dpair * 2 + (lane >> 4);
    const float An2 = -__expf(alog[d * 16 + s]) * LOG2E;
    float h = 0.f, P = 1.f;
    const int l0 = chunk * CT_;
    const float2* ap = g_a   + (size_t)(b * LL + l0) * 512 + d;
    const float2* bp = g_bcc + (size_t)(b * LL + l0) * 16 + s;
#pragma unroll 4
    for (int t = 0; t < CT_; t++) {
        float2 av = ap[t * 512];
        float2 bc = bp[t * 16];
        float dA  = exp2f(av.x * An2);
        h = fmaf(dA, h, av.y * bc.x);
        P *= dA;
    }
    const int tI = (b * 512 + d) * 16 + s;
    g_P[chunk * TT_ + tI]  = P;
    g_Hc[chunk * TT_ + tI] = h;
}

// =====================================================================
// K9: sequential combine across chunks (chunk-major: coalesced)
// =====================================================================
__global__ void k_comb() {
    const int t = blockIdx.x * blockDim.x + threadIdx.x;
    float h = 0.f;
    for (int c = 0; c < NCH; c++) {
        g_hini[c * TT_ + t] = h;
        h = g_P[c * TT_ + t] * h + g_Hc[c * TT_ + t];
    }
}

// =====================================================================
// K10: scan pass 2 — replay, y = (sum_s h*C + u*D)*silu(z)
// =====================================================================
__global__ void k_scan2(const float* __restrict__ alog, const float* __restrict__ Dp) {
    const int w    = (blockIdx.x * blockDim.x + threadIdx.x) >> 5;
    const int lane = threadIdx.x & 31;
    const int chunk = w & (NCH - 1);
    const int dpair = (w >> 5) & 255;
    const int b     = w >> 13;
    const int s = lane & 15;
    const int d = dpair * 2 + (lane >> 4);
    const float An2 = -__expf(alog[d * 16 + s]) * LOG2E;
    const float Dv = Dp[d];
    const int tI = (b * 512 + d) * 16 + s;
    float h = g_hini[chunk * TT_ + tI];
    const int l0 = chunk * CT_;
    const float2* ap = g_a   + (size_t)(b * LL + l0) * 512 + d;
    const float2* bp = g_bcc + (size_t)(b * LL + l0) * 16 + s;
    const float2* up = g_uz  + (size_t)(b * LL + l0) * 512 + d;
    float* yp        = g_yfin + (size_t)(b * LL + l0) * 512 + d;
#pragma unroll 2
    for (int t = 0; t < CT_; t++) {
        float2 av = ap[t * 512];
        float2 bc = bp[t * 16];
        float dA  = exp2f(av.x * An2);
        h = fmaf(dA, h, av.y * bc.x);
        float part = h * bc.y;
        part += __shfl_xor_sync(0xffffffffu, part, 1);
        part += __shfl_xor_sync(0xffffffffu, part, 2);
        part += __shfl_xor_sync(0xffffffffu, part, 4);
        part += __shfl_xor_sync(0xffffffffu, part, 8);
        if (s == 0) {
            float2 uzv = up[t * 512];
            yp[t * 512] = (part + uzv.x * Dv) * uzv.y;
        }
    }
}

// =====================================================================
// K11: out_proj GEMM — TF32 mma.sync, K=512 staged by 32, residual add,
//      NCHW scatter epilogue.
// =====================================================================
__global__ void __launch_bounds__(256)
k_outproj_tc(const float* __restrict__ w, float* __restrict__ out) {
    __shared__ __align__(16) unsigned As[128 * 36];
    __shared__ __align__(16) unsigned Bs[128 * 36];
    const int m0 = blockIdx.x * 128, n0 = blockIdx.y * 128;
    const int tid = threadIdx.x, lane = tid & 31, wid = tid >> 5;
    const int wm = wid >> 2, wn = wid & 3;
    const int g = lane >> 2, t4 = lane & 3;
    const int r0 = tid >> 3, c4 = tid & 7;
    float acc[4][4][4] = {};
    float4 av[4], bv[4];
#pragma unroll
    for (int i = 0; i < 4; i++) {
        av[i] = *(const float4*)&g_yfin[(m0 + r0 + 32 * i) * 512 + c4 * 4];
        bv[i] = *(const float4*)&w[(n0 + r0 + 32 * i) * 512 + c4 * 4];
    }
    for (int st = 0; st < 16; st++) {
#pragma unroll
        for (int i = 0; i < 4; i++) {
            int row = r0 + 32 * i;
            unsigned* da = &As[row * 36 + c4 * 4];
            da[0] = tf32c(av[i].x); da[1] = tf32c(av[i].y);
            da[2] = tf32c(av[i].z); da[3] = tf32c(av[i].w);
            unsigned* db = &Bs[row * 36 + c4 * 4];
            db[0] = tf32c(bv[i].x); db[1] = tf32c(bv[i].y);
            db[2] = tf32c(bv[i].z); db[3] = tf32c(bv[i].w);
        }
        __syncthreads();
        if (st < 15) {
            const int k0 = (st + 1) * 32;
#pragma unroll
            for (int i = 0; i < 4; i++) {
                av[i] = *(const float4*)&g_yfin[(m0 + r0 + 32 * i) * 512 + k0 + c4 * 4];
                bv[i] = *(const float4*)&w[(n0 + r0 + 32 * i) * 512 + k0 + c4 * 4];
            }
        }
#pragma unroll
        for (int k8 = 0; k8 < 4; k8++) {
            const int kb = k8 * 8;
            unsigned af[4][4], bf[4][2];
#pragma unroll
            for (int mf = 0; mf < 4; mf++) {
                int m = wm * 64 + mf * 16 + g;
                af[mf][0] = As[m * 36 + kb + t4];
                af[mf][1] = As[(m + 8) * 36 + kb + t4];
                af[mf][2] = As[m * 36 + kb + t4 + 4];
                af[mf][3] = As[(m + 8) * 36 + kb + t4 + 4];
            }
#pragma unroll
            for (int nf = 0; nf < 4; nf++) {
                int n = wn * 32 + nf * 8 + g;
                bf[nf][0] = Bs[n * 36 + kb + t4];
                bf[nf][1] = Bs[n * 36 + kb + t4 + 4];
            }
#pragma unroll
            for (int mf = 0; mf < 4; mf++)
#pragma unroll
                for (int nf = 0; nf < 4; nf++)
                    mma8(acc[mf][nf], af[mf], bf[nf]);
        }
        __syncthreads();
    }
    const int bb = m0 >> 12;
#pragma unroll
    for (int mf = 0; mf < 4; mf++) {
        int m = m0 + wm * 64 + mf * 16 + g;
        int l = m & 4095;
#pragma unroll
        for (int nf = 0; nf < 4; nf++) {
            int n = n0 + wn * 32 + nf * 8 + 2 * t4;
            size_t i0 = (size_t)(bb * 256 + n) * 4096 + l;
            size_t i1 = i0 + 4096;          // n+1
            out[i0]     = acc[mf][nf][0] + g_fused[i0];
            out[i1]     = acc[mf][nf][1] + g_fused[i1];
            out[i0 + 8] = acc[mf][nf][2] + g_fused[i0 + 8];   // row m+8
            out[i1 + 8] = acc[mf][nf][3] + g_fused[i1 + 8];
        }
    }
}

// =====================================================================
extern "C" void kernel_launch(void* const* d_in, const int* in_sizes, int n_in,
                              void* d_out, int out_size) {
    const float* resnet = (const float*)d_in[0];
    const float* scp    = (const float*)d_in[1];
    const float* scpw   = (const float*)d_in[2];
    const float* sg = (const float*)d_in[3];
    const float* sb = (const float*)d_in[4];
    const float* sm = (const float*)d_in[5];
    const float* sv = (const float*)d_in[6];
    const float* rg = (const float*)d_in[7];
    const float* rb = (const float*)d_in[8];
    const float* rm = (const float*)d_in[9];
    const float* rv = (const float*)d_in[10];
    const float* lg = (const float*)d_in[11];
    const float* lb = (const float*)d_in[12];
    const float* inw = (const float*)d_in[13];
    const float* cw  = (const float*)d_in[14];
    const float* cb  = (const float*)d_in[15];
    const float* xw  = (const float*)d_in[16];
    const float* dtw = (const float*)d_in[17];
    const float* dtb = (const float*)d_in[18];
    const float* alog = (const float*)d_in[19];
    const float* Dp   = (const float*)d_in[20];
    const float* ow   = (const float*)d_in[21];
    float* out = (float*)d_out;

    k_scp      <<<dim3(16, 4, 2), 256>>>(scp, scpw, sg, sb, sm, sv);
    k_fuse     <<<dim3(128, 8, 2), dim3(32, 8)>>>(resnet, rg, rb, rm, rv);
    k_inproj_tc<<<dim3(64, 8), 256>>>(inw, lg, lb);
    k_conv4    <<<(NB * LL * DI_) / 1024, 256>>>(cw, cb);
    k_xproj    <<<dim3(128, 1), 256>>>(xw);
    k_dtproj   <<<dim3(128, 8), 256>>>(dtw, dtb);
    k_scan1    <<<2048, 256>>>(alog);
    k_comb     <<<64, 256>>>();
    k_scan2    <<<2048, 256>>>(alog, Dp);
    k_outproj_tc<<<dim3(64, 2), 256>>>(ow, out);
}

// round 6
// speedup vs baseline: 2.0984x; 1.1307x over previous
#include <cuda_runtime.h>

// ---------------- problem constants ----------------
#define NB   2
#define CR_  256
#define CS_  512
#define LL   4096     // 64*64
#define PS_  1024     // 32*32
#define DI_  512
#define DS_  16
#define NCH  32       // scan chunks
#define CT_  128      // chunk length (NCH*CT_ == LL)
#define TT_  (NB*DI_*DS_)   // 16384 scan tracks
#define EPSF 1e-5f
#define LOG2E 1.4426950408889634f

__device__ __forceinline__ unsigned tf32c(float x) {
    unsigned r; asm("cvt.rna.tf32.f32 %0, %1;" : "=r"(r) : "f"(x)); return r;
}
__device__ __forceinline__ void mma8(float* c, const unsigned* a, const unsigned* b) {
    asm volatile("mma.sync.aligned.m16n8k8.row.col.f32.tf32.tf32.f32 "
        "{%0,%1,%2,%3}, {%4,%5,%6,%7}, {%8,%9}, {%0,%1,%2,%3};"
        : "+f"(c[0]), "+f"(c[1]), "+f"(c[2]), "+f"(c[3])
        : "r"(a[0]), "r"(a[1]), "r"(a[2]), "r"(a[3]), "r"(b[0]), "r"(b[1]));
}

// ---------------- scratch (static device allocs only) ----------------
__device__ float  g_sp   [NB*CR_*PS_];
__device__ float  g_fused[NB*CR_*LL];
__device__ float  g_xt   [NB*LL*CR_];
__device__ float2 g_psum [NB*LL*8];
__device__ float  g_xm   [NB*LL*DI_];
__device__ float  g_z    [NB*LL*DI_];
__device__ float  g_u    [NB*LL*DI_];
__device__ float  g_dtin [NB*LL*DS_];
__device__ float2 g_bcc  [NB*LL*DS_];
__device__ float2 g_a    [NB*LL*DI_];
__device__ float2 g_uz   [NB*LL*DI_];
__device__ float  g_P    [NCH*TT_];       // chunk-major
__device__ float  g_Hc   [NCH*TT_];
__device__ float  g_yfin [NB*LL*DI_];

// =====================================================================
// K1: scp 1x1 conv GEMM + BN — TF32 TC, B transpose-staged (stride 33)
// =====================================================================
__global__ void __launch_bounds__(256)
k_scp_tc(const float* __restrict__ scp, const float* __restrict__ w,
         const float* __restrict__ gg, const float* __restrict__ bb,
         const float* __restrict__ mm, const float* __restrict__ vv) {
    __shared__ __align__(16) unsigned As[128 * 36];   // W  [o][k]
    __shared__ __align__(16) unsigned Bs[128 * 33];   // scp^T [p][k]
    const int b  = blockIdx.z;
    const int m0 = blockIdx.x * 128;   // o
    const int n0 = blockIdx.y * 128;   // p
    const int tid = threadIdx.x, lane = tid & 31, wid = tid >> 5;
    const int wm = wid >> 2, wn = wid & 3;
    const int g = lane >> 2, t4 = lane & 3;
    const int r0 = tid >> 3, c4 = tid & 7;
    const int kq = tid >> 6, pq2 = (tid & 63) * 2;
    float acc[4][4][4] = {};
    float4 av[4]; float2 bvv[8];
#pragma unroll
    for (int i = 0; i < 4; i++)
        av[i] = *(const float4*)&w[(m0 + r0 + 32 * i) * 512 + c4 * 4];
#pragma unroll
    for (int j = 0; j < 8; j++)
        bvv[j] = *(const float2*)&scp[(b * 512 + j * 4 + kq) * 1024 + n0 + pq2];
    for (int st = 0; st < 16; st++) {
#pragma unroll
        for (int i = 0; i < 4; i++) {
            unsigned* da = &As[(r0 + 32 * i) * 36 + c4 * 4];
            da[0] = tf32c(av[i].x); da[1] = tf32c(av[i].y);
            da[2] = tf32c(av[i].z); da[3] = tf32c(av[i].w);
        }
#pragma unroll
        for (int j = 0; j < 8; j++) {
            Bs[pq2 * 33 + j * 4 + kq]       = tf32c(bvv[j].x);
            Bs[(pq2 + 1) * 33 + j * 4 + kq] = tf32c(bvv[j].y);
        }
        __syncthreads();
        if (st < 15) {
            const int k0 = (st + 1) * 32;
#pragma unroll
            for (int i = 0; i < 4; i++)
                av[i] = *(const float4*)&w[(m0 + r0 + 32 * i) * 512 + k0 + c4 * 4];
#pragma unroll
            for (int j = 0; j < 8; j++)
                bvv[j] = *(const float2*)&scp[(b * 512 + k0 + j * 4 + kq) * 1024 + n0 + pq2];
        }
#pragma unroll
        for (int k8 = 0; k8 < 4; k8++) {
            const int kb = k8 * 8;
            unsigned af[4][4], bf[4][2];
#pragma unroll
            for (int mf = 0; mf < 4; mf++) {
                int m = wm * 64 + mf * 16 + g;
                af[mf][0] = As[m * 36 + kb + t4];
                af[mf][1] = As[(m + 8) * 36 + kb + t4];
                af[mf][2] = As[m * 36 + kb + t4 + 4];
                af[mf][3] = As[(m + 8) * 36 + kb + t4 + 4];
            }
#pragma unroll
            for (int nf = 0; nf < 4; nf++) {
                int n = wn * 32 + nf * 8 + g;
                bf[nf][0] = Bs[n * 33 + kb + t4];
                bf[nf][1] = Bs[n * 33 + kb + t4 + 4];
            }
#pragma unroll
            for (int mf = 0; mf < 4; mf++)
#pragma unroll
                for (int nf = 0; nf < 4; nf++)
                    mma8(acc[mf][nf], af[mf], bf[nf]);
        }
        __syncthreads();
    }
#pragma unroll
    for (int mf = 0; mf < 4; mf++) {
        int o = m0 + wm * 64 + mf * 16 + g;
        float iv0 = gg[o] * rsqrtf(vv[o] + EPSF);
        float be0 = bb[o] - mm[o] * iv0;
        float iv1 = gg[o + 8] * rsqrtf(vv[o + 8] + EPSF);
        float be1 = bb[o + 8] - mm[o + 8] * iv1;
#pragma unroll
        for (int nf = 0; nf < 4; nf++) {
            int p = n0 + wn * 32 + nf * 8 + 2 * t4;
            float* dp  = &g_sp[(b * 256 + o) * 1024 + p];
            float* dp8 = &g_sp[(b * 256 + o + 8) * 1024 + p];
            dp[0]  = acc[mf][nf][0] * iv0 + be0;
            dp[1]  = acc[mf][nf][1] * iv0 + be0;
            dp8[0] = acc[mf][nf][2] * iv1 + be1;
            dp8[1] = acc[mf][nf][3] * iv1 + be1;
        }
    }
}

// =====================================================================
// K2: fused = BN(resnet) + bilinear(sp); (B,C,HW) + (B,HW,C) + LN psums
// =====================================================================
__global__ void k_fuse(const float* __restrict__ res,
                       const float* __restrict__ rg, const float* __restrict__ rb,
                       const float* __restrict__ rm, const float* __restrict__ rv) {
    __shared__ float tile[32][33];
    const int b  = blockIdx.z;
    const int c0 = blockIdx.y * 32;
    const int l0 = blockIdx.x * 32;
    const int tx = threadIdx.x, ty = threadIdx.y;
    const int l = l0 + tx;
    const int h = l >> 6, wq = l & 63;
    float sh = h * 0.5f - 0.25f;
    float sw = wq * 0.5f - 0.25f;
    int h0 = (int)floorf(sh); float fh = sh - (float)h0;
    int w0 = (int)floorf(sw); float fw = sw - (float)w0;
    int h0c = max(h0, 0), h1c = min(h0 + 1, 31);
    int w0c = max(w0, 0), w1c = min(w0 + 1, 31);
#pragma unroll
    for (int i = 0; i < 4; i++) {
        int c = c0 + ty + i * 8;
        float inv  = rg[c] * rsqrtf(rv[c] + EPSF);
        float beta = rb[c] - rm[c] * inv;
        float val = res[(b * 256 + c) * 4096 + l] * inv + beta;
        const float* spb = g_sp + (b * 256 + c) * 1024;
        float s00 = spb[h0c * 32 + w0c], s01 = spb[h0c * 32 + w1c];
        float s10 = spb[h1c * 32 + w0c], s11 = spb[h1c * 32 + w1c];
        val += (1.f - fh) * ((1.f - fw) * s00 + fw * s01)
             +        fh  * ((1.f - fw) * s10 + fw * s11);
        g_fused[(b * 256 + c) * 4096 + l] = val;
        tile[ty + i * 8][tx] = val;
    }
    __syncthreads();
#pragma unroll
    for (int i = 0; i < 4; i++) {
        int c  = c0 + tx;
        int ll = l0 + ty + i * 8;
        g_xt[(b * 4096 + ll) * 256 + c] = tile[tx][ty + i * 8];
    }
    const int tid = ty * 32 + tx;
    if (tid < 32) {
        float s = 0.f, q = 0.f;
#pragma unroll
        for (int cc = 0; cc < 32; cc++) {
            float v = tile[cc][tid];
            s += v; q += v * v;
        }
        g_psum[(b * 4096 + l0 + tid) * 8 + (c0 >> 5)] = make_float2(s, q);
    }
}

// =====================================================================
// K4: in_proj GEMM — TF32 TC, double-buffered smem, fused LN on A
// =====================================================================
__global__ void __launch_bounds__(256)
k_inproj_tc(const float* __restrict__ w,
            const float* __restrict__ lg, const float* __restrict__ lb) {
    extern __shared__ unsigned dyn[];
    unsigned* As = dyn;             // [2][128*36]
    unsigned* Bs = dyn + 2 * 4608;  // [2][128*36]
    __shared__ float s_mu[128], s_rs[128];
    const int m0 = blockIdx.x * 128, n0 = blockIdx.y * 128;
    const int tid = threadIdx.x, lane = tid & 31, wid = tid >> 5;
    const int wm = wid >> 2, wn = wid & 3;
    const int g = lane >> 2, t4 = lane & 3;
    if (tid < 128) {
        float s = 0.f, qq = 0.f;
#pragma unroll
        for (int i = 0; i < 8; i++) {
            float2 p = g_psum[(m0 + tid) * 8 + i];
            s += p.x; qq += p.y;
        }
        float mu = s * (1.f / 256.f);
        s_mu[tid] = mu;
        s_rs[tid] = rsqrtf(qq * (1.f / 256.f) - mu * mu + EPSF);
    }
    __syncthreads();
    const int r0 = tid >> 3, c4 = tid & 7;
    float mu[4], rs[4];
#pragma unroll
    for (int i = 0; i < 4; i++) { mu[i] = s_mu[r0 + 32 * i]; rs[i] = s_rs[r0 + 32 * i]; }
    float acc[4][4][4] = {};
    float4 av[4], bv[4], g4, e4;
#pragma unroll
    for (int i = 0; i < 4; i++) {
        av[i] = *(const float4*)&g_xt[(m0 + r0 + 32 * i) * 256 + c4 * 4];
        bv[i] = *(const float4*)&w[(n0 + r0 + 32 * i) * 256 + c4 * 4];
    }
    g4 = *(const float4*)&lg[c4 * 4];
    e4 = *(const float4*)&lb[c4 * 4];
    // store stage 0 into buffer 0
#pragma unroll
    for (int i = 0; i < 4; i++) {
        int row = r0 + 32 * i;
        unsigned* da = &As[row * 36 + c4 * 4];
        da[0] = tf32c((av[i].x - mu[i]) * rs[i] * g4.x + e4.x);
        da[1] = tf32c((av[i].y - mu[i]) * rs[i] * g4.y + e4.y);
        da[2] = tf32c((av[i].z - mu[i]) * rs[i] * g4.z + e4.z);
        da[3] = tf32c((av[i].w - mu[i]) * rs[i] * g4.w + e4.w);
        unsigned* db = &Bs[row * 36 + c4 * 4];
        db[0] = tf32c(bv[i].x); db[1] = tf32c(bv[i].y);
        db[2] = tf32c(bv[i].z); db[3] = tf32c(bv[i].w);
    }
    __syncthreads();
    for (int st = 0; st < 8; st++) {
        const unsigned* Ab = As + (st & 1) * 4608;
        const unsigned* Bb = Bs + (st & 1) * 4608;
        if (st < 7) {
            const int k0 = (st + 1) * 32;
#pragma unroll
            for (int i = 0; i < 4; i++) {
                av[i] = *(const float4*)&g_xt[(m0 + r0 + 32 * i) * 256 + k0 + c4 * 4];
                bv[i] = *(const float4*)&w[(n0 + r0 + 32 * i) * 256 + k0 + c4 * 4];
            }
            g4 = *(const float4*)&lg[k0 + c4 * 4];
            e4 = *(const float4*)&lb[k0 + c4 * 4];
        }
#pragma unroll
        for (int k8 = 0; k8 < 4; k8++) {
            const int kb = k8 * 8;
            unsigned af[4][4], bf[4][2];
#pragma unroll
            for (int mf = 0; mf < 4; mf++) {
                int m = wm * 64 + mf * 16 + g;
                af[mf][0] = Ab[m * 36 + kb + t4];
                af[mf][1] = Ab[(m + 8) * 36 + kb + t4];
                af[mf][2] = Ab[m * 36 + kb + t4 + 4];
                af[mf][3] = Ab[(m + 8) * 36 + kb + t4 + 4];
            }
#pragma unroll
            for (int nf = 0; nf < 4; nf++) {
                int n = wn * 32 + nf * 8 + g;
                bf[nf][0] = Bb[n * 36 + kb + t4];
                bf[nf][1] = Bb[n * 36 + kb + t4 + 4];
            }
#pragma unroll
            for (int mf = 0; mf < 4; mf++)
#pragma unroll
                for (int nf = 0; nf < 4; nf++)
                    mma8(acc[mf][nf], af[mf], bf[nf]);
        }
        if (st < 7) {
            unsigned* Aw = As + ((st + 1) & 1) * 4608;
            unsigned* Bw = Bs + ((st + 1) & 1) * 4608;
#pragma unroll
            for (int i = 0; i < 4; i++) {
                int row = r0 + 32 * i;
                unsigned* da = &Aw[row * 36 + c4 * 4];
                da[0] = tf32c((av[i].x - mu[i]) * rs[i] * g4.x + e4.x);
                da[1] = tf32c((av[i].y - mu[i]) * rs[i] * g4.y + e4.y);
                da[2] = tf32c((av[i].z - mu[i]) * rs[i] * g4.z + e4.z);
                da[3] = tf32c((av[i].w - mu[i]) * rs[i] * g4.w + e4.w);
                unsigned* db = &Bw[row * 36 + c4 * 4];
                db[0] = tf32c(bv[i].x); db[1] = tf32c(bv[i].y);
                db[2] = tf32c(bv[i].z); db[3] = tf32c(bv[i].w);
            }
            __syncthreads();
        }
    }
    float* dst = (n0 < 512) ? g_xm : g_z;
    const int nb = (n0 < 512) ? n0 : (n0 - 512);
#pragma unroll
    for (int mf = 0; mf < 4; mf++) {
        int m = m0 + wm * 64 + mf * 16 + g;
#pragma unroll
        for (int nf = 0; nf < 4; nf++) {
            int n = nb + wn * 32 + nf * 8 + 2 * t4;
            *(float2*)&dst[m * 512 + n]       = make_float2(acc[mf][nf][0], acc[mf][nf][1]);
            *(float2*)&dst[(m + 8) * 512 + n] = make_float2(acc[mf][nf][2], acc[mf][nf][3]);
        }
    }
}

// =====================================================================
// K5: causal depthwise conv (k=3) + SiLU -> u ; {u, silu(z)}; float4
// =====================================================================
__global__ void k_conv4(const float* __restrict__ cw, const float* __restrict__ cb) {
    const int g = blockIdx.x * blockDim.x + threadIdx.x;
    const int base = g * 4;
    const int d = base & 511;
    const int l = (base >> 9) & 4095;
    float4 x2 = *(const float4*)&g_xm[base];
    float4 x1 = make_float4(0.f, 0.f, 0.f, 0.f);
    float4 x0 = make_float4(0.f, 0.f, 0.f, 0.f);
    if (l >= 1) x1 = *(const float4*)&g_xm[base - 512];
    if (l >= 2) x0 = *(const float4*)&g_xm[base - 1024];
    float4 w0 = *(const float4*)&cw[d * 3];
    float4 w1 = *(const float4*)&cw[d * 3 + 4];
    float4 w2 = *(const float4*)&cw[d * 3 + 8];
    float4 cb4 = *(const float4*)&cb[d];
    float f[12] = {w0.x, w0.y, w0.z, w0.w, w1.x, w1.y, w1.z, w1.w, w2.x, w2.y, w2.z, w2.w};
    float a0 = x0.x * f[0] + x1.x * f[1]  + x2.x * f[2]  + cb4.x;
    float a1 = x0.y * f[3] + x1.y * f[4]  + x2.y * f[5]  + cb4.y;
    float a2 = x0.z * f[6] + x1.z * f[7]  + x2.z * f[8]  + cb4.z;
    float a3 = x0.w * f[9] + x1.w * f[10] + x2.w * f[11] + cb4.w;
    float4 u4;
    u4.x = a0 / (1.f + __expf(-a0));
    u4.y = a1 / (1.f + __expf(-a1));
    u4.z = a2 / (1.f + __expf(-a2));
    u4.w = a3 / (1.f + __expf(-a3));
    *(float4*)&g_u[base] = u4;
    float4 z4 = *(const float4*)&g_z[base];
    float4 p0, p1;
    p0.x = u4.x; p0.y = z4.x / (1.f + __expf(-z4.x));
    p0.z = u4.y; p0.w = z4.y / (1.f + __expf(-z4.y));
    p1.x = u4.z; p1.y = z4.z / (1.f + __expf(-z4.z));
    p1.z = u4.w; p1.w = z4.w / (1.f + __expf(-z4.w));
    *(float4*)&g_uz[base]     = p0;
    *(float4*)&g_uz[base + 2] = p1;
}

// =====================================================================
// K6: x_proj GEMM — TF32 TC 128x64 (48 live cols), writes dtin + bcc
// =====================================================================
__global__ void __launch_bounds__(256)
k_xproj_tc(const float* __restrict__ w) {
    __shared__ __align__(16) unsigned As[128 * 36];
    __shared__ __align__(16) unsigned Bs[64 * 36];
    const int m0 = blockIdx.x * 128;
    const int tid = threadIdx.x, lane = tid & 31, wid = tid >> 5;
    const int wm = wid >> 1, wn = wid & 1;
    const int g = lane >> 2, t4 = lane & 3;
    const int r0 = tid >> 3, c4 = tid & 7;
    float acc[2][4][4] = {};
    float4 av[4], bv[2];
#pragma unroll
    for (int i = 0; i < 4; i++)
        av[i] = *(const float4*)&g_u[(m0 + r0 + 32 * i) * 512 + c4 * 4];
#pragma unroll
    for (int i = 0; i < 2; i++) {
        int n = r0 + 32 * i;
        bv[i] = (n < 48) ? *(const float4*)&w[n * 512 + c4 * 4]
                         : make_float4(0.f, 0.f, 0.f, 0.f);
    }
    for (int st = 0; st < 16; st++) {
#pragma unroll
        for (int i = 0; i < 4; i++) {
            unsigned* da = &As[(r0 + 32 * i) * 36 + c4 * 4];
            da[0] = tf32c(av[i].x); da[1] = tf32c(av[i].y);
            da[2] = tf32c(av[i].z); da[3] = tf32c(av[i].w);
        }
#pragma unroll
        for (int i = 0; i < 2; i++) {
            unsigned* db = &Bs[(r0 + 32 * i) * 36 + c4 * 4];
            db[0] = tf32c(bv[i].x); db[1] = tf32c(bv[i].y);
            db[2] = tf32c(bv[i].z); db[3] = tf32c(bv[i].w);
        }
        __syncthreads();
        if (st < 15) {
            const int k0 = (st + 1) * 32;
#pragma unroll
            for (int i = 0; i < 4; i++)
                av[i] = *(const float4*)&g_u[(m0 + r0 + 32 * i) * 512 + k0 + c4 * 4];
#pragma unroll
            for (int i = 0; i < 2; i++) {
                int n = r0 + 32 * i;
                bv[i] = (n < 48) ? *(const float4*)&w[n * 512 + k0 + c4 * 4]
                                 : make_float4(0.f, 0.f, 0.f, 0.f);
            }
        }
#pragma unroll
        for (int k8 = 0; k8 < 4; k8++) {
            const int kb = k8 * 8;
            unsigned af[2][4], bf[4][2];
#pragma unroll
            for (int mf = 0; mf < 2; mf++) {
                int m = wm * 32 + mf * 16 + g;
                af[mf][0] = As[m * 36 + kb + t4];
                af[mf][1] = As[(m + 8) * 36 + kb + t4];
                af[mf][2] = As[m * 36 + kb + t4 + 4];
                af[mf][3] = As[(m + 8) * 36 + kb + t4 + 4];
            }
#pragma unroll
            for (int nf = 0; nf < 4; nf++) {
                int n = wn * 32 + nf * 8 + g;
                bf[nf][0] = Bs[n * 36 + kb + t4];
                bf[nf][1] = Bs[n * 36 + kb + t4 + 4];
            }
#pragma unroll
            for (int mf = 0; mf < 2; mf++)
#pragma unroll
                for (int nf = 0; nf < 4; nf++)
                    mma8(acc[mf][nf], af[mf], bf[nf]);
        }
        __syncthreads();
    }
    float* bccf = (float*)g_bcc;
#pragma unroll
    for (int mf = 0; mf < 2; mf++) {
#pragma unroll
        for (int nf = 0; nf < 4; nf++) {
#pragma unroll
            for (int half = 0; half < 2; half++) {
                int gm = m0 + wm * 32 + mf * 16 + g + half * 8;
#pragma unroll
                for (int jj = 0; jj < 2; jj++) {
                    int gn = wn * 32 + nf * 8 + 2 * t4 + jj;
                    float v = acc[mf][nf][half * 2 + jj];
                    if (gn < 16)      g_dtin[gm * 16 + gn] = v;
                    else if (gn < 32) bccf[gm * 32 + 2 * (gn - 16)] = v;
                    else if (gn < 48) bccf[gm * 32 + 2 * (gn - 32) + 1] = v;
                }
            }
        }
    }
}

// =====================================================================
// K7: dt_proj GEMM (K=16) + softplus; writes {dt, dt*u}
// =====================================================================
__global__ void k_dtproj(const float* __restrict__ w, const float* __restrict__ dtb) {
    __shared__ float As[16][65];
    __shared__ float Bs[16][65];
    const int m0 = blockIdx.x * 64;
    const int n0 = blockIdx.y * 64;
    const int tid = threadIdx.x;
    const int tx = tid & 15, ty = tid >> 4;
    float acc[4][4] = {};
#pragma unroll
    for (int i = 0; i < 4; i++) {
        int idx = tid + i * 256;
        int m = idx >> 4, kk = idx & 15;
        As[kk][m] = g_dtin[(m0 + m) * 16 + kk];
    }
#pragma unroll
    for (int i = 0; i < 4; i++) {
        int idx = tid + i * 256;
        int n = idx >> 4, kk = idx & 15;
        Bs[kk][n] = w[(n0 + n) * 16 + kk];
    }
    __syncthreads();
#pragma unroll
    for (int kk = 0; kk < 16; kk++) {
        float a[4], c[4];
#pragma unroll
        for (int i = 0; i < 4; i++) a[i] = As[kk][ty * 4 + i];
#pragma unroll
        for (int j = 0; j < 4; j++) c[j] = Bs[kk][tx * 4 + j];
#pragma unroll
        for (int i = 0; i < 4; i++)
#pragma unroll
            for (int j = 0; j < 4; j++) acc[i][j] += a[i] * c[j];
    }
#pragma unroll
    for (int i = 0; i < 4; i++) {
        int gm = m0 + ty * 4 + i;
        float4 u4 = *(const float4*)&g_u[gm * 512 + n0 + tx * 4];
        float um[4] = {u4.x, u4.y, u4.z, u4.w};
#pragma unroll
        for (int j = 0; j < 4; j++) {
            int gn = n0 + tx * 4 + j;
            float x = acc[i][j] + dtb[gn];
            float sp = (x > 20.f) ? x : log1pf(__expf(x));
            float2 p; p.x = sp; p.y = sp * um[j];
            g_a[gm * 512 + gn] = p;
        }
    }
}

// =====================================================================
// K8: scan pass 1 — per chunk: P = prod dA, Hc = local final state
// =====================================================================
__global__ void k_scan1(const float* __restrict__ alog) {
    const int w    = (blockIdx.x * blockDim.x + threadIdx.x) >> 5;
    const int lane = threadIdx.x & 31;
    const int chunk = w & (NCH - 1);
    const int dpair = (w >> 5) & 255;
    const int b     = w >> 13;
    const int s = lane & 15;
    const int d = dpair * 2 + (lane >> 4);
    const float An2 = -__expf(alog[d * 16 + s]) * LOG2E;
    float h = 0.f, P = 1.f;
    const int l0 = chunk * CT_;
    const float2* ap = g_a   + (size_t)(b * LL + l0) * 512 + d;
    const float2* bp = g_bcc + (size_t)(b * LL + l0) * 16 + s;
#pragma unroll 4
    for (int t = 0; t < CT_; t++) {
        float2 av = ap[t * 512];
        float2 bc = bp[t * 16];
        float dA  = exp2f(av.x * An2);
        h = fmaf(dA, h, av.y * bc.x);
        P *= dA;
    }
    const int tI = (b * 512 + d) * 16 + s;
    g_P[chunk * TT_ + tI]  = P;
    g_Hc[chunk * TT_ + tI] = h;
}

// =====================================================================
// K10: scan pass 2 — inline chunk combine + replay + y
// =====================================================================
__global__ void k_scan2(const float* __restrict__ alog, const float* __restrict__ Dp) {
    const int w    = (blockIdx.x * blockDim.x + threadIdx.x) >> 5;
    const int lane = threadIdx.x & 31;
    const int chunk = w & (NCH - 1);
    const int dpair = (w >> 5) & 255;
    const int b     = w >> 13;
    const int s = lane & 15;
    const int d = dpair * 2 + (lane >> 4);
    const float An2 = -__expf(alog[d * 16 + s]) * LOG2E;
    const float Dv = Dp[d];
    const int tI = (b * 512 + d) * 16 + s;
    // inline prefix combine over chunks < chunk (predicated, unrolled)
    float h = 0.f;
#pragma unroll
    for (int c = 0; c < NCH; c++) {
        if (c < chunk) h = g_P[c * TT_ + tI] * h + g_Hc[c * TT_ + tI];
    }
    const int l0 = chunk * CT_;
    const float2* ap = g_a   + (size_t)(b * LL + l0) * 512 + d;
    const float2* bp = g_bcc + (size_t)(b * LL + l0) * 16 + s;
    const float2* up = g_uz  + (size_t)(b * LL + l0) * 512 + d;
    float* yp        = g_yfin + (size_t)(b * LL + l0) * 512 + d;
#pragma unroll 2
    for (int t = 0; t < CT_; t++) {
        float2 av = ap[t * 512];
        float2 bc = bp[t * 16];
        float dA  = exp2f(av.x * An2);
        h = fmaf(dA, h, av.y * bc.x);
        float part = h * bc.y;
        part += __shfl_xor_sync(0xffffffffu, part, 1);
        part += __shfl_xor_sync(0xffffffffu, part, 2);
        part += __shfl_xor_sync(0xffffffffu, part, 4);
        part += __shfl_xor_sync(0xffffffffu, part, 8);
        if (s == 0) {
            float2 uzv = up[t * 512];
            yp[t * 512] = (part + uzv.x * Dv) * uzv.y;
        }
    }
}

// =====================================================================
// K11: out_proj GEMM — TF32 TC, double-buffered, residual + NCHW scatter
// =====================================================================
__global__ void __launch_bounds__(256)
k_outproj_tc(const float* __restrict__ w, float* __restrict__ out) {
    extern __shared__ unsigned dyn[];
    unsigned* As = dyn;
    unsigned* Bs = dyn + 2 * 4608;
    const int m0 = blockIdx.x * 128, n0 = blockIdx.y * 128;
    const int tid = threadIdx.x, lane = tid & 31, wid = tid >> 5;
    const int wm = wid >> 2, wn = wid & 3;
    const int g = lane >> 2, t4 = lane & 3;
    const int r0 = tid >> 3, c4 = tid & 7;
    float acc[4][4][4] = {};
    float4 av[4], bv[4];
#pragma unroll
    for (int i = 0; i < 4; i++) {
        av[i] = *(const float4*)&g_yfin[(m0 + r0 + 32 * i) * 512 + c4 * 4];
        bv[i] = *(const float4*)&w[(n0 + r0 + 32 * i) * 512 + c4 * 4];
    }
#pragma unroll
    for (int i = 0; i < 4; i++) {
        int row = r0 + 32 * i;
        unsigned* da = &As[row * 36 + c4 * 4];
        da[0] = tf32c(av[i].x); da[1] = tf32c(av[i].y);
        da[2] = tf32c(av[i].z); da[3] = tf32c(av[i].w);
        unsigned* db = &Bs[row * 36 + c4 * 4];
        db[0] = tf32c(bv[i].x); db[1] = tf32c(bv[i].y);
        db[2] = tf32c(bv[i].z); db[3] = tf32c(bv[i].w);
    }
    __syncthreads();
    for (int st = 0; st < 16; st++) {
        const unsigned* Ab = As + (st & 1) * 4608;
        const unsigned* Bb = Bs + (st & 1) * 4608;
        if (st < 15) {
            const int k0 = (st + 1) * 32;
#pragma unroll
            for (int i = 0; i < 4; i++) {
                av[i] = *(const float4*)&g_yfin[(m0 + r0 + 32 * i) * 512 + k0 + c4 * 4];
                bv[i] = *(const float4*)&w[(n0 + r0 + 32 * i) * 512 + k0 + c4 * 4];
            }
        }
#pragma unroll
        for (int k8 = 0; k8 < 4; k8++) {
            const int kb = k8 * 8;
            unsigned af[4][4], bf[4][2];
#pragma unroll
            for (int mf = 0; mf < 4; mf++) {
                int m = wm * 64 + mf * 16 + g;
                af[mf][0] = Ab[m * 36 + kb + t4];
                af[mf][1] = Ab[(m + 8) * 36 + kb + t4];
                af[mf][2] = Ab[m * 36 + kb + t4 + 4];
                af[mf][3] = Ab[(m + 8) * 36 + kb + t4 + 4];
            }
#pragma unroll
            for (int nf = 0; nf < 4; nf++) {
                int n = wn * 32 + nf * 8 + g;
                bf[nf][0] = Bb[n * 36 + kb + t4];
                bf[nf][1] = Bb[n * 36 + kb + t4 + 4];
            }
#pragma unroll
            for (int mf = 0; mf < 4; mf++)
#pragma unroll
                for (int nf = 0; nf < 4; nf++)
                    mma8(acc[mf][nf], af[mf], bf[nf]);
        }
        if (st < 15) {
            unsigned* Aw = As + ((st + 1) & 1) * 4608;
            unsigned* Bw = Bs + ((st + 1) & 1) * 4608;
#pragma unroll
            for (int i = 0; i < 4; i++) {
                int row = r0 + 32 * i;
                unsigned* da = &Aw[row * 36 + c4 * 4];
                da[0] = tf32c(av[i].x); da[1] = tf32c(av[i].y);
                da[2] = tf32c(av[i].z); da[3] = tf32c(av[i].w);
                unsigned* db = &Bw[row * 36 + c4 * 4];
                db[0] = tf32c(bv[i].x); db[1] = tf32c(bv[i].y);
                db[2] = tf32c(bv[i].z); db[3] = tf32c(bv[i].w);
            }
            __syncthreads();
        }
    }
    const int bb = m0 >> 12;
#pragma unroll
    for (int mf = 0; mf < 4; mf++) {
        int m = m0 + wm * 64 + mf * 16 + g;
        int l = m & 4095;
#pragma unroll
        for (int nf = 0; nf < 4; nf++) {
            int n = n0 + wn * 32 + nf * 8 + 2 * t4;
            size_t i0 = (size_t)(bb * 256 + n) * 4096 + l;
            size_t i1 = i0 + 4096;
            out[i0]     = acc[mf][nf][0] + g_fused[i0];
            out[i1]     = acc[mf][nf][1] + g_fused[i1];
            out[i0 + 8] = acc[mf][nf][2] + g_fused[i0 + 8];
            out[i1 + 8] = acc[mf][nf][3] + g_fused[i1 + 8];
        }
    }
}

// =====================================================================
extern "C" void kernel_launch(void* const* d_in, const int* in_sizes, int n_in,
                              void* d_out, int out_size) {
    const float* resnet = (const float*)d_in[0];
    const float* scp    = (const float*)d_in[1];
    const float* scpw   = (const float*)d_in[2];
    const float* sg = (const float*)d_in[3];
    const float* sb = (const float*)d_in[4];
    const float* sm = (const float*)d_in[5];
    const float* sv = (const float*)d_in[6];
    const float* rg = (const float*)d_in[7];
    const float* rb = (const float*)d_in[8];
    const float* rm = (const float*)d_in[9];
    const float* rv = (const float*)d_in[10];
    const float* lg = (const float*)d_in[11];
    const float* lb = (const float*)d_in[12];
    const float* inw = (const float*)d_in[13];
    const float* cw  = (const float*)d_in[14];
    const float* cb  = (const float*)d_in[15];
    const float* xw  = (const float*)d_in[16];
    const float* dtw = (const float*)d_in[17];
    const float* dtb = (const float*)d_in[18];
    const float* alog = (const float*)d_in[19];
    const float* Dp   = (const float*)d_in[20];
    const float* ow   = (const float*)d_in[21];
    float* out = (float*)d_out;

    const int DYN = 4 * 4608 * 4;  // 73728 bytes (double-buffered As+Bs)
    cudaFuncSetAttribute(k_inproj_tc, cudaFuncAttributeMaxDynamicSharedMemorySize, DYN);
    cudaFuncSetAttribute(k_outproj_tc, cudaFuncAttributeMaxDynamicSharedMemorySize, DYN);

    k_scp_tc   <<<dim3(2, 8, 2), 256>>>(scp, scpw, sg, sb, sm, sv);
    k_fuse     <<<dim3(128, 8, 2), dim3(32, 8)>>>(resnet, rg, rb, rm, rv);
    k_inproj_tc<<<dim3(64, 8), 256, DYN>>>(inw, lg, lb);
    k_conv4    <<<(NB * LL * DI_) / 1024, 256>>>(cw, cb);
    k_xproj_tc <<<64, 256>>>(xw);
    k_dtproj   <<<dim3(128, 8), 256>>>(dtw, dtb);
    k_scan1    <<<2048, 256>>>(alog);
    k_scan2    <<<2048, 256>>>(alog, Dp);
    k_outproj_tc<<<dim3(64, 2), 256, DYN>>>(ow, out);
}

// round 7
// speedup vs baseline: 2.1817x; 1.0397x over previous
#include <cuda_runtime.h>

// ---------------- problem constants ----------------
#define NB   2
#define CR_  256
#define CS_  512
#define LL   4096     // 64*64
#define PS_  1024     // 32*32
#define DI_  512
#define DS_  16
#define NCH  32       // scan chunks
#define CT_  128      // chunk length (NCH*CT_ == LL)
#define TT_  (NB*DI_*DS_)   // 16384 scan tracks
#define EPSF 1e-5f
#define LOG2E 1.4426950408889634f

__device__ __forceinline__ unsigned tf32c(float x) {
    unsigned r; asm("cvt.rna.tf32.f32 %0, %1;" : "=r"(r) : "f"(x)); return r;
}
__device__ __forceinline__ void mma8(float* c, const unsigned* a, const unsigned* b) {
    asm volatile("mma.sync.aligned.m16n8k8.row.col.f32.tf32.tf32.f32 "
        "{%0,%1,%2,%3}, {%4,%5,%6,%7}, {%8,%9}, {%0,%1,%2,%3};"
        : "+f"(c[0]), "+f"(c[1]), "+f"(c[2]), "+f"(c[3])
        : "r"(a[0]), "r"(a[1]), "r"(a[2]), "r"(a[3]), "r"(b[0]), "r"(b[1]));
}

// ---------------- scratch (static device allocs only) ----------------
__device__ float  g_sp   [NB*CR_*PS_];
__device__ float  g_fused[NB*CR_*LL];
__device__ float  g_xt   [NB*LL*CR_];
__device__ float2 g_psum [NB*LL*8];
__device__ float  g_xm   [NB*LL*DI_];
__device__ float  g_z    [NB*LL*DI_];
__device__ float  g_u    [NB*LL*DI_];
__device__ float  g_dtin [NB*LL*DS_];
__device__ float2 g_bcc  [NB*LL*DS_];
__device__ float2 g_a    [NB*LL*DI_];
__device__ float2 g_uz   [NB*LL*DI_];
__device__ float  g_P    [NCH*TT_];       // chunk-major, state-pairs contiguous
__device__ float  g_Hc   [NCH*TT_];
__device__ float  g_yfin [NB*LL*DI_];

// =====================================================================
// K1: scp 1x1 conv GEMM + BN — TF32 TC, B transpose-staged (stride 33)
// =====================================================================
__global__ void __launch_bounds__(256)
k_scp_tc(const float* __restrict__ scp, const float* __restrict__ w,
         const float* __restrict__ gg, const float* __restrict__ bb,
         const float* __restrict__ mm, const float* __restrict__ vv) {
    __shared__ __align__(16) unsigned As[128 * 36];   // W  [o][k]
    __shared__ __align__(16) unsigned Bs[128 * 33];   // scp^T [p][k]
    const int b  = blockIdx.z;
    const int m0 = blockIdx.x * 128;   // o
    const int n0 = blockIdx.y * 128;   // p
    const int tid = threadIdx.x, lane = tid & 31, wid = tid >> 5;
    const int wm = wid >> 2, wn = wid & 3;
    const int g = lane >> 2, t4 = lane & 3;
    const int r0 = tid >> 3, c4 = tid & 7;
    const int kq = tid >> 6, pq2 = (tid & 63) * 2;
    float acc[4][4][4] = {};
    float4 av[4]; float2 bvv[8];
#pragma unroll
    for (int i = 0; i < 4; i++)
        av[i] = *(const float4*)&w[(m0 + r0 + 32 * i) * 512 + c4 * 4];
#pragma unroll
    for (int j = 0; j < 8; j++)
        bvv[j] = *(const float2*)&scp[(b * 512 + j * 4 + kq) * 1024 + n0 + pq2];
    for (int st = 0; st < 16; st++) {
#pragma unroll
        for (int i = 0; i < 4; i++) {
            unsigned* da = &As[(r0 + 32 * i) * 36 + c4 * 4];
            da[0] = tf32c(av[i].x); da[1] = tf32c(av[i].y);
            da[2] = tf32c(av[i].z); da[3] = tf32c(av[i].w);
        }
#pragma unroll
        for (int j = 0; j < 8; j++) {
            Bs[pq2 * 33 + j * 4 + kq]       = tf32c(bvv[j].x);
            Bs[(pq2 + 1) * 33 + j * 4 + kq] = tf32c(bvv[j].y);
        }
        __syncthreads();
        if (st < 15) {
            const int k0 = (st + 1) * 32;
#pragma unroll
            for (int i = 0; i < 4; i++)
                av[i] = *(const float4*)&w[(m0 + r0 + 32 * i) * 512 + k0 + c4 * 4];
#pragma unroll
            for (int j = 0; j < 8; j++)
                bvv[j] = *(const float2*)&scp[(b * 512 + k0 + j * 4 + kq) * 1024 + n0 + pq2];
        }
#pragma unroll
        for (int k8 = 0; k8 < 4; k8++) {
            const int kb = k8 * 8;
            unsigned af[4][4], bf[4][2];
#pragma unroll
            for (int mf = 0; mf < 4; mf++) {
                int m = wm * 64 + mf * 16 + g;
                af[mf][0] = As[m * 36 + kb + t4];
                af[mf][1] = As[(m + 8) * 36 + kb + t4];
                af[mf][2] = As[m * 36 + kb + t4 + 4];
                af[mf][3] = As[(m + 8) * 36 + kb + t4 + 4];
            }
#pragma unroll
            for (int nf = 0; nf < 4; nf++) {
                int n = wn * 32 + nf * 8 + g;
                bf[nf][0] = Bs[n * 33 + kb + t4];
                bf[nf][1] = Bs[n * 33 + kb + t4 + 4];
            }
#pragma unroll
            for (int mf = 0; mf < 4; mf++)
#pragma unroll
                for (int nf = 0; nf < 4; nf++)
                    mma8(acc[mf][nf], af[mf], bf[nf]);
        }
        __syncthreads();
    }
#pragma unroll
    for (int mf = 0; mf < 4; mf++) {
        int o = m0 + wm * 64 + mf * 16 + g;
        float iv0 = gg[o] * rsqrtf(vv[o] + EPSF);
        float be0 = bb[o] - mm[o] * iv0;
        float iv1 = gg[o + 8] * rsqrtf(vv[o + 8] + EPSF);
        float be1 = bb[o + 8] - mm[o + 8] * iv1;
#pragma unroll
        for (int nf = 0; nf < 4; nf++) {
            int p = n0 + wn * 32 + nf * 8 + 2 * t4;
            float* dp  = &g_sp[(b * 256 + o) * 1024 + p];
            float* dp8 = &g_sp[(b * 256 + o + 8) * 1024 + p];
            dp[0]  = acc[mf][nf][0] * iv0 + be0;
            dp[1]  = acc[mf][nf][1] * iv0 + be0;
            dp8[0] = acc[mf][nf][2] * iv1 + be1;
            dp8[1] = acc[mf][nf][3] * iv1 + be1;
        }
    }
}

// =====================================================================
// K2: fused = BN(resnet) + bilinear(sp); (B,C,HW) + (B,HW,C) + LN psums
// =====================================================================
__global__ void k_fuse(const float* __restrict__ res,
                       const float* __restrict__ rg, const float* __restrict__ rb,
                       const float* __restrict__ rm, const float* __restrict__ rv) {
    __shared__ float tile[32][33];
    const int b  = blockIdx.z;
    const int c0 = blockIdx.y * 32;
    const int l0 = blockIdx.x * 32;
    const int tx = threadIdx.x, ty = threadIdx.y;
    const int l = l0 + tx;
    const int h = l >> 6, wq = l & 63;
    float sh = h * 0.5f - 0.25f;
    float sw = wq * 0.5f - 0.25f;
    int h0 = (int)floorf(sh); float fh = sh - (float)h0;
    int w0 = (int)floorf(sw); float fw = sw - (float)w0;
    int h0c = max(h0, 0), h1c = min(h0 + 1, 31);
    int w0c = max(w0, 0), w1c = min(w0 + 1, 31);
#pragma unroll
    for (int i = 0; i < 4; i++) {
        int c = c0 + ty + i * 8;
        float inv  = rg[c] * rsqrtf(rv[c] + EPSF);
        float beta = rb[c] - rm[c] * inv;
        float val = res[(b * 256 + c) * 4096 + l] * inv + beta;
        const float* spb = g_sp + (b * 256 + c) * 1024;
        float s00 = spb[h0c * 32 + w0c], s01 = spb[h0c * 32 + w1c];
        float s10 = spb[h1c * 32 + w0c], s11 = spb[h1c * 32 + w1c];
        val += (1.f - fh) * ((1.f - fw) * s00 + fw * s01)
             +        fh  * ((1.f - fw) * s10 + fw * s11);
        g_fused[(b * 256 + c) * 4096 + l] = val;
        tile[ty + i * 8][tx] = val;
    }
    __syncthreads();
#pragma unroll
    for (int i = 0; i < 4; i++) {
        int c  = c0 + tx;
        int ll = l0 + ty + i * 8;
        g_xt[(b * 4096 + ll) * 256 + c] = tile[tx][ty + i * 8];
    }
    const int tid = ty * 32 + tx;
    if (tid < 32) {
        float s = 0.f, q = 0.f;
#pragma unroll
        for (int cc = 0; cc < 32; cc++) {
            float v = tile[cc][tid];
            s += v; q += v * v;
        }
        g_psum[(b * 4096 + l0 + tid) * 8 + (c0 >> 5)] = make_float2(s, q);
    }
}

// =====================================================================
// K4: in_proj GEMM — TF32 TC, double-buffered smem, fused LN on A
// =====================================================================
__global__ void __launch_bounds__(256)
k_inproj_tc(const float* __restrict__ w,
            const float* __restrict__ lg, const float* __restrict__ lb) {
    extern __shared__ unsigned dyn[];
    unsigned* As = dyn;             // [2][128*36]
    unsigned* Bs = dyn + 2 * 4608;  // [2][128*36]
    __shared__ float s_mu[128], s_rs[128];
    const int m0 = blockIdx.x * 128, n0 = blockIdx.y * 128;
    const int tid = threadIdx.x, lane = tid & 31, wid = tid >> 5;
    const int wm = wid >> 2, wn = wid & 3;
    const int g = lane >> 2, t4 = lane & 3;
    if (tid < 128) {
        float s = 0.f, qq = 0.f;
#pragma unroll
        for (int i = 0; i < 8; i++) {
            float2 p = g_psum[(m0 + tid) * 8 + i];
            s += p.x; qq += p.y;
        }
        float mu = s * (1.f / 256.f);
        s_mu[tid] = mu;
        s_rs[tid] = rsqrtf(qq * (1.f / 256.f) - mu * mu + EPSF);
    }
    __syncthreads();
    const int r0 = tid >> 3, c4 = tid & 7;
    float mu[4], rs[4];
#pragma unroll
    for (int i = 0; i < 4; i++) { mu[i] = s_mu[r0 + 32 * i]; rs[i] = s_rs[r0 + 32 * i]; }
    float acc[4][4][4] = {};
    float4 av[4], bv[4], g4, e4;
#pragma unroll
    for (int i = 0; i < 4; i++) {
        av[i] = *(const float4*)&g_xt[(m0 + r0 + 32 * i) * 256 + c4 * 4];
        bv[i] = *(const float4*)&w[(n0 + r0 + 32 * i) * 256 + c4 * 4];
    }
    g4 = *(const float4*)&lg[c4 * 4];
    e4 = *(const float4*)&lb[c4 * 4];
#pragma unroll
    for (int i = 0; i < 4; i++) {
        int row = r0 + 32 * i;
        unsigned* da = &As[row * 36 + c4 * 4];
        da[0] = tf32c((av[i].x - mu[i]) * rs[i] * g4.x + e4.x);
        da[1] = tf32c((av[i].y - mu[i]) * rs[i] * g4.y + e4.y);
        da[2] = tf32c((av[i].z - mu[i]) * rs[i] * g4.z + e4.z);
        da[3] = tf32c((av[i].w - mu[i]) * rs[i] * g4.w + e4.w);
        unsigned* db = &Bs[row * 36 + c4 * 4];
        db[0] = tf32c(bv[i].x); db[1] = tf32c(bv[i].y);
        db[2] = tf32c(bv[i].z); db[3] = tf32c(bv[i].w);
    }
    __syncthreads();
    for (int st = 0; st < 8; st++) {
        const unsigned* Ab = As + (st & 1) * 4608;
        const unsigned* Bb = Bs + (st & 1) * 4608;
        if (st < 7) {
            const int k0 = (st + 1) * 32;
#pragma unroll
            for (int i = 0; i < 4; i++) {
                av[i] = *(const float4*)&g_xt[(m0 + r0 + 32 * i) * 256 + k0 + c4 * 4];
                bv[i] = *(const float4*)&w[(n0 + r0 + 32 * i) * 256 + k0 + c4 * 4];
            }
            g4 = *(const float4*)&lg[k0 + c4 * 4];
            e4 = *(const float4*)&lb[k0 + c4 * 4];
        }
#pragma unroll
        for (int k8 = 0; k8 < 4; k8++) {
            const int kb = k8 * 8;
            unsigned af[4][4], bf[4][2];
#pragma unroll
            for (int mf = 0; mf < 4; mf++) {
                int m = wm * 64 + mf * 16 + g;
                af[mf][0] = Ab[m * 36 + kb + t4];
                af[mf][1] = Ab[(m + 8) * 36 + kb + t4];
                af[mf][2] = Ab[m * 36 + kb + t4 + 4];
                af[mf][3] = Ab[(m + 8) * 36 + kb + t4 + 4];
            }
#pragma unroll
            for (int nf = 0; nf < 4; nf++) {
                int n = wn * 32 + nf * 8 + g;
                bf[nf][0] = Bb[n * 36 + kb + t4];
                bf[nf][1] = Bb[n * 36 + kb + t4 + 4];
            }
#pragma unroll
            for (int mf = 0; mf < 4; mf++)
#pragma unroll
                for (int nf = 0; nf < 4; nf++)
                    mma8(acc[mf][nf], af[mf], bf[nf]);
        }
        if (st < 7) {
            unsigned* Aw = As + ((st + 1) & 1) * 4608;
            unsigned* Bw = Bs + ((st + 1) & 1) * 4608;
#pragma unroll
            for (int i = 0; i < 4; i++) {
                int row = r0 + 32 * i;
                unsigned* da = &Aw[row * 36 + c4 * 4];
                da[0] = tf32c((av[i].x - mu[i]) * rs[i] * g4.x + e4.x);
                da[1] = tf32c((av[i].y - mu[i]) * rs[i] * g4.y + e4.y);
                da[2] = tf32c((av[i].z - mu[i]) * rs[i] * g4.z + e4.z);
                da[3] = tf32c((av[i].w - mu[i]) * rs[i] * g4.w + e4.w);
                unsigned* db = &Bw[row * 36 + c4 * 4];
                db[0] = tf32c(bv[i].x); db[1] = tf32c(bv[i].y);
                db[2] = tf32c(bv[i].z); db[3] = tf32c(bv[i].w);
            }
            __syncthreads();
        }
    }
    float* dst = (n0 < 512) ? g_xm : g_z;
    const int nb = (n0 < 512) ? n0 : (n0 - 512);
#pragma unroll
    for (int mf = 0; mf < 4; mf++) {
        int m = m0 + wm * 64 + mf * 16 + g;
#pragma unroll
        for (int nf = 0; nf < 4; nf++) {
            int n = nb + wn * 32 + nf * 8 + 2 * t4;
            *(float2*)&dst[m * 512 + n]       = make_float2(acc[mf][nf][0], acc[mf][nf][1]);
            *(float2*)&dst[(m + 8) * 512 + n] = make_float2(acc[mf][nf][2], acc[mf][nf][3]);
        }
    }
}

// =====================================================================
// K5: causal depthwise conv (k=3) + SiLU -> u ; {u, silu(z)}; float4
// =====================================================================
__global__ void k_conv4(const float* __restrict__ cw, const float* __restrict__ cb) {
    const int g = blockIdx.x * blockDim.x + threadIdx.x;
    const int base = g * 4;
    const int d = base & 511;
    const int l = (base >> 9) & 4095;
    float4 x2 = *(const float4*)&g_xm[base];
    float4 x1 = make_float4(0.f, 0.f, 0.f, 0.f);
    float4 x0 = make_float4(0.f, 0.f, 0.f, 0.f);
    if (l >= 1) x1 = *(const float4*)&g_xm[base - 512];
    if (l >= 2) x0 = *(const float4*)&g_xm[base - 1024];
    float4 w0 = *(const float4*)&cw[d * 3];
    float4 w1 = *(const float4*)&cw[d * 3 + 4];
    float4 w2 = *(const float4*)&cw[d * 3 + 8];
    float4 cb4 = *(const float4*)&cb[d];
    float f[12] = {w0.x, w0.y, w0.z, w0.w, w1.x, w1.y, w1.z, w1.w, w2.x, w2.y, w2.z, w2.w};
    float a0 = x0.x * f[0] + x1.x * f[1]  + x2.x * f[2]  + cb4.x;
    float a1 = x0.y * f[3] + x1.y * f[4]  + x2.y * f[5]  + cb4.y;
    float a2 = x0.z * f[6] + x1.z * f[7]  + x2.z * f[8]  + cb4.z;
    float a3 = x0.w * f[9] + x1.w * f[10] + x2.w * f[11] + cb4.w;
    float4 u4;
    u4.x = a0 / (1.f + __expf(-a0));
    u4.y = a1 / (1.f + __expf(-a1));
    u4.z = a2 / (1.f + __expf(-a2));
    u4.w = a3 / (1.f + __expf(-a3));
    *(float4*)&g_u[base] = u4;
    float4 z4 = *(const float4*)&g_z[base];
    float4 p0, p1;
    p0.x = u4.x; p0.y = z4.x / (1.f + __expf(-z4.x));
    p0.z = u4.y; p0.w = z4.y / (1.f + __expf(-z4.y));
    p1.x = u4.z; p1.y = z4.z / (1.f + __expf(-z4.z));
    p1.z = u4.w; p1.w = z4.w / (1.f + __expf(-z4.w));
    *(float4*)&g_uz[base]     = p0;
    *(float4*)&g_uz[base + 2] = p1;
}

// =====================================================================
// K6: x_proj GEMM — TF32 TC 128x64 (48 live cols), writes dtin + bcc
// =====================================================================
__global__ void __launch_bounds__(256)
k_xproj_tc(const float* __restrict__ w) {
    __shared__ __align__(16) unsigned As[128 * 36];
    __shared__ __align__(16) unsigned Bs[64 * 36];
    const int m0 = blockIdx.x * 128;
    const int tid = threadIdx.x, lane = tid & 31, wid = tid >> 5;
    const int wm = wid >> 1, wn = wid & 1;
    const int g = lane >> 2, t4 = lane & 3;
    const int r0 = tid >> 3, c4 = tid & 7;
    float acc[2][4][4] = {};
    float4 av[4], bv[2];
#pragma unroll
    for (int i = 0; i < 4; i++)
        av[i] = *(const float4*)&g_u[(m0 + r0 + 32 * i) * 512 + c4 * 4];
#pragma unroll
    for (int i = 0; i < 2; i++) {
        int n = r0 + 32 * i;
        bv[i] = (n < 48) ? *(const float4*)&w[n * 512 + c4 * 4]
                         : make_float4(0.f, 0.f, 0.f, 0.f);
    }
    for (int st = 0; st < 16; st++) {
#pragma unroll
        for (int i = 0; i < 4; i++) {
            unsigned* da = &As[(r0 + 32 * i) * 36 + c4 * 4];
            da[0] = tf32c(av[i].x); da[1] = tf32c(av[i].y);
            da[2] = tf32c(av[i].z); da[3] = tf32c(av[i].w);
        }
#pragma unroll
        for (int i = 0; i < 2; i++) {
            unsigned* db = &Bs[(r0 + 32 * i) * 36 + c4 * 4];
            db[0] = tf32c(bv[i].x); db[1] = tf32c(bv[i].y);
            db[2] = tf32c(bv[i].z); db[3] = tf32c(bv[i].w);
        }
        __syncthreads();
        if (st < 15) {
            const int k0 = (st + 1) * 32;
#pragma unroll
            for (int i = 0; i < 4; i++)
                av[i] = *(const float4*)&g_u[(m0 + r0 + 32 * i) * 512 + k0 + c4 * 4];
#pragma unroll
            for (int i = 0; i < 2; i++) {
                int n = r0 + 32 * i;
                bv[i] = (n < 48) ? *(const float4*)&w[n * 512 + k0 + c4 * 4]
                                 : make_float4(0.f, 0.f, 0.f, 0.f);
            }
        }
#pragma unroll
        for (int k8 = 0; k8 < 4; k8++) {
            const int kb = k8 * 8;
            unsigned af[2][4], bf[4][2];
#pragma unroll
            for (int mf = 0; mf < 2; mf++) {
                int m = wm * 32 + mf * 16 + g;
                af[mf][0] = As[m * 36 + kb + t4];
                af[mf][1] = As[(m + 8) * 36 + kb + t4];
                af[mf][2] = As[m * 36 + kb + t4 + 4];
                af[mf][3] = As[(m + 8) * 36 + kb + t4 + 4];
            }
#pragma unroll
            for (int nf = 0; nf < 4; nf++) {
                int n = wn * 32 + nf * 8 + g;
                bf[nf][0] = Bs[n * 36 + kb + t4];
                bf[nf][1] = Bs[n * 36 + kb + t4 + 4];
            }
#pragma unroll
            for (int mf = 0; mf < 2; mf++)
#pragma unroll
                for (int nf = 0; nf < 4; nf++)
                    mma8(acc[mf][nf], af[mf], bf[nf]);
        }
        __syncthreads();
    }
    float* bccf = (float*)g_bcc;
#pragma unroll
    for (int mf = 0; mf < 2; mf++) {
#pragma unroll
        for (int nf = 0; nf < 4; nf++) {
#pragma unroll
            for (int half = 0; half < 2; half++) {
                int gm = m0 + wm * 32 + mf * 16 + g + half * 8;
#pragma unroll
                for (int jj = 0; jj < 2; jj++) {
                    int gn = wn * 32 + nf * 8 + 2 * t4 + jj;
                    float v = acc[mf][nf][half * 2 + jj];
                    if (gn < 16)      g_dtin[gm * 16 + gn] = v;
                    else if (gn < 32) bccf[gm * 32 + 2 * (gn - 16)] = v;
                    else if (gn < 48) bccf[gm * 32 + 2 * (gn - 32) + 1] = v;
                }
            }
        }
    }
}

// =====================================================================
// K7: dt_proj GEMM (K=16) + softplus; writes {dt, dt*u}
// =====================================================================
__global__ void k_dtproj(const float* __restrict__ w, const float* __restrict__ dtb) {
    __shared__ float As[16][65];
    __shared__ float Bs[16][65];
    const int m0 = blockIdx.x * 64;
    const int n0 = blockIdx.y * 64;
    const int tid = threadIdx.x;
    const int tx = tid & 15, ty = tid >> 4;
    float acc[4][4] = {};
#pragma unroll
    for (int i = 0; i < 4; i++) {
        int idx = tid + i * 256;
        int m = idx >> 4, kk = idx & 15;
        As[kk][m] = g_dtin[(m0 + m) * 16 + kk];
    }
#pragma unroll
    for (int i = 0; i < 4; i++) {
        int idx = tid + i * 256;
        int n = idx >> 4, kk = idx & 15;
        Bs[kk][n] = w[(n0 + n) * 16 + kk];
    }
    __syncthreads();
#pragma unroll
    for (int kk = 0; kk < 16; kk++) {
        float a[4], c[4];
#pragma unroll
        for (int i = 0; i < 4; i++) a[i] = As[kk][ty * 4 + i];
#pragma unroll
        for (int j = 0; j < 4; j++) c[j] = Bs[kk][tx * 4 + j];
#pragma unroll
        for (int i = 0; i < 4; i++)
#pragma unroll
            for (int j = 0; j < 4; j++) acc[i][j] += a[i] * c[j];
    }
#pragma unroll
    for (int i = 0; i < 4; i++) {
        int gm = m0 + ty * 4 + i;
        float4 u4 = *(const float4*)&g_u[gm * 512 + n0 + tx * 4];
        float um[4] = {u4.x, u4.y, u4.z, u4.w};
#pragma unroll
        for (int j = 0; j < 4; j++) {
            int gn = n0 + tx * 4 + j;
            float x = acc[i][j] + dtb[gn];
            float sp = (x > 20.f) ? x : log1pf(__expf(x));
            float2 p; p.x = sp; p.y = sp * um[j];
            g_a[gm * 512 + gn] = p;
        }
    }
}

// =====================================================================
// K8: scan pass 1 — warp = 4 channels x 8 lanes x 2 states/lane
// =====================================================================
__global__ void __launch_bounds__(256)
k_scan1(const float* __restrict__ alog) {
    const int w    = (blockIdx.x * blockDim.x + threadIdx.x) >> 5;
    const int lane = threadIdx.x & 31;
    const int chunk = w & (NCH - 1);
    const int dq   = (w >> 5) & 127;
    const int b    = w >> 12;
    const int c2 = lane >> 3, s8 = lane & 7;
    const int d  = dq * 4 + c2;
    const int s0 = 2 * s8;
    const float An2a = -__expf(alog[d * 16 + s0])     * LOG2E;
    const float An2b = -__expf(alog[d * 16 + s0 + 1]) * LOG2E;
    float2 h = make_float2(0.f, 0.f);
    float2 P = make_float2(1.f, 1.f);
    const int l0 = chunk * CT_;
    const float2* ap = g_a + (size_t)(b * LL + l0) * 512 + d;
    const float4* bp = (const float4*)(g_bcc + (size_t)(b * LL + l0) * 16) + s8;
#pragma unroll 8
    for (int t = 0; t < CT_; t++) {
        float2 av = ap[t * 512];
        float4 bc = bp[t * 8];
        float dAa = exp2f(av.x * An2a);
        float dAb = exp2f(av.x * An2b);
        h.x = fmaf(dAa, h.x, av.y * bc.x);
        h.y = fmaf(dAb, h.y, av.y * bc.z);
        P.x *= dAa; P.y *= dAb;
    }
    const int tI = (b * 512 + d) * 16 + s0;
    *(float2*)&g_P[chunk * TT_ + tI]  = P;
    *(float2*)&g_Hc[chunk * TT_ + tI] = h;
}

// =====================================================================
// K10: scan pass 2 — inline prefix combine + replay + y
// =====================================================================
__global__ void __launch_bounds__(256)
k_scan2(const float* __restrict__ alog, const float* __restrict__ Dp) {
    const int w    = (blockIdx.x * blockDim.x + threadIdx.x) >> 5;
    const int lane = threadIdx.x & 31;
    const int chunk = w & (NCH - 1);
    const int dq   = (w >> 5) & 127;
    const int b    = w >> 12;
    const int c2 = lane >> 3, s8 = lane & 7;
    const int d  = dq * 4 + c2;
    const int s0 = 2 * s8;
    const float An2a = -__expf(alog[d * 16 + s0])     * LOG2E;
    const float An2b = -__expf(alog[d * 16 + s0 + 1]) * LOG2E;
    const float Dv = Dp[d];
    const int tI = (b * 512 + d) * 16 + s0;
    float2 h = make_float2(0.f, 0.f);
#pragma unroll
    for (int c = 0; c < NCH; c++) {
        if (c < chunk) {
            float2 Pv = *(const float2*)&g_P[c * TT_ + tI];
            float2 Hv = *(const float2*)&g_Hc[c * TT_ + tI];
            h.x = Pv.x * h.x + Hv.x;
            h.y = Pv.y * h.y + Hv.y;
        }
    }
    const int l0 = chunk * CT_;
    const float2* ap = g_a  + (size_t)(b * LL + l0) * 512 + d;
    const float4* bp = (const float4*)(g_bcc + (size_t)(b * LL + l0) * 16) + s8;
    const float2* up = g_uz + (size_t)(b * LL + l0) * 512 + d;
    float* yp = g_yfin + (size_t)(b * LL + l0) * 512 + d;
#pragma unroll 4
    for (int t = 0; t < CT_; t++) {
        float2 av = ap[t * 512];
        float4 bc = bp[t * 8];
        float dAa = exp2f(av.x * An2a);
        float dAb = exp2f(av.x * An2b);
        h.x = fmaf(dAa, h.x, av.y * bc.x);
        h.y = fmaf(dAb, h.y, av.y * bc.z);
        float part = h.x * bc.y + h.y * bc.w;
        part += __shfl_xor_sync(0xffffffffu, part, 1);
        part += __shfl_xor_sync(0xffffffffu, part, 2);
        part += __shfl_xor_sync(0xffffffffu, part, 4);
        if (s8 == 0) {
            float2 uzv = up[t * 512];
            yp[t * 512] = (part + uzv.x * Dv) * uzv.y;
        }
    }
}

// =====================================================================
// K11: out_proj GEMM — TF32 TC, double-buffered, residual + NCHW scatter
// =====================================================================
__global__ void __launch_bounds__(256)
k_outproj_tc(const float* __restrict__ w, float* __restrict__ out) {
    extern __shared__ unsigned dyn[];
    unsigned* As = dyn;
    unsigned* Bs = dyn + 2 * 4608;
    const int m0 = blockIdx.x * 128, n0 = blockIdx.y * 128;
    const int tid = threadIdx.x, lane = tid & 31, wid = tid >> 5;
    const int wm = wid >> 2, wn = wid & 3;
    const int g = lane >> 2, t4 = lane & 3;
    const int r0 = tid >> 3, c4 = tid & 7;
    float acc[4][4][4] = {};
    float4 av[4], bv[4];
#pragma unroll
    for (int i = 0; i < 4; i++) {
        av[i] = *(const float4*)&g_yfin[(m0 + r0 + 32 * i) * 512 + c4 * 4];
        bv[i] = *(const float4*)&w[(n0 + r0 + 32 * i) * 512 + c4 * 4];
    }
#pragma unroll
    for (int i = 0; i < 4; i++) {
        int row = r0 + 32 * i;
        unsigned* da = &As[row * 36 + c4 * 4];
        da[0] = tf32c(av[i].x); da[1] = tf32c(av[i].y);
        da[2] = tf32c(av[i].z); da[3] = tf32c(av[i].w);
        unsigned* db = &Bs[row * 36 + c4 * 4];
        db[0] = tf32c(bv[i].x); db[1] = tf32c(bv[i].y);
        db[2] = tf32c(bv[i].z); db[3] = tf32c(bv[i].w);
    }
    __syncthreads();
    for (int st = 0; st < 16; st++) {
        const unsigned* Ab = As + (st & 1) * 4608;
        const unsigned* Bb = Bs + (st & 1) * 4608;
        if (st < 15) {
            const int k0 = (st + 1) * 32;
#pragma unroll
            for (int i = 0; i < 4; i++) {
                av[i] = *(const float4*)&g_yfin[(m0 + r0 + 32 * i) * 512 + k0 + c4 * 4];
                bv[i] = *(const float4*)&w[(n0 + r0 + 32 * i) * 512 + k0 + c4 * 4];
            }
        }
#pragma unroll
        for (int k8 = 0; k8 < 4; k8++) {
            const int kb = k8 * 8;
            unsigned af[4][4], bf[4][2];
#pragma unroll
            for (int mf = 0; mf < 4; mf++) {
                int m = wm * 64 + mf * 16 + g;
                af[mf][0] = Ab[m * 36 + kb + t4];
                af[mf][1] = Ab[(m + 8) * 36 + kb + t4];
                af[mf][2] = Ab[m * 36 + kb + t4 + 4];
                af[mf][3] = Ab[(m + 8) * 36 + kb + t4 + 4];
            }
#pragma unroll
            for (int nf = 0; nf < 4; nf++) {
                int n = wn * 32 + nf * 8 + g;
                bf[nf][0] = Bb[n * 36 + kb + t4];
                bf[nf][1] = Bb[n * 36 + kb + t4 + 4];
            }
#pragma unroll
            for (int mf = 0; mf < 4; mf++)
#pragma unroll
                for (int nf = 0; nf < 4; nf++)
                    mma8(acc[mf][nf], af[mf], bf[nf]);
        }
        if (st < 15) {
            unsigned* Aw = As + ((st + 1) & 1) * 4608;
            unsigned* Bw = Bs + ((st + 1) & 1) * 4608;
#pragma unroll
            for (int i = 0; i < 4; i++) {
                int row = r0 + 32 * i;
                unsigned* da = &Aw[row * 36 + c4 * 4];
                da[0] = tf32c(av[i].x); da[1] = tf32c(av[i].y);
                da[2] = tf32c(av[i].z); da[3] = tf32c(av[i].w);
                unsigned* db = &Bw[row * 36 + c4 * 4];
                db[0] = tf32c(bv[i].x); db[1] = tf32c(bv[i].y);
                db[2] = tf32c(bv[i].z); db[3] = tf32c(bv[i].w);
            }
            __syncthreads();
        }
    }
    const int bb = m0 >> 12;
#pragma unroll
    for (int mf = 0; mf < 4; mf++) {
        int m = m0 + wm * 64 + mf * 16 + g;
        int l = m & 4095;
#pragma unroll
        for (int nf = 0; nf < 4; nf++) {
            int n = n0 + wn * 32 + nf * 8 + 2 * t4;
            size_t i0 = (size_t)(bb * 256 + n) * 4096 + l;
            size_t i1 = i0 + 4096;
            out[i0]     = acc[mf][nf][0] + g_fused[i0];
            out[i1]     = acc[mf][nf][1] + g_fused[i1];
            out[i0 + 8] = acc[mf][nf][2] + g_fused[i0 + 8];
            out[i1 + 8] = acc[mf][nf][3] + g_fused[i1 + 8];
        }
    }
}

// =====================================================================
extern "C" void kernel_launch(void* const* d_in, const int* in_sizes, int n_in,
                              void* d_out, int out_size) {
    const float* resnet = (const float*)d_in[0];
    const float* scp    = (const float*)d_in[1];
    const float* scpw   = (const float*)d_in[2];
    const float* sg = (const float*)d_in[3];
    const float* sb = (const float*)d_in[4];
    const float* sm = (const float*)d_in[5];
    const float* sv = (const float*)d_in[6];
    const float* rg = (const float*)d_in[7];
    const float* rb = (const float*)d_in[8];
    const float* rm = (const float*)d_in[9];
    const float* rv = (const float*)d_in[10];
    const float* lg = (const float*)d_in[11];
    const float* lb = (const float*)d_in[12];
    const float* inw = (const float*)d_in[13];
    const float* cw  = (const float*)d_in[14];
    const float* cb  = (const float*)d_in[15];
    const float* xw  = (const float*)d_in[16];
    const float* dtw = (const float*)d_in[17];
    const float* dtb = (const float*)d_in[18];
    const float* alog = (const float*)d_in[19];
    const float* Dp   = (const float*)d_in[20];
    const float* ow   = (const float*)d_in[21];
    float* out = (float*)d_out;

    const int DYN = 4 * 4608 * 4;  // 73728 bytes (double-buffered As+Bs)
    cudaFuncSetAttribute(k_inproj_tc, cudaFuncAttributeMaxDynamicSharedMemorySize, DYN);
    cudaFuncSetAttribute(k_outproj_tc, cudaFuncAttributeMaxDynamicSharedMemorySize, DYN);

    k_scp_tc   <<<dim3(2, 8, 2), 256>>>(scp, scpw, sg, sb, sm, sv);
    k_fuse     <<<dim3(128, 8, 2), dim3(32, 8)>>>(resnet, rg, rb, rm, rv);
    k_inproj_tc<<<dim3(64, 8), 256, DYN>>>(inw, lg, lb);
    k_conv4    <<<(NB * LL * DI_) / 1024, 256>>>(cw, cb);
    k_xproj_tc <<<64, 256>>>(xw);
    k_dtproj   <<<dim3(128, 8), 256>>>(dtw, dtb);
    k_scan1    <<<1024, 256>>>(alog);
    k_scan2    <<<1024, 256>>>(alog, Dp);
    k_outproj_tc<<<dim3(64, 2), 256, DYN>>>(ow, out);
}

// round 8
// speedup vs baseline: 2.2802x; 1.0452x over previous
#include <cuda_runtime.h>
#include <cuda_fp16.h>

// ---------------- problem constants ----------------
#define NB   2
#define CR_  256
#define CS_  512
#define LL   4096     // 64*64
#define PS_  1024     // 32*32
#define DI_  512
#define DS_  16
#define NCH  32       // scan chunks
#define CT_  128      // chunk length (NCH*CT_ == LL)
#define TT_  (NB*DI_*DS_)   // 16384 scan tracks
#define EPSF 1e-5f
#define LOG2E 1.4426950408889634f

__device__ __forceinline__ unsigned tf32c(float x) {
    unsigned r; asm("cvt.rna.tf32.f32 %0, %1;" : "=r"(r) : "f"(x)); return r;
}
__device__ __forceinline__ void mma8(float* c, const unsigned* a, const unsigned* b) {
    asm volatile("mma.sync.aligned.m16n8k8.row.col.f32.tf32.tf32.f32 "
        "{%0,%1,%2,%3}, {%4,%5,%6,%7}, {%8,%9}, {%0,%1,%2,%3};"
        : "+f"(c[0]), "+f"(c[1]), "+f"(c[2]), "+f"(c[3])
        : "r"(a[0]), "r"(a[1]), "r"(a[2]), "r"(a[3]), "r"(b[0]), "r"(b[1]));
}

// ---------------- scratch (static device allocs only) ----------------
__device__ float   g_sp   [NB*CR_*PS_];
__device__ float   g_fused[NB*CR_*LL];
__device__ float   g_xt   [NB*LL*CR_];
__device__ float2  g_psum [NB*LL*8];
__device__ float   g_xm   [NB*LL*DI_];
__device__ float   g_z    [NB*LL*DI_];
__device__ float   g_u    [NB*LL*DI_];
__device__ float   g_dtin [NB*LL*DS_];
__device__ float2  g_bcc  [NB*LL*DS_];
__device__ __half2 g_a    [NB*LL*DI_];    // {dt, dt*u} fp16
__device__ __half2 g_uz   [NB*LL*DI_];    // {u, silu(z)} fp16
__device__ float   g_P    [NCH*TT_];      // chunk-major, state-pairs contiguous
__device__ float   g_Hc   [NCH*TT_];
__device__ __half  g_yfin [NB*LL*DI_];    // y fp16

// =====================================================================
// K1: scp 1x1 conv GEMM + BN — TF32 TC, B transpose-staged (stride 33)
// =====================================================================
__global__ void __launch_bounds__(256)
k_scp_tc(const float* __restrict__ scp, const float* __restrict__ w,
         const float* __restrict__ gg, const float* __restrict__ bb,
         const float* __restrict__ mm, const float* __restrict__ vv) {
    __shared__ __align__(16) unsigned As[128 * 36];   // W  [o][k]
    __shared__ __align__(16) unsigned Bs[128 * 33];   // scp^T [p][k]
    const int b  = blockIdx.z;
    const int m0 = blockIdx.x * 128;   // o
    const int n0 = blockIdx.y * 128;   // p
    const int tid = threadIdx.x, lane = tid & 31, wid = tid >> 5;
    const int wm = wid >> 2, wn = wid & 3;
    const int g = lane >> 2, t4 = lane & 3;
    const int r0 = tid >> 3, c4 = tid & 7;
    const int kq = tid >> 6, pq2 = (tid & 63) * 2;
    float acc[4][4][4] = {};
    float4 av[4]; float2 bvv[8];
#pragma unroll
    for (int i = 0; i < 4; i++)
        av[i] = *(const float4*)&w[(m0 + r0 + 32 * i) * 512 + c4 * 4];
#pragma unroll
    for (int j = 0; j < 8; j++)
        bvv[j] = *(const float2*)&scp[(b * 512 + j * 4 + kq) * 1024 + n0 + pq2];
    for (int st = 0; st < 16; st++) {
#pragma unroll
        for (int i = 0; i < 4; i++) {
            unsigned* da = &As[(r0 + 32 * i) * 36 + c4 * 4];
            da[0] = tf32c(av[i].x); da[1] = tf32c(av[i].y);
            da[2] = tf32c(av[i].z); da[3] = tf32c(av[i].w);
        }
#pragma unroll
        for (int j = 0; j < 8; j++) {
            Bs[pq2 * 33 + j * 4 + kq]       = tf32c(bvv[j].x);
            Bs[(pq2 + 1) * 33 + j * 4 + kq] = tf32c(bvv[j].y);
        }
        __syncthreads();
        if (st < 15) {
            const int k0 = (st + 1) * 32;
#pragma unroll
            for (int i = 0; i < 4; i++)
                av[i] = *(const float4*)&w[(m0 + r0 + 32 * i) * 512 + k0 + c4 * 4];
#pragma unroll
            for (int j = 0; j < 8; j++)
                bvv[j] = *(const float2*)&scp[(b * 512 + k0 + j * 4 + kq) * 1024 + n0 + pq2];
        }
#pragma unroll
        for (int k8 = 0; k8 < 4; k8++) {
            const int kb = k8 * 8;
            unsigned af[4][4], bf[4][2];
#pragma unroll
            for (int mf = 0; mf < 4; mf++) {
                int m = wm * 64 + mf * 16 + g;
                af[mf][0] = As[m * 36 + kb + t4];
                af[mf][1] = As[(m + 8) * 36 + kb + t4];
                af[mf][2] = As[m * 36 + kb + t4 + 4];
                af[mf][3] = As[(m + 8) * 36 + kb + t4 + 4];
            }
#pragma unroll
            for (int nf = 0; nf < 4; nf++) {
                int n = wn * 32 + nf * 8 + g;
                bf[nf][0] = Bs[n * 33 + kb + t4];
                bf[nf][1] = Bs[n * 33 + kb + t4 + 4];
            }
#pragma unroll
            for (int mf = 0; mf < 4; mf++)
#pragma unroll
                for (int nf = 0; nf < 4; nf++)
                    mma8(acc[mf][nf], af[mf], bf[nf]);
        }
        __syncthreads();
    }
#pragma unroll
    for (int mf = 0; mf < 4; mf++) {
        int o = m0 + wm * 64 + mf * 16 + g;
        float iv0 = gg[o] * rsqrtf(vv[o] + EPSF);
        float be0 = bb[o] - mm[o] * iv0;
        float iv1 = gg[o + 8] * rsqrtf(vv[o + 8] + EPSF);
        float be1 = bb[o + 8] - mm[o + 8] * iv1;
#pragma unroll
        for (int nf = 0; nf < 4; nf++) {
            int p = n0 + wn * 32 + nf * 8 + 2 * t4;
            float* dp  = &g_sp[(b * 256 + o) * 1024 + p];
            float* dp8 = &g_sp[(b * 256 + o + 8) * 1024 + p];
            dp[0]  = acc[mf][nf][0] * iv0 + be0;
            dp[1]  = acc[mf][nf][1] * iv0 + be0;
            dp8[0] = acc[mf][nf][2] * iv1 + be1;
            dp8[1] = acc[mf][nf][3] * iv1 + be1;
        }
    }
}

// =====================================================================
// K2: fused = BN(resnet) + bilinear(sp); (B,C,HW) + (B,HW,C) + LN psums
// =====================================================================
__global__ void k_fuse(const float* __restrict__ res,
                       const float* __restrict__ rg, const float* __restrict__ rb,
                       const float* __restrict__ rm, const float* __restrict__ rv) {
    __shared__ float tile[32][33];
    const int b  = blockIdx.z;
    const int c0 = blockIdx.y * 32;
    const int l0 = blockIdx.x * 32;
    const int tx = threadIdx.x, ty = threadIdx.y;
    const int l = l0 + tx;
    const int h = l >> 6, wq = l & 63;
    float sh = h * 0.5f - 0.25f;
    float sw = wq * 0.5f - 0.25f;
    int h0 = (int)floorf(sh); float fh = sh - (float)h0;
    int w0 = (int)floorf(sw); float fw = sw - (float)w0;
    int h0c = max(h0, 0), h1c = min(h0 + 1, 31);
    int w0c = max(w0, 0), w1c = min(w0 + 1, 31);
#pragma unroll
    for (int i = 0; i < 4; i++) {
        int c = c0 + ty + i * 8;
        float inv  = rg[c] * rsqrtf(rv[c] + EPSF);
        float beta = rb[c] - rm[c] * inv;
        float val = res[(b * 256 + c) * 4096 + l] * inv + beta;
        const float* spb = g_sp + (b * 256 + c) * 1024;
        float s00 = spb[h0c * 32 + w0c], s01 = spb[h0c * 32 + w1c];
        float s10 = spb[h1c * 32 + w0c], s11 = spb[h1c * 32 + w1c];
        val += (1.f - fh) * ((1.f - fw) * s00 + fw * s01)
             +        fh  * ((1.f - fw) * s10 + fw * s11);
        g_fused[(b * 256 + c) * 4096 + l] = val;
        tile[ty + i * 8][tx] = val;
    }
    __syncthreads();
#pragma unroll
    for (int i = 0; i < 4; i++) {
        int c  = c0 + tx;
        int ll = l0 + ty + i * 8;
        g_xt[(b * 4096 + ll) * 256 + c] = tile[tx][ty + i * 8];
    }
    const int tid = ty * 32 + tx;
    if (tid < 32) {
        float s = 0.f, q = 0.f;
#pragma unroll
        for (int cc = 0; cc < 32; cc++) {
            float v = tile[cc][tid];
            s += v; q += v * v;
        }
        g_psum[(b * 4096 + l0 + tid) * 8 + (c0 >> 5)] = make_float2(s, q);
    }
}

// =====================================================================
// K4: in_proj GEMM — TF32 TC, double-buffered smem, fused LN on A
// =====================================================================
__global__ void __launch_bounds__(256)
k_inproj_tc(const float* __restrict__ w,
            const float* __restrict__ lg, const float* __restrict__ lb) {
    extern __shared__ unsigned dyn[];
    unsigned* As = dyn;             // [2][128*36]
    unsigned* Bs = dyn + 2 * 4608;  // [2][128*36]
    __shared__ float s_mu[128], s_rs[128];
    const int m0 = blockIdx.x * 128, n0 = blockIdx.y * 128;
    const int tid = threadIdx.x, lane = tid & 31, wid = tid >> 5;
    const int wm = wid >> 2, wn = wid & 3;
    const int g = lane >> 2, t4 = lane & 3;
    if (tid < 128) {
        float s = 0.f, qq = 0.f;
#pragma unroll
        for (int i = 0; i < 8; i++) {
            float2 p = g_psum[(m0 + tid) * 8 + i];
            s += p.x; qq += p.y;
        }
        float mu = s * (1.f / 256.f);
        s_mu[tid] = mu;
        s_rs[tid] = rsqrtf(qq * (1.f / 256.f) - mu * mu + EPSF);
    }
    __syncthreads();
    const int r0 = tid >> 3, c4 = tid & 7;
    float mu[4], rs[4];
#pragma unroll
    for (int i = 0; i < 4; i++) { mu[i] = s_mu[r0 + 32 * i]; rs[i] = s_rs[r0 + 32 * i]; }
    float acc[4][4][4] = {};
    float4 av[4], bv[4], g4, e4;
#pragma unroll
    for (int i = 0; i < 4; i++) {
        av[i] = *(const float4*)&g_xt[(m0 + r0 + 32 * i) * 256 + c4 * 4];
        bv[i] = *(const float4*)&w[(n0 + r0 + 32 * i) * 256 + c4 * 4];
    }
    g4 = *(const float4*)&lg[c4 * 4];
    e4 = *(const float4*)&lb[c4 * 4];
#pragma unroll
    for (int i = 0; i < 4; i++) {
        int row = r0 + 32 * i;
        unsigned* da = &As[row * 36 + c4 * 4];
        da[0] = tf32c((av[i].x - mu[i]) * rs[i] * g4.x + e4.x);
        da[1] = tf32c((av[i].y - mu[i]) * rs[i] * g4.y + e4.y);
        da[2] = tf32c((av[i].z - mu[i]) * rs[i] * g4.z + e4.z);
        da[3] = tf32c((av[i].w - mu[i]) * rs[i] * g4.w + e4.w);
        unsigned* db = &Bs[row * 36 + c4 * 4];
        db[0] = tf32c(bv[i].x); db[1] = tf32c(bv[i].y);
        db[2] = tf32c(bv[i].z); db[3] = tf32c(bv[i].w);
    }
    __syncthreads();
    for (int st = 0; st < 8; st++) {
        const unsigned* Ab = As + (st & 1) * 4608;
        const unsigned* Bb = Bs + (st & 1) * 4608;
        if (st < 7) {
            const int k0 = (st + 1) * 32;
#pragma unroll
            for (int i = 0; i < 4; i++) {
                av[i] = *(const float4*)&g_xt[(m0 + r0 + 32 * i) * 256 + k0 + c4 * 4];
                bv[i] = *(const float4*)&w[(n0 + r0 + 32 * i) * 256 + k0 + c4 * 4];
            }
            g4 = *(const float4*)&lg[k0 + c4 * 4];
            e4 = *(const float4*)&lb[k0 + c4 * 4];
        }
#pragma unroll
        for (int k8 = 0; k8 < 4; k8++) {
            const int kb = k8 * 8;
            unsigned af[4][4], bf[4][2];
#pragma unroll
            for (int mf = 0; mf < 4; mf++) {
                int m = wm * 64 + mf * 16 + g;
                af[mf][0] = Ab[m * 36 + kb + t4];
                af[mf][1] = Ab[(m + 8) * 36 + kb + t4];
                af[mf][2] = Ab[m * 36 + kb + t4 + 4];
                af[mf][3] = Ab[(m + 8) * 36 + kb + t4 + 4];
            }
#pragma unroll
            for (int nf = 0; nf < 4; nf++) {
                int n = wn * 32 + nf * 8 + g;
                bf[nf][0] = Bb[n * 36 + kb + t4];
                bf[nf][1] = Bb[n * 36 + kb + t4 + 4];
            }
#pragma unroll
            for (int mf = 0; mf < 4; mf++)
#pragma unroll
                for (int nf = 0; nf < 4; nf++)
                    mma8(acc[mf][nf], af[mf], bf[nf]);
        }
        if (st < 7) {
            unsigned* Aw = As + ((st + 1) & 1) * 4608;
            unsigned* Bw = Bs + ((st + 1) & 1) * 4608;
#pragma unroll
            for (int i = 0; i < 4; i++) {
                int row = r0 + 32 * i;
                unsigned* da = &Aw[row * 36 + c4 * 4];
                da[0] = tf32c((av[i].x - mu[i]) * rs[i] * g4.x + e4.x);
                da[1] = tf32c((av[i].y - mu[i]) * rs[i] * g4.y + e4.y);
                da[2] = tf32c((av[i].z - mu[i]) * rs[i] * g4.z + e4.z);
                da[3] = tf32c((av[i].w - mu[i]) * rs[i] * g4.w + e4.w);
                unsigned* db = &Bw[row * 36 + c4 * 4];
                db[0] = tf32c(bv[i].x); db[1] = tf32c(bv[i].y);
                db[2] = tf32c(bv[i].z); db[3] = tf32c(bv[i].w);
            }
            __syncthreads();
        }
    }
    float* dst = (n0 < 512) ? g_xm : g_z;
    const int nb = (n0 < 512) ? n0 : (n0 - 512);
#pragma unroll
    for (int mf = 0; mf < 4; mf++) {
        int m = m0 + wm * 64 + mf * 16 + g;
#pragma unroll
        for (int nf = 0; nf < 4; nf++) {
            int n = nb + wn * 32 + nf * 8 + 2 * t4;
            *(float2*)&dst[m * 512 + n]       = make_float2(acc[mf][nf][0], acc[mf][nf][1]);
            *(float2*)&dst[(m + 8) * 512 + n] = make_float2(acc[mf][nf][2], acc[mf][nf][3]);
        }
    }
}

// =====================================================================
// K5: causal depthwise conv (k=3) + SiLU -> u (fp32) ; {u, silu(z)} fp16
// =====================================================================
__global__ void k_conv4(const float* __restrict__ cw, const float* __restrict__ cb) {
    const int g = blockIdx.x * blockDim.x + threadIdx.x;
    const int base = g * 4;
    const int d = base & 511;
    const int l = (base >> 9) & 4095;
    float4 x2 = *(const float4*)&g_xm[base];
    float4 x1 = make_float4(0.f, 0.f, 0.f, 0.f);
    float4 x0 = make_float4(0.f, 0.f, 0.f, 0.f);
    if (l >= 1) x1 = *(const float4*)&g_xm[base - 512];
    if (l >= 2) x0 = *(const float4*)&g_xm[base - 1024];
    float4 w0 = *(const float4*)&cw[d * 3];
    float4 w1 = *(const float4*)&cw[d * 3 + 4];
    float4 w2 = *(const float4*)&cw[d * 3 + 8];
    float4 cb4 = *(const float4*)&cb[d];
    float f[12] = {w0.x, w0.y, w0.z, w0.w, w1.x, w1.y, w1.z, w1.w, w2.x, w2.y, w2.z, w2.w};
    float a0 = x0.x * f[0] + x1.x * f[1]  + x2.x * f[2]  + cb4.x;
    float a1 = x0.y * f[3] + x1.y * f[4]  + x2.y * f[5]  + cb4.y;
    float a2 = x0.z * f[6] + x1.z * f[7]  + x2.z * f[8]  + cb4.z;
    float a3 = x0.w * f[9] + x1.w * f[10] + x2.w * f[11] + cb4.w;
    float4 u4;
    u4.x = a0 / (1.f + __expf(-a0));
    u4.y = a1 / (1.f + __expf(-a1));
    u4.z = a2 / (1.f + __expf(-a2));
    u4.w = a3 / (1.f + __expf(-a3));
    *(float4*)&g_u[base] = u4;
    float4 z4 = *(const float4*)&g_z[base];
    g_uz[base]     = __floats2half2_rn(u4.x, z4.x / (1.f + __expf(-z4.x)));
    g_uz[base + 1] = __floats2half2_rn(u4.y, z4.y / (1.f + __expf(-z4.y)));
    g_uz[base + 2] = __floats2half2_rn(u4.z, z4.z / (1.f + __expf(-z4.z)));
    g_uz[base + 3] = __floats2half2_rn(u4.w, z4.w / (1.f + __expf(-z4.w)));
}

// =====================================================================
// K6: x_proj GEMM — TF32 TC 128x64 (48 live cols), writes dtin + bcc
// =====================================================================
__global__ void __launch_bounds__(256)
k_xproj_tc(const float* __restrict__ w) {
    __shared__ __align__(16) unsigned As[128 * 36];
    __shared__ __align__(16) unsigned Bs[64 * 36];
    const int m0 = blockIdx.x * 128;
    const int tid = threadIdx.x, lane = tid & 31, wid = tid >> 5;
    const int wm = wid >> 1, wn = wid & 1;
    const int g = lane >> 2, t4 = lane & 3;
    const int r0 = tid >> 3, c4 = tid & 7;
    float acc[2][4][4] = {};
    float4 av[4], bv[2];
#pragma unroll
    for (int i = 0; i < 4; i++)
        av[i] = *(const float4*)&g_u[(m0 + r0 + 32 * i) * 512 + c4 * 4];
#pragma unroll
    for (int i = 0; i < 2; i++) {
        int n = r0 + 32 * i;
        bv[i] = (n < 48) ? *(const float4*)&w[n * 512 + c4 * 4]
                         : make_float4(0.f, 0.f, 0.f, 0.f);
    }
    for (int st = 0; st < 16; st++) {
#pragma unroll
        for (int i = 0; i < 4; i++) {
            unsigned* da = &As[(r0 + 32 * i) * 36 + c4 * 4];
            da[0] = tf32c(av[i].x); da[1] = tf32c(av[i].y);
            da[2] = tf32c(av[i].z); da[3] = tf32c(av[i].w);
        }
#pragma unroll
        for (int i = 0; i < 2; i++) {
            unsigned* db = &Bs[(r0 + 32 * i) * 36 + c4 * 4];
            db[0] = tf32c(bv[i].x); db[1] = tf32c(bv[i].y);
            db[2] = tf32c(bv[i].z); db[3] = tf32c(bv[i].w);
        }
        __syncthreads();
        if (st < 15) {
            const int k0 = (st + 1) * 32;
#pragma unroll
            for (int i = 0; i < 4; i++)
                av[i] = *(const float4*)&g_u[(m0 + r0 + 32 * i) * 512 + k0 + c4 * 4];
#pragma unroll
            for (int i = 0; i < 2; i++) {
                int n = r0 + 32 * i;
                bv[i] = (n < 48) ? *(const float4*)&w[n * 512 + k0 + c4 * 4]
                                 : make_float4(0.f, 0.f, 0.f, 0.f);
            }
        }
#pragma unroll
        for (int k8 = 0; k8 < 4; k8++) {
            const int kb = k8 * 8;
            unsigned af[2][4], bf[4][2];
#pragma unroll
            for (int mf = 0; mf < 2; mf++) {
                int m = wm * 32 + mf * 16 + g;
                af[mf][0] = As[m * 36 + kb + t4];
                af[mf][1] = As[(m + 8) * 36 + kb + t4];
                af[mf][2] = As[m * 36 + kb + t4 + 4];
                af[mf][3] = As[(m + 8) * 36 + kb + t4 + 4];
            }
#pragma unroll
            for (int nf = 0; nf < 4; nf++) {
                int n = wn * 32 + nf * 8 + g;
                bf[nf][0] = Bs[n * 36 + kb + t4];
                bf[nf][1] = Bs[n * 36 + kb + t4 + 4];
            }
#pragma unroll
            for (int mf = 0; mf < 2; mf++)
#pragma unroll
                for (int nf = 0; nf < 4; nf++)
                    mma8(acc[mf][nf], af[mf], bf[nf]);
        }
        __syncthreads();
    }
    float* bccf = (float*)g_bcc;
#pragma unroll
    for (int mf = 0; mf < 2; mf++) {
#pragma unroll
        for (int nf = 0; nf < 4; nf++) {
#pragma unroll
            for (int half = 0; half < 2; half++) {
                int gm = m0 + wm * 32 + mf * 16 + g + half * 8;
#pragma unroll
                for (int jj = 0; jj < 2; jj++) {
                    int gn = wn * 32 + nf * 8 + 2 * t4 + jj;
                    float v = acc[mf][nf][half * 2 + jj];
                    if (gn < 16)      g_dtin[gm * 16 + gn] = v;
                    else if (gn < 32) bccf[gm * 32 + 2 * (gn - 16)] = v;
                    else if (gn < 48) bccf[gm * 32 + 2 * (gn - 32) + 1] = v;
                }
            }
        }
    }
}

// =====================================================================
// K7: dt_proj GEMM (K=16) + softplus; writes {dt, dt*u} fp16
// =====================================================================
__global__ void k_dtproj(const float* __restrict__ w, const float* __restrict__ dtb) {
    __shared__ float As[16][65];
    __shared__ float Bs[16][65];
    const int m0 = blockIdx.x * 64;
    const int n0 = blockIdx.y * 64;
    const int tid = threadIdx.x;
    const int tx = tid & 15, ty = tid >> 4;
    float acc[4][4] = {};
#pragma unroll
    for (int i = 0; i < 4; i++) {
        int idx = tid + i * 256;
        int m = idx >> 4, kk = idx & 15;
        As[kk][m] = g_dtin[(m0 + m) * 16 + kk];
    }
#pragma unroll
    for (int i = 0; i < 4; i++) {
        int idx = tid + i * 256;
        int n = idx >> 4, kk = idx & 15;
        Bs[kk][n] = w[(n0 + n) * 16 + kk];
    }
    __syncthreads();
#pragma unroll
    for (int kk = 0; kk < 16; kk++) {
        float a[4], c[4];
#pragma unroll
        for (int i = 0; i < 4; i++) a[i] = As[kk][ty * 4 + i];
#pragma unroll
        for (int j = 0; j < 4; j++) c[j] = Bs[kk][tx * 4 + j];
#pragma unroll
        for (int i = 0; i < 4; i++)
#pragma unroll
            for (int j = 0; j < 4; j++) acc[i][j] += a[i] * c[j];
    }
#pragma unroll
    for (int i = 0; i < 4; i++) {
        int gm = m0 + ty * 4 + i;
        float4 u4 = *(const float4*)&g_u[gm * 512 + n0 + tx * 4];
        float um[4] = {u4.x, u4.y, u4.z, u4.w};
#pragma unroll
        for (int j = 0; j < 4; j++) {
            int gn = n0 + tx * 4 + j;
            float x = acc[i][j] + dtb[gn];
            float sp = (x > 20.f) ? x : log1pf(__expf(x));
            g_a[gm * 512 + gn] = __floats2half2_rn(sp, sp * um[j]);
        }
    }
}

// =====================================================================
// K8: scan pass 1 — warp = 4 channels x 8 lanes x 2 states/lane
// =====================================================================
__global__ void __launch_bounds__(256)
k_scan1(const float* __restrict__ alog) {
    const int w    = (blockIdx.x * blockDim.x + threadIdx.x) >> 5;
    const int lane = threadIdx.x & 31;
    const int chunk = w & (NCH - 1);
    const int dq   = (w >> 5) & 127;
    const int b    = w >> 12;
    const int c2 = lane >> 3, s8 = lane & 7;
    const int d  = dq * 4 + c2;
    const int s0 = 2 * s8;
    const float An2a = -__expf(alog[d * 16 + s0])     * LOG2E;
    const float An2b = -__expf(alog[d * 16 + s0 + 1]) * LOG2E;
    float2 h = make_float2(0.f, 0.f);
    float2 P = make_float2(1.f, 1.f);
    const int l0 = chunk * CT_;
    const __half2* ap = g_a + (size_t)(b * LL + l0) * 512 + d;
    const float4*  bp = (const float4*)(g_bcc + (size_t)(b * LL + l0) * 16) + s8;
#pragma unroll 8
    for (int t = 0; t < CT_; t++) {
        float2 av = __half22float2(ap[t * 512]);
        float4 bc = bp[t * 8];
        float dAa = exp2f(av.x * An2a);
        float dAb = exp2f(av.x * An2b);
        h.x = fmaf(dAa, h.x, av.y * bc.x);
        h.y = fmaf(dAb, h.y, av.y * bc.z);
        P.x *= dAa; P.y *= dAb;
    }
    const int tI = (b * 512 + d) * 16 + s0;
    *(float2*)&g_P[chunk * TT_ + tI]  = P;
    *(float2*)&g_Hc[chunk * TT_ + tI] = h;
}

// =====================================================================
// K10: scan pass 2 — inline prefix combine + replay + y (fp16 out)
// =====================================================================
__global__ void __launch_bounds__(256)
k_scan2(const float* __restrict__ alog, const float* __restrict__ Dp) {
    const int w    = (blockIdx.x * blockDim.x + threadIdx.x) >> 5;
    const int lane = threadIdx.x & 31;
    const int chunk = w & (NCH - 1);
    const int dq   = (w >> 5) & 127;
    const int b    = w >> 12;
    const int c2 = lane >> 3, s8 = lane & 7;
    const int d  = dq * 4 + c2;
    const int s0 = 2 * s8;
    const float An2a = -__expf(alog[d * 16 + s0])     * LOG2E;
    const float An2b = -__expf(alog[d * 16 + s0 + 1]) * LOG2E;
    const float Dv = Dp[d];
    const int tI = (b * 512 + d) * 16 + s0;
    float2 h = make_float2(0.f, 0.f);
#pragma unroll
    for (int c = 0; c < NCH; c++) {
        if (c < chunk) {
            float2 Pv = *(const float2*)&g_P[c * TT_ + tI];
            float2 Hv = *(const float2*)&g_Hc[c * TT_ + tI];
            h.x = Pv.x * h.x + Hv.x;
            h.y = Pv.y * h.y + Hv.y;
        }
    }
    const int l0 = chunk * CT_;
    const __half2* ap = g_a  + (size_t)(b * LL + l0) * 512 + d;
    const float4*  bp = (const float4*)(g_bcc + (size_t)(b * LL + l0) * 16) + s8;
    const __half2* up = g_uz + (size_t)(b * LL + l0) * 512 + d;
    __half* yp = g_yfin + (size_t)(b * LL + l0) * 512 + d;
#pragma unroll 4
    for (int t = 0; t < CT_; t++) {
        float2 av = __half22float2(ap[t * 512]);
        float4 bc = bp[t * 8];
        float dAa = exp2f(av.x * An2a);
        float dAb = exp2f(av.x * An2b);
        h.x = fmaf(dAa, h.x, av.y * bc.x);
        h.y = fmaf(dAb, h.y, av.y * bc.z);
        float part = h.x * bc.y + h.y * bc.w;
        part += __shfl_xor_sync(0xffffffffu, part, 1);
        part += __shfl_xor_sync(0xffffffffu, part, 2);
        part += __shfl_xor_sync(0xffffffffu, part, 4);
        if (s8 == 0) {
            float2 uzv = __half22float2(up[t * 512]);
            yp[t * 512] = __float2half((part + uzv.x * Dv) * uzv.y);
        }
    }
}

// =====================================================================
// K11: out_proj GEMM — TF32 TC, fp16 A source, double-buffered,
//      residual + NCHW scatter
// =====================================================================
__global__ void __launch_bounds__(256)
k_outproj_tc(const float* __restrict__ w, float* __restrict__ out) {
    extern __shared__ unsigned dyn[];
    unsigned* As = dyn;
    unsigned* Bs = dyn + 2 * 4608;
    const int m0 = blockIdx.x * 128, n0 = blockIdx.y * 128;
    const int tid = threadIdx.x, lane = tid & 31, wid = tid >> 5;
    const int wm = wid >> 2, wn = wid & 3;
    const int g = lane >> 2, t4 = lane & 3;
    const int r0 = tid >> 3, c4 = tid & 7;
    float acc[4][4][4] = {};
    uint2 ah[4]; float4 bv[4];
#pragma unroll
    for (int i = 0; i < 4; i++) {
        ah[i] = *(const uint2*)&g_yfin[(m0 + r0 + 32 * i) * 512 + c4 * 4];
        bv[i] = *(const float4*)&w[(n0 + r0 + 32 * i) * 512 + c4 * 4];
    }
#pragma unroll
    for (int i = 0; i < 4; i++) {
        int row = r0 + 32 * i;
        float2 f01 = __half22float2(*(const __half2*)&ah[i].x);
        float2 f23 = __half22float2(*(const __half2*)&ah[i].y);
        unsigned* da = &As[row * 36 + c4 * 4];
        da[0] = tf32c(f01.x); da[1] = tf32c(f01.y);
        da[2] = tf32c(f23.x); da[3] = tf32c(f23.y);
        unsigned* db = &Bs[row * 36 + c4 * 4];
        db[0] = tf32c(bv[i].x); db[1] = tf32c(bv[i].y);
        db[2] = tf32c(bv[i].z); db[3] = tf32c(bv[i].w);
    }
    __syncthreads();
    for (int st = 0; st < 16; st++) {
        const unsigned* Ab = As + (st & 1) * 4608;
        const unsigned* Bb = Bs + (st & 1) * 4608;
        if (st < 15) {
            const int k0 = (st + 1) * 32;
#pragma unroll
            for (int i = 0; i < 4; i++) {
                ah[i] = *(const uint2*)&g_yfin[(m0 + r0 + 32 * i) * 512 + k0 + c4 * 4];
                bv[i] = *(const float4*)&w[(n0 + r0 + 32 * i) * 512 + k0 + c4 * 4];
            }
        }
#pragma unroll
        for (int k8 = 0; k8 < 4; k8++) {
            const int kb = k8 * 8;
            unsigned af[4][4], bf[4][2];
#pragma unroll
            for (int mf = 0; mf < 4; mf++) {
                int m = wm * 64 + mf * 16 + g;
                af[mf][0] = Ab[m * 36 + kb + t4];
                af[mf][1] = Ab[(m + 8) * 36 + kb + t4];
                af[mf][2] = Ab[m * 36 + kb + t4 + 4];
                af[mf][3] = Ab[(m + 8) * 36 + kb + t4 + 4];
            }
#pragma unroll
            for (int nf = 0; nf < 4; nf++) {
                int n = wn * 32 + nf * 8 + g;
                bf[nf][0] = Bb[n * 36 + kb + t4];
                bf[nf][1] = Bb[n * 36 + kb + t4 + 4];
            }
#pragma unroll
            for (int mf = 0; mf < 4; mf++)
#pragma unroll
                for (int nf = 0; nf < 4; nf++)
                    mma8(acc[mf][nf], af[mf], bf[nf]);
        }
        if (st < 15) {
            unsigned* Aw = As + ((st + 1) & 1) * 4608;
            unsigned* Bw = Bs + ((st + 1) & 1) * 4608;
#pragma unroll
            for (int i = 0; i < 4; i++) {
                int row = r0 + 32 * i;
                float2 f01 = __half22float2(*(const __half2*)&ah[i].x);
                float2 f23 = __half22float2(*(const __half2*)&ah[i].y);
                unsigned* da = &Aw[row * 36 + c4 * 4];
                da[0] = tf32c(f01.x); da[1] = tf32c(f01.y);
                da[2] = tf32c(f23.x); da[3] = tf32c(f23.y);
                unsigned* db = &Bw[row * 36 + c4 * 4];
                db[0] = tf32c(bv[i].x); db[1] = tf32c(bv[i].y);
                db[2] = tf32c(bv[i].z); db[3] = tf32c(bv[i].w);
            }
            __syncthreads();
        }
    }
    const int bb = m0 >> 12;
#pragma unroll
    for (int mf = 0; mf < 4; mf++) {
        int m = m0 + wm * 64 + mf * 16 + g;
        int l = m & 4095;
#pragma unroll
        for (int nf = 0; nf < 4; nf++) {
            int n = n0 + wn * 32 + nf * 8 + 2 * t4;
            size_t i0 = (size_t)(bb * 256 + n) * 4096 + l;
            size_t i1 = i0 + 4096;
            out[i0]     = acc[mf][nf][0] + g_fused[i0];
            out[i1]     = acc[mf][nf][1] + g_fused[i1];
            out[i0 + 8] = acc[mf][nf][2] + g_fused[i0 + 8];
            out[i1 + 8] = acc[mf][nf][3] + g_fused[i1 + 8];
        }
    }
}

// =====================================================================
extern "C" void kernel_launch(void* const* d_in, const int* in_sizes, int n_in,
                              void* d_out, int out_size) {
    const float* resnet = (const float*)d_in[0];
    const float* scp    = (const float*)d_in[1];
    const float* scpw   = (const float*)d_in[2];
    const float* sg = (const float*)d_in[3];
    const float* sb = (const float*)d_in[4];
    const float* sm = (const float*)d_in[5];
    const float* sv = (const float*)d_in[6];
    const float* rg = (const float*)d_in[7];
    const float* rb = (const float*)d_in[8];
    const float* rm = (const float*)d_in[9];
    const float* rv = (const float*)d_in[10];
    const float* lg = (const float*)d_in[11];
    const float* lb = (const float*)d_in[12];
    const float* inw = (const float*)d_in[13];
    const float* cw  = (const float*)d_in[14];
    const float* cb  = (const float*)d_in[15];
    const float* xw  = (const float*)d_in[16];
    const float* dtw = (const float*)d_in[17];
    const float* dtb = (const float*)d_in[18];
    const float* alog = (const float*)d_in[19];
    const float* Dp   = (const float*)d_in[20];
    const float* ow   = (const float*)d_in[21];
    float* out = (float*)d_out;

    const int DYN = 4 * 4608 * 4;  // 73728 bytes (double-buffered As+Bs)
    cudaFuncSetAttribute(k_inproj_tc, cudaFuncAttributeMaxDynamicSharedMemorySize, DYN);
    cudaFuncSetAttribute(k_outproj_tc, cudaFuncAttributeMaxDynamicSharedMemorySize, DYN);

    k_scp_tc   <<<dim3(2, 8, 2), 256>>>(scp, scpw, sg, sb, sm, sv);
    k_fuse     <<<dim3(128, 8, 2), dim3(32, 8)>>>(resnet, rg, rb, rm, rv);
    k_inproj_tc<<<dim3(64, 8), 256, DYN>>>(inw, lg, lb);
    k_conv4    <<<(NB * LL * DI_) / 1024, 256>>>(cw, cb);
    k_xproj_tc <<<64, 256>>>(xw);
    k_dtproj   <<<dim3(128, 8), 256>>>(dtw, dtb);
    k_scan1    <<<1024, 256>>>(alog);
    k_scan2    <<<1024, 256>>>(alog, Dp);
    k_outproj_tc<<<dim3(64, 2), 256, DYN>>>(ow, out);
}